// round 2
// baseline (speedup 1.0000x reference)
#include <cuda_runtime.h>

#define NPIX 262144
#define CIN  200
#define HD   128
#define SP   4096
#define EAE  65536
#define EME  2097152
#define NCLS 16

// ---------------- scratch (device globals; allocation-free rule) ----------------
__device__ float  d_x0 [NPIX*HD];
__device__ float  d_pfa[NPIX*HD];
__device__ float  d_pfb[NPIX*HD];
__device__ float  d_v  [NPIX*HD];
__device__ float  d_q  [NPIX*HD];
__device__ float  d_att[NPIX*HD];
__device__ float  d_s0 [EME];
__device__ float  d_s1 [EME];
__device__ float  d_mx0[NPIX];
__device__ float  d_mx1[NPIX];
__device__ float  d_z0 [NPIX];
__device__ float  d_z1 [NPIX];
__device__ double d_sums [HD];
__device__ double d_sumsq[HD];
__device__ float  d_mean [HD];
__device__ float  d_scl  [HD];
__device__ float  d_hp [SP*HD];
__device__ float  d_hb [SP*HD];
__device__ float  d_xs [SP*HD];
__device__ float  d_acc[SP*HD];
__device__ float  d_ba [SP*HD];
__device__ float  d_bb [SP*HD];
__device__ float  d_cnt[SP];
__device__ float  d_wv [2*HD*HD];
__device__ float  d_wq [2*HD*HD];
__device__ float  d_bv [2*HD];
__device__ float  d_bq [2*HD];

// ---------------- helpers ----------------
__device__ __forceinline__ void atomicMaxFloat(float* addr, float val) {
    if (__float_as_int(val) >= 0) {
        atomicMax((int*)addr, __float_as_int(val));
    } else {
        atomicMin((unsigned int*)addr, __float_as_uint(val));
    }
}

// ---------------- weight packing: [2][2][128][64] -> [2][128][128] ----------------
__global__ void pack_weights(const float* __restrict__ Wv, const float* __restrict__ bv,
                             const float* __restrict__ Wq, const float* __restrict__ bq,
                             float* __restrict__ wvp, float* __restrict__ bvp,
                             float* __restrict__ wqp, float* __restrict__ bqp)
{
    int idx = blockIdx.x * blockDim.x + threadIdx.x;
    if (idx >= 2 * HD * HD) return;
    int l = idx >> 14;
    int rem = idx & 16383;
    int k = rem >> 7;
    int c = rem & 127;
    int h = c >> 6;
    int j = c & 63;
    int sidx = ((l * 2 + h) * HD + k) * 64 + j;
    wvp[idx] = Wv[sidx];
    wqp[idx] = Wq[sidx];
    if (k == 0) {
        bvp[(l << 7) | c] = bv[(l * 2 + h) * 64 + j];
        bqp[(l << 7) | c] = bq[(l * 2 + h) * 64 + j];
    }
}

// ---------------- SGEMM: C[M,128] = A[M,K] @ B[K,128] + bias ----------------
// block = 256 threads, tile 128x128, KC=16, 8x8 microtile
__global__ __launch_bounds__(256) void gemm128(
    const float* __restrict__ A, const float* __restrict__ B,
    const float* __restrict__ bias, float* __restrict__ C, int M, int K)
{
    __shared__ float As[16][128];
    __shared__ float Bs[16][128];
    const int tid  = threadIdx.x;
    const int m0   = blockIdx.x * 128;
    const int trow = tid >> 4;   // 0..15
    const int tcol = tid & 15;   // 0..15

    float acc[8][8];
#pragma unroll
    for (int i = 0; i < 8; i++)
#pragma unroll
        for (int j = 0; j < 8; j++) acc[i][j] = 0.f;

    for (int k0 = 0; k0 < K; k0 += 16) {
        // A tile -> As[k][row] (transposed)
#pragma unroll
        for (int i = 0; i < 2; i++) {
            int slot = tid + i * 256;       // 0..511
            int row  = slot >> 2;           // 0..127
            int kq   = (slot & 3) << 2;     // 0,4,8,12
            const float* ap = A + (size_t)(m0 + row) * K + (k0 + kq);
            float4 v;
            if (k0 + kq + 3 < K) {
                v = *(const float4*)ap;
            } else {
                v.x = (k0 + kq + 0 < K) ? ap[0] : 0.f;
                v.y = (k0 + kq + 1 < K) ? ap[1] : 0.f;
                v.z = (k0 + kq + 2 < K) ? ap[2] : 0.f;
                v.w = (k0 + kq + 3 < K) ? ap[3] : 0.f;
            }
            As[kq + 0][row] = v.x; As[kq + 1][row] = v.y;
            As[kq + 2][row] = v.z; As[kq + 3][row] = v.w;
        }
        // B tile -> Bs[k][c]
#pragma unroll
        for (int i = 0; i < 2; i++) {
            int slot = tid + i * 256;
            int kr = slot >> 5;             // 0..15
            int c  = (slot & 31) << 2;      // 0..124
            float4 v = make_float4(0.f, 0.f, 0.f, 0.f);
            if (k0 + kr < K) v = *(const float4*)(B + (size_t)(k0 + kr) * 128 + c);
            *(float4*)&Bs[kr][c] = v;
        }
        __syncthreads();
#pragma unroll
        for (int kk = 0; kk < 16; kk++) {
            float a[8], b[8];
            *(float4*)&a[0] = *(const float4*)&As[kk][trow * 4];
            *(float4*)&a[4] = *(const float4*)&As[kk][64 + trow * 4];
            *(float4*)&b[0] = *(const float4*)&Bs[kk][tcol * 4];
            *(float4*)&b[4] = *(const float4*)&Bs[kk][64 + tcol * 4];
#pragma unroll
            for (int i = 0; i < 8; i++)
#pragma unroll
                for (int j = 0; j < 8; j++)
                    acc[i][j] += a[i] * b[j];
        }
        __syncthreads();
    }
    float bb[8];
    *(float4*)&bb[0] = *(const float4*)&bias[tcol * 4];
    *(float4*)&bb[4] = *(const float4*)&bias[64 + tcol * 4];
#pragma unroll
    for (int i = 0; i < 8; i++) {
        int row = m0 + ((i < 4) ? (trow * 4 + i) : (64 + trow * 4 + (i - 4)));
        float4 o0 = make_float4(acc[i][0] + bb[0], acc[i][1] + bb[1],
                                acc[i][2] + bb[2], acc[i][3] + bb[3]);
        float4 o1 = make_float4(acc[i][4] + bb[4], acc[i][5] + bb[5],
                                acc[i][6] + bb[6], acc[i][7] + bb[7]);
        *(float4*)(C + (size_t)row * 128 + tcol * 4)      = o0;
        *(float4*)(C + (size_t)row * 128 + 64 + tcol * 4) = o1;
    }
}

// ---------------- BatchNorm stats (column mean/var over rows) ----------------
__global__ void colstats(const float* __restrict__ X, int nrows,
                         double* __restrict__ sums, double* __restrict__ sumsq)
{
    int c    = threadIdx.x & 127;
    int half = threadIdx.x >> 7;
    float s = 0.f, s2 = 0.f;
    for (int r = blockIdx.x * 2 + half; r < nrows; r += gridDim.x * 2) {
        float v = X[(size_t)r * 128 + c];
        s += v;
        s2 = fmaf(v, v, s2);
    }
    __shared__ float sh[2][128], sh2[2][128];
    sh[half][c] = s; sh2[half][c] = s2;
    __syncthreads();
    if (half == 0) {
        atomicAdd(&sums[c],  (double)(s  + sh[1][c]));
        atomicAdd(&sumsq[c], (double)(s2 + sh2[1][c]));
    }
}

__global__ void finalize_stats(const double* __restrict__ sums,
                               const double* __restrict__ sumsq,
                               float* __restrict__ mean, float* __restrict__ scl,
                               double inv_n)
{
    int c = threadIdx.x;
    double m   = sums[c] * inv_n;
    double var = sumsq[c] * inv_n - m * m;
    mean[c] = (float)m;
    scl[c]  = (float)(1.0 / sqrt(var + 1e-5));
}

__global__ void bn_apply(const float* __restrict__ X, float* __restrict__ Y,
                         const float* __restrict__ mean, const float* __restrict__ scl,
                         const float* __restrict__ g, const float* __restrict__ b,
                         int nrows, int lrelu)
{
    int total = nrows * 32;
    for (int idx = blockIdx.x * blockDim.x + threadIdx.x; idx < total;
         idx += gridDim.x * blockDim.x) {
        int c4 = idx & 31;
        float4 xv = ((const float4*)X)[idx];
        float4 m4 = ((const float4*)mean)[c4];
        float4 s4 = ((const float4*)scl)[c4];
        float4 g4 = ((const float4*)g)[c4];
        float4 b4 = ((const float4*)b)[c4];
        float4 o;
        o.x = (xv.x - m4.x) * s4.x * g4.x + b4.x;
        o.y = (xv.y - m4.y) * s4.y * g4.y + b4.y;
        o.z = (xv.z - m4.z) * s4.z * g4.z + b4.z;
        o.w = (xv.w - m4.w) * s4.w * g4.w + b4.w;
        if (lrelu) {
            o.x = o.x >= 0.f ? o.x : 0.01f * o.x;
            o.y = o.y >= 0.f ? o.y : 0.01f * o.y;
            o.z = o.z >= 0.f ? o.z : 0.01f * o.z;
            o.w = o.w >= 0.f ? o.w : 0.01f * o.w;
        }
        ((float4*)Y)[idx] = o;
    }
}

// ---------------- per-head LayerNorm over 64-wide halves (in place) ----------------
__global__ void ln_halves(float* __restrict__ q, int nrows)
{
    int warp = (blockIdx.x * blockDim.x + threadIdx.x) >> 5;
    int lane = threadIdx.x & 31;
    if (warp >= nrows) return;
    float4* qp = (float4*)q + (size_t)warp * 32;
    float4 v = qp[lane];
    float s  = v.x + v.y + v.z + v.w;
    float s2 = v.x * v.x + v.y * v.y + v.z * v.z + v.w * v.w;
#pragma unroll
    for (int off = 1; off < 16; off <<= 1) {
        s  += __shfl_xor_sync(0xffffffffu, s,  off);
        s2 += __shfl_xor_sync(0xffffffffu, s2, off);
    }
    float m   = s * (1.f / 64.f);
    float var = s2 * (1.f / 64.f) - m * m;
    float r   = rsqrtf(var + 1e-5f);
    v.x = (v.x - m) * r; v.y = (v.y - m) * r;
    v.z = (v.z - m) * r; v.w = (v.w - m) * r;
    qp[lane] = v;
}

__global__ void fill_neginf(float* __restrict__ a, float* __restrict__ b, int n)
{
    int i = blockIdx.x * blockDim.x + threadIdx.x;
    if (i < n) {
        float ninf = __int_as_float(0xff800000u);
        a[i] = ninf;
        b[i] = ninf;
    }
}

// ---------------- edge pass A: s = q[src].q[dst]/128 per head, segment max ----------------
__global__ void edge_dot_max(const float* __restrict__ q, const int* __restrict__ src,
                             const int* __restrict__ dst, float* __restrict__ s0buf,
                             float* __restrict__ s1buf, float* __restrict__ mx0,
                             float* __restrict__ mx1, int E)
{
    int warp = (blockIdx.x * blockDim.x + threadIdx.x) >> 5;
    int lane = threadIdx.x & 31;
    if (warp >= E) return;
    int s = src[warp], d = dst[warp];
    float4 a = ((const float4*)q)[(size_t)s * 32 + lane];
    float4 b = ((const float4*)q)[(size_t)d * 32 + lane];
    float p = a.x * b.x + a.y * b.y + a.z * b.z + a.w * b.w;
    p += __shfl_xor_sync(0xffffffffu, p, 1);
    p += __shfl_xor_sync(0xffffffffu, p, 2);
    p += __shfl_xor_sync(0xffffffffu, p, 4);
    p += __shfl_xor_sync(0xffffffffu, p, 8);
    float sval = p * (1.0f / 128.0f);
    if (lane == 0)  { s0buf[warp] = sval; atomicMaxFloat(&mx0[s], sval); }
    if (lane == 16) { s1buf[warp] = sval; atomicMaxFloat(&mx1[s], sval); }
}

// ---------------- edge pass B: e = exp(s - mx[src]), segment sum z ----------------
__global__ void edge_exp(float* __restrict__ s0buf, float* __restrict__ s1buf,
                         const int* __restrict__ src, const float* __restrict__ mx0,
                         const float* __restrict__ mx1, float* __restrict__ z0,
                         float* __restrict__ z1, int E)
{
    int e = blockIdx.x * blockDim.x + threadIdx.x;
    if (e >= E) return;
    int s = src[e];
    float e0 = __expf(s0buf[e] - mx0[s]);
    float e1 = __expf(s1buf[e] - mx1[s]);
    s0buf[e] = e0; s1buf[e] = e1;
    atomicAdd(&z0[s], e0);
    atomicAdd(&z1[s], e1);
}

// ---------------- edge pass C: out[src] += att * v[dst] (both heads) ----------------
__global__ void edge_agg(const float* __restrict__ v, const float* __restrict__ e0,
                         const float* __restrict__ e1, const int* __restrict__ src,
                         const int* __restrict__ dst, const float* __restrict__ z0,
                         const float* __restrict__ z1, float* __restrict__ out, int E)
{
    int warp = (blockIdx.x * blockDim.x + threadIdx.x) >> 5;
    int lane = threadIdx.x & 31;
    if (warp >= E) return;
    int s = src[warp], d = dst[warp];
    float att = (lane < 16) ? __fdividef(e0[warp], z0[s]) : __fdividef(e1[warp], z1[s]);
    float4 vv = ((const float4*)v)[(size_t)d * 32 + lane];
    float* op = out + (size_t)s * 128 + lane * 4;
    atomicAdd(op + 0, att * vv.x);
    atomicAdd(op + 1, att * vv.y);
    atomicAdd(op + 2, att * vv.z);
    atomicAdd(op + 3, att * vv.w);
}

// ---------------- superpixel pooling ----------------
__global__ void pool(const float* __restrict__ x0, const int* __restrict__ seg,
                     float* __restrict__ hsum, float* __restrict__ cnt)
{
    int idx = blockIdx.x * blockDim.x + threadIdx.x;
    if (idx >= NPIX * 32) return;
    int pix = idx >> 5, lane = idx & 31;
    int s = seg[pix];
    float4 xv = ((const float4*)x0)[(size_t)pix * 32 + lane];
    float* hs = hsum + (size_t)s * 128 + lane * 4;
    atomicAdd(hs + 0, xv.x);
    atomicAdd(hs + 1, xv.y);
    atomicAdd(hs + 2, xv.z);
    atomicAdd(hs + 3, xv.w);
    if (lane == 0) atomicAdd(&cnt[s], 1.0f);
}

__global__ void hp_div(float* __restrict__ hp, const float* __restrict__ cnt)
{
    int idx = blockIdx.x * blockDim.x + threadIdx.x;
    if (idx >= SP * HD) return;
    hp[idx] = hp[idx] / fmaxf(cnt[idx >> 7], 1.0f);
}

// ---------------- superpixel graph propagate: out[dst] += w * h[src] ----------------
__global__ void sf_prop(const float* __restrict__ h, const int* __restrict__ src,
                        const int* __restrict__ dst, const float* __restrict__ w,
                        float* __restrict__ out, int E)
{
    int warp = (blockIdx.x * blockDim.x + threadIdx.x) >> 5;
    int lane = threadIdx.x & 31;
    if (warp >= E) return;
    int s = src[warp], d = dst[warp];
    float wt = w[warp];
    float4 hv = ((const float4*)h)[(size_t)s * 32 + lane];
    float* op = out + (size_t)d * 128 + lane * 4;
    atomicAdd(op + 0, wt * hv.x);
    atomicAdd(op + 1, wt * hv.y);
    atomicAdd(op + 2, wt * hv.z);
    atomicAdd(op + 3, wt * hv.w);
}

__global__ void sf_combine(float* __restrict__ acc, const float* __restrict__ xs,
                           float* __restrict__ nxt)
{
    int idx = blockIdx.x * blockDim.x + threadIdx.x;
    if (idx >= SP * 32) return;
    float4 a = ((float4*)acc)[idx];
    float4 x = ((const float4*)xs)[idx];
    const float inv = 1.0f / 2.9f;
    float4 o = make_float4((a.x + x.x) * inv, (a.y + x.y) * inv,
                           (a.z + x.z) * inv, (a.w + x.w) * inv);
    ((float4*)nxt)[idx] = o;
    ((float4*)acc)[idx] = make_float4(0.f, 0.f, 0.f, 0.f);
}

// ---------------- final: H1 = pf + hp[seg]; softmax(H1 @ W + b) ----------------
__global__ __launch_bounds__(256) void final_out(
    const float* __restrict__ pf, const float* __restrict__ hp,
    const int* __restrict__ seg, const float* __restrict__ Wout,
    const float* __restrict__ bout, float* __restrict__ out, int nrows)
{
    __shared__ float sWt[16 * 128];   // transposed: [c][k]
    __shared__ float sb[16];
    for (int i = threadIdx.x; i < 2048; i += 256) {
        int k = i >> 4, c = i & 15;
        sWt[c * 128 + k] = Wout[i];
    }
    if (threadIdx.x < 16) sb[threadIdx.x] = bout[threadIdx.x];
    __syncthreads();

    int warp = (blockIdx.x * 256 + threadIdx.x) >> 5;
    int lane = threadIdx.x & 31;
    if (warp >= nrows) return;
    int s = seg[warp];
    float4 a = ((const float4*)pf)[(size_t)warp * 32 + lane];
    float4 b = ((const float4*)hp)[(size_t)s * 32 + lane];
    float4 h = make_float4(a.x + b.x, a.y + b.y, a.z + b.z, a.w + b.w);

    float lg[16];
#pragma unroll
    for (int c = 0; c < 16; c++) {
        float4 w = ((const float4*)sWt)[c * 32 + lane];
        lg[c] = h.x * w.x + h.y * w.y + h.z * w.z + h.w * w.w;
    }
#pragma unroll
    for (int off = 16; off >= 1; off >>= 1)
#pragma unroll
        for (int c = 0; c < 16; c++)
            lg[c] += __shfl_xor_sync(0xffffffffu, lg[c], off);

    if (lane < 16) {
        float mx = -1e30f;
#pragma unroll
        for (int c = 0; c < 16; c++) { lg[c] += sb[c]; mx = fmaxf(mx, lg[c]); }
        float sum = 0.f;
#pragma unroll
        for (int c = 0; c < 16; c++) { lg[c] = __expf(lg[c] - mx); sum += lg[c]; }
        float inv = __fdividef(1.0f, sum);
        float r = 0.f;
#pragma unroll
        for (int c = 0; c < 16; c++) if (lane == c) r = lg[c];
        out[(size_t)warp * 16 + lane] = r * inv;
    }
}

// ---------------- host ----------------
#define GSYM(p, sym) cudaGetSymbolAddress((void**)&p, sym)

static void run_bn(const float* X, float* Y, const float* g, const float* b,
                   int nrows, int lrelu,
                   double* sums, double* sumsq, float* mean, float* scl)
{
    cudaMemsetAsync(sums, 0, HD * sizeof(double));
    cudaMemsetAsync(sumsq, 0, HD * sizeof(double));
    int sblocks = (nrows >= NPIX) ? 512 : 16;
    colstats<<<sblocks, 256>>>(X, nrows, sums, sumsq);
    finalize_stats<<<1, 128>>>(sums, sumsq, mean, scl, 1.0 / (double)nrows);
    int ablocks = (nrows * 32 + 255) / 256;
    if (ablocks > 4096) ablocks = 4096;
    bn_apply<<<ablocks, 256>>>(X, Y, mean, scl, g, b, nrows, lrelu);
}

extern "C" void kernel_launch(void* const* d_in, const int* in_sizes, int n_in,
                              void* d_out, int out_size)
{
    const float* x       = (const float*)d_in[0];
    const int*   seg     = (const int*)  d_in[1];
    const int*   a_src   = (const int*)  d_in[2];
    const int*   a_dst   = (const int*)  d_in[3];
    const float* a_w     = (const float*)d_in[4];
    const int*   m_src   = (const int*)  d_in[5];
    const int*   m_dst   = (const int*)  d_in[6];
    const float* pre_W   = (const float*)d_in[7];
    const float* pre_b   = (const float*)d_in[8];
    const float* bn0_g   = (const float*)d_in[9];
    const float* bn0_b   = (const float*)d_in[10];
    const float* sf_W    = (const float*)d_in[11];
    const float* sf_b    = (const float*)d_in[12];
    const float* sf_g    = (const float*)d_in[13];
    const float* sf_beta = (const float*)d_in[14];
    const float* pf_Wv   = (const float*)d_in[15];
    const float* pf_bv   = (const float*)d_in[16];
    const float* pf_Wq   = (const float*)d_in[17];
    const float* pf_bq   = (const float*)d_in[18];
    const float* pf_g    = (const float*)d_in[19];
    const float* pf_beta = (const float*)d_in[20];
    const float* out_W   = (const float*)d_in[21];
    const float* out_b   = (const float*)d_in[22];
    float* out = (float*)d_out;

    float *x0, *pfa, *pfb, *v, *q, *att, *s0, *s1, *mx0, *mx1, *z0, *z1;
    float *mean, *scl, *hp, *hb, *xs, *acc, *ba, *bb, *cnt, *wv, *wq, *bv, *bq;
    double *sums, *sumsq;
    GSYM(x0, d_x0);   GSYM(pfa, d_pfa); GSYM(pfb, d_pfb);
    GSYM(v, d_v);     GSYM(q, d_q);     GSYM(att, d_att);
    GSYM(s0, d_s0);   GSYM(s1, d_s1);
    GSYM(mx0, d_mx0); GSYM(mx1, d_mx1); GSYM(z0, d_z0); GSYM(z1, d_z1);
    GSYM(sums, d_sums); GSYM(sumsq, d_sumsq); GSYM(mean, d_mean); GSYM(scl, d_scl);
    GSYM(hp, d_hp); GSYM(hb, d_hb); GSYM(xs, d_xs); GSYM(acc, d_acc);
    GSYM(ba, d_ba); GSYM(bb, d_bb); GSYM(cnt, d_cnt);
    GSYM(wv, d_wv); GSYM(wq, d_wq); GSYM(bv, d_bv); GSYM(bq, d_bq);

    // pack per-head attention weights into [128,128]
    pack_weights<<<(2 * HD * HD + 255) / 256, 256>>>(pf_Wv, pf_bv, pf_Wq, pf_bq,
                                                     wv, bv, wq, bq);

    // ---- pre: x0 = BN(x @ pre_W + pre_b) ----
    gemm128<<<NPIX / 128, 256>>>(x, pre_W, pre_b, x0, NPIX, CIN);
    run_bn(x0, x0, bn0_g, bn0_b, NPIX, 0, sums, sumsq, mean, scl);

    // ---- PF branch: 2 attention layers on the pixel graph ----
    const float* pin = x0;
    for (int l = 0; l < 2; l++) {
        float* pout = (l == 0) ? pfa : pfb;
        gemm128<<<NPIX / 128, 256>>>(pin, wv + l * HD * HD, bv + l * HD, v, NPIX, HD);
        gemm128<<<NPIX / 128, 256>>>(pin, wq + l * HD * HD, bq + l * HD, q, NPIX, HD);
        ln_halves<<<NPIX / 8, 256>>>(q, NPIX);
        cudaMemsetAsync(att, 0, (size_t)NPIX * HD * sizeof(float));
        cudaMemsetAsync(z0, 0, NPIX * sizeof(float));
        cudaMemsetAsync(z1, 0, NPIX * sizeof(float));
        fill_neginf<<<NPIX / 256, 256>>>(mx0, mx1, NPIX);
        edge_dot_max<<<EME / 8, 256>>>(q, m_src, m_dst, s0, s1, mx0, mx1, EME);
        edge_exp<<<EME / 256, 256>>>(s0, s1, m_src, mx0, mx1, z0, z1, EME);
        edge_agg<<<EME / 8, 256>>>(v, s0, s1, m_src, m_dst, z0, z1, att, EME);
        run_bn(att, pout, pf_g + l * HD, pf_beta + l * HD, NPIX, 1, sums, sumsq, mean, scl);
        pin = pout;
    }

    // ---- SF branch: pool -> 5 SFNet layers on superpixel graph ----
    cudaMemsetAsync(hp, 0, (size_t)SP * HD * sizeof(float));
    cudaMemsetAsync(cnt, 0, SP * sizeof(float));
    pool<<<NPIX * 32 / 256, 256>>>(x0, seg, hp, cnt);
    hp_div<<<SP * HD / 256, 256>>>(hp, cnt);

    for (int l = 0; l < 5; l++) {
        gemm128<<<SP / 128, 256>>>(hp, sf_W + l * HD * HD, sf_b + l * HD, hb, SP, HD);
        cudaMemsetAsync(xs, 0, (size_t)SP * HD * sizeof(float));
        sf_prop<<<EAE * 32 / 256, 256>>>(hb, a_src, a_dst, a_w, xs, EAE);
        cudaMemsetAsync(acc, 0, (size_t)SP * HD * sizeof(float));
        const float* cur = hp;
        for (int it = 0; it < 5; it++) {
            float* nxt = (it & 1) ? bb : ba;
            sf_prop<<<EAE * 32 / 256, 256>>>(cur, a_src, a_dst, a_w, acc, EAE);
            sf_combine<<<SP * 32 / 256, 256>>>(acc, xs, nxt);
            cur = nxt;
        }
        run_bn(cur, hp, sf_g + l * HD, sf_beta + l * HD, SP, 1, sums, sumsq, mean, scl);
    }

    // ---- final: softmax((pf + hp[seg]) @ out_W + out_b) ----
    final_out<<<NPIX / 8, 256>>>(pfb, hp, seg, out_W, out_b, out, NPIX);
}

// round 5
// speedup vs baseline: 1.3150x; 1.3150x over previous
#include <cuda_runtime.h>
#include <cuda_bf16.h>

#define NPIX 262144
#define CIN  200
#define HD   128
#define SP   4096
#define EAE  65536
#define EME  2097152
#define NCLS 16

// ---------------- scratch (device globals; allocation-free rule) ----------------
__device__ float  d_x0 [NPIX*HD];
__device__ float  d_pfa[NPIX*HD];
__device__ float  d_pfb[NPIX*HD];
__device__ float  d_v  [NPIX*HD];
__device__ float  d_q  [NPIX*HD];
__device__ float  d_att[NPIX*HD];
__device__ float  d_s0 [EME];
__device__ float  d_s1 [EME];
__device__ float  d_mx0[NPIX];
__device__ float  d_mx1[NPIX];
__device__ float  d_z0 [NPIX];
__device__ float  d_z1 [NPIX];
__device__ double d_sums [HD];
__device__ double d_sumsq[HD];
__device__ float  d_mean [HD];
__device__ float  d_scl  [HD];
__device__ float  d_hp [SP*HD];
__device__ float  d_hb [SP*HD];
__device__ float  d_xs [SP*HD];
__device__ float  d_acc[SP*HD];
__device__ float  d_ba [SP*HD];
__device__ float  d_bb [SP*HD];
__device__ float  d_cnt[SP];
__device__ float  d_wv [2*HD*HD];
__device__ float  d_wq [2*HD*HD];
__device__ float  d_bv [2*HD];
__device__ float  d_bq [2*HD];

// ---------------- helpers ----------------
__device__ __forceinline__ void atomicMaxFloat(float* addr, float val) {
    if (__float_as_int(val) >= 0) {
        atomicMax((int*)addr, __float_as_int(val));
    } else {
        atomicMin((unsigned int*)addr, __float_as_uint(val));
    }
}

__device__ __forceinline__ void red_add_v4(float* p, float a, float b, float c, float d) {
    asm volatile("red.global.add.v4.f32 [%0], {%1,%2,%3,%4};"
                 :: "l"(p), "f"(a), "f"(b), "f"(c), "f"(d) : "memory");
}

// split fp32 into bf16 hi + bf16 lo (16-bit effective mantissa)
__device__ __forceinline__ void cvt_hilo(float v, unsigned& hi, unsigned& lo) {
    __nv_bfloat16 h = __float2bfloat16(v);
    float r = v - __bfloat162float(h);
    __nv_bfloat16 l = __float2bfloat16(r);
    hi = (unsigned)__bfloat16_as_ushort(h);
    lo = (unsigned)__bfloat16_as_ushort(l);
}

__device__ __forceinline__ void mma16816(float* c, const unsigned* a, const unsigned* b) {
    asm volatile("mma.sync.aligned.m16n8k16.row.col.f32.bf16.bf16.f32 "
                 "{%0,%1,%2,%3}, {%4,%5,%6,%7}, {%8,%9}, {%0,%1,%2,%3};"
                 : "+f"(c[0]), "+f"(c[1]), "+f"(c[2]), "+f"(c[3])
                 : "r"(a[0]), "r"(a[1]), "r"(a[2]), "r"(a[3]),
                   "r"(b[0]), "r"(b[1]));
}

// ---------------- weight packing: [2][2][128][64] -> [2][128][128] ----------------
__global__ void pack_weights(const float* __restrict__ Wv, const float* __restrict__ bv,
                             const float* __restrict__ Wq, const float* __restrict__ bq,
                             float* __restrict__ wvp, float* __restrict__ bvp,
                             float* __restrict__ wqp, float* __restrict__ bqp)
{
    int idx = blockIdx.x * blockDim.x + threadIdx.x;
    if (idx >= 2 * HD * HD) return;
    int l = idx >> 14;
    int rem = idx & 16383;
    int k = rem >> 7;
    int c = rem & 127;
    int h = c >> 6;
    int j = c & 63;
    int sidx = ((l * 2 + h) * HD + k) * 64 + j;
    wvp[idx] = Wv[sidx];
    wqp[idx] = Wq[sidx];
    if (k == 0) {
        bvp[(l << 7) | c] = bv[(l * 2 + h) * 64 + j];
        bqp[(l << 7) | c] = bq[(l * 2 + h) * 64 + j];
    }
}

// ---------------- Tensor-core GEMM: C[M,128] = A[M,K] @ B[K,128] + bias ----------------
// bf16 hi/lo 3-term split, block tile 128x128, 8 warps (2x4), mma m16n8k16
__global__ __launch_bounds__(256) void gemm_tc(
    const float* __restrict__ A, const float* __restrict__ B,
    const float* __restrict__ bias, float* __restrict__ C, int M, int K)
{
    __shared__ unsigned As_h[128 * 8];     // [row][kpair], 8 u32 per row
    __shared__ unsigned As_l[128 * 8];
    __shared__ unsigned Bs_h[8 * 132];     // [kpair][n], padded 132
    __shared__ unsigned Bs_l[8 * 132];

    const int tid  = threadIdx.x;
    const int lane = tid & 31;
    const int warp = tid >> 5;
    const int wm   = warp >> 2;            // 0..1 (64 rows each)
    const int wn   = warp & 3;             // 0..3 (32 cols each)
    const int m0   = blockIdx.x * 128;

    float acc[4][4][4];
#pragma unroll
    for (int mt = 0; mt < 4; mt++)
#pragma unroll
        for (int nt = 0; nt < 4; nt++)
#pragma unroll
            for (int i = 0; i < 4; i++) acc[mt][nt][i] = 0.f;

    const int lr = lane >> 2;              // 0..7
    const int jj = lane & 3;               // 0..3

    for (int k0 = 0; k0 < K; k0 += 16) {
        // ---- A tile: 128 rows x 16 k, fp32 -> bf16 hi/lo ----
        {
            int r  = tid & 127;
            int qb = (tid >> 7) << 1;      // quad base 0 or 2
            const float* ap = A + (size_t)(m0 + r) * K;
#pragma unroll
            for (int qq = 0; qq < 2; qq++) {
                int q  = qb + qq;
                int kk = k0 + q * 4;
                float v0 = 0.f, v1 = 0.f, v2 = 0.f, v3 = 0.f;
                if (kk + 3 < K) {
                    float4 t = *(const float4*)(ap + kk);
                    v0 = t.x; v1 = t.y; v2 = t.z; v3 = t.w;
                } else {
                    if (kk + 0 < K) v0 = ap[kk + 0];
                    if (kk + 1 < K) v1 = ap[kk + 1];
                    if (kk + 2 < K) v2 = ap[kk + 2];
                    if (kk + 3 < K) v3 = ap[kk + 3];
                }
                unsigned h0, l0, h1, l1, h2, l2, h3, l3;
                cvt_hilo(v0, h0, l0); cvt_hilo(v1, h1, l1);
                cvt_hilo(v2, h2, l2); cvt_hilo(v3, h3, l3);
                As_h[r * 8 + q * 2 + 0] = h0 | (h1 << 16);
                As_h[r * 8 + q * 2 + 1] = h2 | (h3 << 16);
                As_l[r * 8 + q * 2 + 0] = l0 | (l1 << 16);
                As_l[r * 8 + q * 2 + 1] = l2 | (l3 << 16);
            }
        }
        // ---- B tile: 16 k x 128 n, transposed pack into [kpair][n] ----
        {
            int kp  = tid >> 5;            // 0..7
            int np0 = tid & 31;
#pragma unroll
            for (int hh = 0; hh < 2; hh++) {
                int np = np0 + hh * 32;    // 0..63
                int n  = np * 2;
                int ka = k0 + kp * 2;
                float a = 0.f, b = 0.f, c = 0.f, d = 0.f;
                if (ka < K)     { float2 t = *(const float2*)(B + (size_t)ka * 128 + n);       a = t.x; b = t.y; }
                if (ka + 1 < K) { float2 t = *(const float2*)(B + (size_t)(ka + 1) * 128 + n); c = t.x; d = t.y; }
                unsigned ha, la, hb_, lb, hc, lc, hd, ld;
                cvt_hilo(a, ha, la); cvt_hilo(b, hb_, lb);
                cvt_hilo(c, hc, lc); cvt_hilo(d, hd, ld);
                Bs_h[kp * 132 + n + 0] = ha  | (hc << 16);
                Bs_h[kp * 132 + n + 1] = hb_ | (hd << 16);
                Bs_l[kp * 132 + n + 0] = la  | (lc << 16);
                Bs_l[kp * 132 + n + 1] = lb  | (ld << 16);
            }
        }
        __syncthreads();

        // ---- fragments + 3-term mma ----
        unsigned ah[4][4];
#pragma unroll
        for (int mt = 0; mt < 4; mt++) {
            int r = wm * 64 + mt * 16 + lr;
            ah[mt][0] = As_h[r * 8 + jj];
            ah[mt][1] = As_h[(r + 8) * 8 + jj];
            ah[mt][2] = As_h[r * 8 + jj + 4];
            ah[mt][3] = As_h[(r + 8) * 8 + jj + 4];
        }
        unsigned bh[4][2];
#pragma unroll
        for (int nt = 0; nt < 4; nt++) {
            int n = wn * 32 + nt * 8 + lr;
            bh[nt][0] = Bs_h[jj * 132 + n];
            bh[nt][1] = Bs_h[(jj + 4) * 132 + n];
        }
        // hi * hi
#pragma unroll
        for (int mt = 0; mt < 4; mt++)
#pragma unroll
            for (int nt = 0; nt < 4; nt++)
                mma16816(acc[mt][nt], ah[mt], bh[nt]);
        // hi * lo
        {
            unsigned bl[4][2];
#pragma unroll
            for (int nt = 0; nt < 4; nt++) {
                int n = wn * 32 + nt * 8 + lr;
                bl[nt][0] = Bs_l[jj * 132 + n];
                bl[nt][1] = Bs_l[(jj + 4) * 132 + n];
            }
#pragma unroll
            for (int mt = 0; mt < 4; mt++)
#pragma unroll
                for (int nt = 0; nt < 4; nt++)
                    mma16816(acc[mt][nt], ah[mt], bl[nt]);
        }
        // lo * hi (reuse ah regs for A-lo fragments)
#pragma unroll
        for (int mt = 0; mt < 4; mt++) {
            int r = wm * 64 + mt * 16 + lr;
            ah[mt][0] = As_l[r * 8 + jj];
            ah[mt][1] = As_l[(r + 8) * 8 + jj];
            ah[mt][2] = As_l[r * 8 + jj + 4];
            ah[mt][3] = As_l[(r + 8) * 8 + jj + 4];
        }
#pragma unroll
        for (int mt = 0; mt < 4; mt++)
#pragma unroll
            for (int nt = 0; nt < 4; nt++)
                mma16816(acc[mt][nt], ah[mt], bh[nt]);
        __syncthreads();
    }

    // ---- epilogue: bias + store ----
    const int lc2 = (lane & 3) * 2;
#pragma unroll
    for (int nt = 0; nt < 4; nt++) {
        int col = wn * 32 + nt * 8 + lc2;
        float b0 = bias[col], b1 = bias[col + 1];
#pragma unroll
        for (int mt = 0; mt < 4; mt++) {
            int r0 = m0 + wm * 64 + mt * 16 + lr;
            float2 o0 = make_float2(acc[mt][nt][0] + b0, acc[mt][nt][1] + b1);
            float2 o1 = make_float2(acc[mt][nt][2] + b0, acc[mt][nt][3] + b1);
            *(float2*)(C + (size_t)r0 * 128 + col)       = o0;
            *(float2*)(C + (size_t)(r0 + 8) * 128 + col) = o1;
        }
    }
}

// ---------------- BatchNorm stats (column mean/var over rows) ----------------
__global__ void colstats(const float* __restrict__ X, int nrows,
                         double* __restrict__ sums, double* __restrict__ sumsq)
{
    int c    = threadIdx.x & 127;
    int half = threadIdx.x >> 7;
    float s = 0.f, s2 = 0.f;
    for (int r = blockIdx.x * 2 + half; r < nrows; r += gridDim.x * 2) {
        float v = X[(size_t)r * 128 + c];
        s += v;
        s2 = fmaf(v, v, s2);
    }
    __shared__ float sh[2][128], sh2[2][128];
    sh[half][c] = s; sh2[half][c] = s2;
    __syncthreads();
    if (half == 0) {
        atomicAdd(&sums[c],  (double)(s  + sh[1][c]));
        atomicAdd(&sumsq[c], (double)(s2 + sh2[1][c]));
    }
}

__global__ void finalize_stats(const double* __restrict__ sums,
                               const double* __restrict__ sumsq,
                               float* __restrict__ mean, float* __restrict__ scl,
                               double inv_n)
{
    int c = threadIdx.x;
    double m   = sums[c] * inv_n;
    double var = sumsq[c] * inv_n - m * m;
    mean[c] = (float)m;
    scl[c]  = (float)(1.0 / sqrt(var + 1e-5));
}

__global__ void bn_apply(const float* __restrict__ X, float* __restrict__ Y,
                         const float* __restrict__ mean, const float* __restrict__ scl,
                         const float* __restrict__ g, const float* __restrict__ b,
                         int nrows, int lrelu)
{
    int total = nrows * 32;
    for (int idx = blockIdx.x * blockDim.x + threadIdx.x; idx < total;
         idx += gridDim.x * blockDim.x) {
        int c4 = idx & 31;
        float4 xv = ((const float4*)X)[idx];
        float4 m4 = ((const float4*)mean)[c4];
        float4 s4 = ((const float4*)scl)[c4];
        float4 g4 = ((const float4*)g)[c4];
        float4 b4 = ((const float4*)b)[c4];
        float4 o;
        o.x = (xv.x - m4.x) * s4.x * g4.x + b4.x;
        o.y = (xv.y - m4.y) * s4.y * g4.y + b4.y;
        o.z = (xv.z - m4.z) * s4.z * g4.z + b4.z;
        o.w = (xv.w - m4.w) * s4.w * g4.w + b4.w;
        if (lrelu) {
            o.x = o.x >= 0.f ? o.x : 0.01f * o.x;
            o.y = o.y >= 0.f ? o.y : 0.01f * o.y;
            o.z = o.z >= 0.f ? o.z : 0.01f * o.z;
            o.w = o.w >= 0.f ? o.w : 0.01f * o.w;
        }
        ((float4*)Y)[idx] = o;
    }
}

// ---------------- per-head LayerNorm over 64-wide halves (in place) ----------------
__global__ void ln_halves(float* __restrict__ q, int nrows)
{
    int warp = (blockIdx.x * blockDim.x + threadIdx.x) >> 5;
    int lane = threadIdx.x & 31;
    if (warp >= nrows) return;
    float4* qp = (float4*)q + (size_t)warp * 32;
    float4 v = qp[lane];
    float s  = v.x + v.y + v.z + v.w;
    float s2 = v.x * v.x + v.y * v.y + v.z * v.z + v.w * v.w;
#pragma unroll
    for (int off = 1; off < 16; off <<= 1) {
        s  += __shfl_xor_sync(0xffffffffu, s,  off);
        s2 += __shfl_xor_sync(0xffffffffu, s2, off);
    }
    float m   = s * (1.f / 64.f);
    float var = s2 * (1.f / 64.f) - m * m;
    float r   = rsqrtf(var + 1e-5f);
    v.x = (v.x - m) * r; v.y = (v.y - m) * r;
    v.z = (v.z - m) * r; v.w = (v.w - m) * r;
    qp[lane] = v;
}

__global__ void fill_neginf(float* __restrict__ a, float* __restrict__ b, int n)
{
    int i = blockIdx.x * blockDim.x + threadIdx.x;
    if (i < n) {
        float ninf = __int_as_float(0xff800000u);
        a[i] = ninf;
        b[i] = ninf;
    }
}

// ---------------- edge pass A: s = q[src].q[dst]/128 per head, segment max ----------------
__global__ void edge_dot_max(const float* __restrict__ q, const int* __restrict__ src,
                             const int* __restrict__ dst, float* __restrict__ s0buf,
                             float* __restrict__ s1buf, float* __restrict__ mx0,
                             float* __restrict__ mx1, int E)
{
    int warp = (blockIdx.x * blockDim.x + threadIdx.x) >> 5;
    int lane = threadIdx.x & 31;
    if (warp >= E) return;
    int s = src[warp], d = dst[warp];
    float4 a = ((const float4*)q)[(size_t)s * 32 + lane];
    float4 b = ((const float4*)q)[(size_t)d * 32 + lane];
    float p = a.x * b.x + a.y * b.y + a.z * b.z + a.w * b.w;
    p += __shfl_xor_sync(0xffffffffu, p, 1);
    p += __shfl_xor_sync(0xffffffffu, p, 2);
    p += __shfl_xor_sync(0xffffffffu, p, 4);
    p += __shfl_xor_sync(0xffffffffu, p, 8);
    float sval = p * (1.0f / 128.0f);
    if (lane == 0)  { s0buf[warp] = sval; atomicMaxFloat(&mx0[s], sval); }
    if (lane == 16) { s1buf[warp] = sval; atomicMaxFloat(&mx1[s], sval); }
}

// ---------------- edge pass B: e = exp(s - mx[src]), segment sum z ----------------
__global__ void edge_exp(float* __restrict__ s0buf, float* __restrict__ s1buf,
                         const int* __restrict__ src, const float* __restrict__ mx0,
                         const float* __restrict__ mx1, float* __restrict__ z0,
                         float* __restrict__ z1, int E)
{
    int e = blockIdx.x * blockDim.x + threadIdx.x;
    if (e >= E) return;
    int s = src[e];
    float e0 = __expf(s0buf[e] - mx0[s]);
    float e1 = __expf(s1buf[e] - mx1[s]);
    s0buf[e] = e0; s1buf[e] = e1;
    atomicAdd(&z0[s], e0);
    atomicAdd(&z1[s], e1);
}

// ---------------- edge pass C: out[src] += att * v[dst] (both heads) ----------------
__global__ void edge_agg(const float* __restrict__ v, const float* __restrict__ e0,
                         const float* __restrict__ e1, const int* __restrict__ src,
                         const int* __restrict__ dst, const float* __restrict__ z0,
                         const float* __restrict__ z1, float* __restrict__ out, int E)
{
    int warp = (blockIdx.x * blockDim.x + threadIdx.x) >> 5;
    int lane = threadIdx.x & 31;
    if (warp >= E) return;
    int s = src[warp], d = dst[warp];
    float att = (lane < 16) ? __fdividef(e0[warp], z0[s]) : __fdividef(e1[warp], z1[s]);
    float4 vv = ((const float4*)v)[(size_t)d * 32 + lane];
    float* op = out + (size_t)s * 128 + lane * 4;
    red_add_v4(op, att * vv.x, att * vv.y, att * vv.z, att * vv.w);
}

// ---------------- superpixel pooling ----------------
__global__ void pool(const float* __restrict__ x0, const int* __restrict__ seg,
                     float* __restrict__ hsum, float* __restrict__ cnt)
{
    int idx = blockIdx.x * blockDim.x + threadIdx.x;
    if (idx >= NPIX * 32) return;
    int pix = idx >> 5, lane = idx & 31;
    int s = seg[pix];
    float4 xv = ((const float4*)x0)[(size_t)pix * 32 + lane];
    float* hs = hsum + (size_t)s * 128 + lane * 4;
    red_add_v4(hs, xv.x, xv.y, xv.z, xv.w);
    if (lane == 0) atomicAdd(&cnt[s], 1.0f);
}

__global__ void hp_div(float* __restrict__ hp, const float* __restrict__ cnt)
{
    int idx = blockIdx.x * blockDim.x + threadIdx.x;
    if (idx >= SP * HD) return;
    hp[idx] = hp[idx] / fmaxf(cnt[idx >> 7], 1.0f);
}

// ---------------- superpixel graph propagate: out[dst] += w * h[src] ----------------
__global__ void sf_prop(const float* __restrict__ h, const int* __restrict__ src,
                        const int* __restrict__ dst, const float* __restrict__ w,
                        float* __restrict__ out, int E)
{
    int warp = (blockIdx.x * blockDim.x + threadIdx.x) >> 5;
    int lane = threadIdx.x & 31;
    if (warp >= E) return;
    int s = src[warp], d = dst[warp];
    float wt = w[warp];
    float4 hv = ((const float4*)h)[(size_t)s * 32 + lane];
    float* op = out + (size_t)d * 128 + lane * 4;
    red_add_v4(op, wt * hv.x, wt * hv.y, wt * hv.z, wt * hv.w);
}

__global__ void sf_combine(float* __restrict__ acc, const float* __restrict__ xs,
                           float* __restrict__ nxt)
{
    int idx = blockIdx.x * blockDim.x + threadIdx.x;
    if (idx >= SP * 32) return;
    float4 a = ((float4*)acc)[idx];
    float4 x = ((const float4*)xs)[idx];
    const float inv = 1.0f / 2.9f;
    float4 o = make_float4((a.x + x.x) * inv, (a.y + x.y) * inv,
                           (a.z + x.z) * inv, (a.w + x.w) * inv);
    ((float4*)nxt)[idx] = o;
    ((float4*)acc)[idx] = make_float4(0.f, 0.f, 0.f, 0.f);
}

// ---------------- final: H1 = pf + hp[seg]; softmax(H1 @ W + b) ----------------
__global__ __launch_bounds__(256) void final_out(
    const float* __restrict__ pf, const float* __restrict__ hp,
    const int* __restrict__ seg, const float* __restrict__ Wout,
    const float* __restrict__ bout, float* __restrict__ out, int nrows)
{
    __shared__ float sWt[16 * 128];   // transposed: [c][k]
    __shared__ float sb[16];
    for (int i = threadIdx.x; i < 2048; i += 256) {
        int k = i >> 4, c = i & 15;
        sWt[c * 128 + k] = Wout[i];
    }
    if (threadIdx.x < 16) sb[threadIdx.x] = bout[threadIdx.x];
    __syncthreads();

    int warp = (blockIdx.x * 256 + threadIdx.x) >> 5;
    int lane = threadIdx.x & 31;
    if (warp >= nrows) return;
    int s = seg[warp];
    float4 a = ((const float4*)pf)[(size_t)warp * 32 + lane];
    float4 b = ((const float4*)hp)[(size_t)s * 32 + lane];
    float4 h = make_float4(a.x + b.x, a.y + b.y, a.z + b.z, a.w + b.w);

    float lg[16];
#pragma unroll
    for (int c = 0; c < 16; c++) {
        float4 w = ((const float4*)sWt)[c * 32 + lane];
        lg[c] = h.x * w.x + h.y * w.y + h.z * w.z + h.w * w.w;
    }
#pragma unroll
    for (int off = 16; off >= 1; off >>= 1)
#pragma unroll
        for (int c = 0; c < 16; c++)
            lg[c] += __shfl_xor_sync(0xffffffffu, lg[c], off);

    if (lane < 16) {
        float mx = -1e30f;
#pragma unroll
        for (int c = 0; c < 16; c++) { lg[c] += sb[c]; mx = fmaxf(mx, lg[c]); }
        float sum = 0.f;
#pragma unroll
        for (int c = 0; c < 16; c++) { lg[c] = __expf(lg[c] - mx); sum += lg[c]; }
        float inv = __fdividef(1.0f, sum);
        float r = 0.f;
#pragma unroll
        for (int c = 0; c < 16; c++) if (lane == c) r = lg[c];
        out[(size_t)warp * 16 + lane] = r * inv;
    }
}

// ---------------- host ----------------
#define GSYM(p, sym) cudaGetSymbolAddress((void**)&p, sym)

static void run_bn(const float* X, float* Y, const float* g, const float* b,
                   int nrows, int lrelu,
                   double* sums, double* sumsq, float* mean, float* scl)
{
    cudaMemsetAsync(sums, 0, HD * sizeof(double));
    cudaMemsetAsync(sumsq, 0, HD * sizeof(double));
    int sblocks = (nrows >= NPIX) ? 512 : 16;
    colstats<<<sblocks, 256>>>(X, nrows, sums, sumsq);
    finalize_stats<<<1, 128>>>(sums, sumsq, mean, scl, 1.0 / (double)nrows);
    int ablocks = (nrows * 32 + 255) / 256;
    if (ablocks > 4096) ablocks = 4096;
    bn_apply<<<ablocks, 256>>>(X, Y, mean, scl, g, b, nrows, lrelu);
}

extern "C" void kernel_launch(void* const* d_in, const int* in_sizes, int n_in,
                              void* d_out, int out_size)
{
    const float* x       = (const float*)d_in[0];
    const int*   seg     = (const int*)  d_in[1];
    const int*   a_src   = (const int*)  d_in[2];
    const int*   a_dst   = (const int*)  d_in[3];
    const float* a_w     = (const float*)d_in[4];
    const int*   m_src   = (const int*)  d_in[5];
    const int*   m_dst   = (const int*)  d_in[6];
    const float* pre_W   = (const float*)d_in[7];
    const float* pre_b   = (const float*)d_in[8];
    const float* bn0_g   = (const float*)d_in[9];
    const float* bn0_b   = (const float*)d_in[10];
    const float* sf_W    = (const float*)d_in[11];
    const float* sf_b    = (const float*)d_in[12];
    const float* sf_g    = (const float*)d_in[13];
    const float* sf_beta = (const float*)d_in[14];
    const float* pf_Wv   = (const float*)d_in[15];
    const float* pf_bv   = (const float*)d_in[16];
    const float* pf_Wq   = (const float*)d_in[17];
    const float* pf_bq   = (const float*)d_in[18];
    const float* pf_g    = (const float*)d_in[19];
    const float* pf_beta = (const float*)d_in[20];
    const float* out_W   = (const float*)d_in[21];
    const float* out_b   = (const float*)d_in[22];
    float* out = (float*)d_out;

    float *x0, *pfa, *pfb, *v, *q, *att, *s0, *s1, *mx0, *mx1, *z0, *z1;
    float *mean, *scl, *hp, *hb, *xs, *acc, *ba, *bb, *cnt, *wv, *wq, *bv, *bq;
    double *sums, *sumsq;
    GSYM(x0, d_x0);   GSYM(pfa, d_pfa); GSYM(pfb, d_pfb);
    GSYM(v, d_v);     GSYM(q, d_q);     GSYM(att, d_att);
    GSYM(s0, d_s0);   GSYM(s1, d_s1);
    GSYM(mx0, d_mx0); GSYM(mx1, d_mx1); GSYM(z0, d_z0); GSYM(z1, d_z1);
    GSYM(sums, d_sums); GSYM(sumsq, d_sumsq); GSYM(mean, d_mean); GSYM(scl, d_scl);
    GSYM(hp, d_hp); GSYM(hb, d_hb); GSYM(xs, d_xs); GSYM(acc, d_acc);
    GSYM(ba, d_ba); GSYM(bb, d_bb); GSYM(cnt, d_cnt);
    GSYM(wv, d_wv); GSYM(wq, d_wq); GSYM(bv, d_bv); GSYM(bq, d_bq);

    // pack per-head attention weights into [128,128]
    pack_weights<<<(2 * HD * HD + 255) / 256, 256>>>(pf_Wv, pf_bv, pf_Wq, pf_bq,
                                                     wv, bv, wq, bq);

    // ---- pre: x0 = BN(x @ pre_W + pre_b) ----
    gemm_tc<<<NPIX / 128, 256>>>(x, pre_W, pre_b, x0, NPIX, CIN);
    run_bn(x0, x0, bn0_g, bn0_b, NPIX, 0, sums, sumsq, mean, scl);

    // ---- PF branch: 2 attention layers on the pixel graph ----
    const float* pin = x0;
    for (int l = 0; l < 2; l++) {
        float* pout = (l == 0) ? pfa : pfb;
        gemm_tc<<<NPIX / 128, 256>>>(pin, wv + l * HD * HD, bv + l * HD, v, NPIX, HD);
        gemm_tc<<<NPIX / 128, 256>>>(pin, wq + l * HD * HD, bq + l * HD, q, NPIX, HD);
        ln_halves<<<NPIX / 8, 256>>>(q, NPIX);
        cudaMemsetAsync(att, 0, (size_t)NPIX * HD * sizeof(float));
        cudaMemsetAsync(z0, 0, NPIX * sizeof(float));
        cudaMemsetAsync(z1, 0, NPIX * sizeof(float));
        fill_neginf<<<NPIX / 256, 256>>>(mx0, mx1, NPIX);
        edge_dot_max<<<EME / 8, 256>>>(q, m_src, m_dst, s0, s1, mx0, mx1, EME);
        edge_exp<<<EME / 256, 256>>>(s0, s1, m_src, mx0, mx1, z0, z1, EME);
        edge_agg<<<EME / 8, 256>>>(v, s0, s1, m_src, m_dst, z0, z1, att, EME);
        run_bn(att, pout, pf_g + l * HD, pf_beta + l * HD, NPIX, 1, sums, sumsq, mean, scl);
        pin = pout;
    }

    // ---- SF branch: pool -> 5 SFNet layers on superpixel graph ----
    cudaMemsetAsync(hp, 0, (size_t)SP * HD * sizeof(float));
    cudaMemsetAsync(cnt, 0, SP * sizeof(float));
    pool<<<NPIX * 32 / 256, 256>>>(x0, seg, hp, cnt);
    hp_div<<<SP * HD / 256, 256>>>(hp, cnt);

    for (int l = 0; l < 5; l++) {
        gemm_tc<<<SP / 128, 256>>>(hp, sf_W + l * HD * HD, sf_b + l * HD, hb, SP, HD);
        cudaMemsetAsync(xs, 0, (size_t)SP * HD * sizeof(float));
        sf_prop<<<EAE * 32 / 256, 256>>>(hb, a_src, a_dst, a_w, xs, EAE);
        cudaMemsetAsync(acc, 0, (size_t)SP * HD * sizeof(float));
        const float* cur = hp;
        for (int it = 0; it < 5; it++) {
            float* nxt = (it & 1) ? bb : ba;
            sf_prop<<<EAE * 32 / 256, 256>>>(cur, a_src, a_dst, a_w, acc, EAE);
            sf_combine<<<SP * 32 / 256, 256>>>(acc, xs, nxt);
            cur = nxt;
        }
        run_bn(cur, hp, sf_g + l * HD, sf_beta + l * HD, SP, 1, sums, sumsq, mean, scl);
    }

    // ---- final: softmax((pf + hp[seg]) @ out_W + out_b) ----
    final_out<<<NPIX / 8, 256>>>(pfb, hp, seg, out_W, out_b, out, NPIX);
}

// round 7
// speedup vs baseline: 1.8079x; 1.3748x over previous
#include <cuda_runtime.h>
#include <cuda_bf16.h>

#define NPIX 262144
#define CIN  200
#define HD   128
#define SP   4096
#define EAE  65536
#define EME  2097152
#define NCLS 16

// ---------------- scratch (device globals; allocation-free rule) ----------------
__device__ float  d_x0 [NPIX*HD];
__device__ float  d_pfa[NPIX*HD];
__device__ float  d_pfb[NPIX*HD];
__device__ float  d_v  [NPIX*HD];
__device__ float  d_q  [NPIX*HD];
__device__ float  d_att[NPIX*HD];
__device__ double d_stats[256];          // sums[128] | sumsq[128]
__device__ float  d_mean [HD];
__device__ float  d_scl  [HD];
__device__ float  d_hp [SP*HD];
__device__ float  d_hb [SP*HD];
__device__ float  d_xs [SP*HD];
__device__ float  d_ba [SP*HD];
__device__ float  d_bb [SP*HD];
__device__ float  d_wv [2*HD*HD];
__device__ float  d_wq [2*HD*HD];
__device__ float  d_bv [2*HD];
__device__ float  d_bq [2*HD];
// CSR scratch: pixel graph (by src)
__device__ int    d_deg   [NPIX];
__device__ int    d_cursor[NPIX];
__device__ int    d_offs  [NPIX+1];
__device__ int    d_btot  [256];
__device__ int    d_csr   [EME];
// superpixel graph (by dst)
__device__ int    d_adeg [SP];
__device__ int    d_acur [SP];
__device__ int    d_aoffs[SP+1];
__device__ int    d_acsrs[EAE];
__device__ float  d_acsrw[EAE];
// seg -> pixel lists
__device__ int    d_sdeg [SP];
__device__ int    d_scur [SP];
__device__ int    d_soffs[SP+1];
__device__ int    d_spix [NPIX];

// ---------------- helpers ----------------
// split fp32 into bf16 hi + bf16 lo (16-bit effective mantissa)
__device__ __forceinline__ void cvt_hilo(float v, unsigned& hi, unsigned& lo) {
    __nv_bfloat16 h = __float2bfloat16(v);
    float r = v - __bfloat162float(h);
    __nv_bfloat16 l = __float2bfloat16(r);
    hi = (unsigned)__bfloat16_as_ushort(h);
    lo = (unsigned)__bfloat16_as_ushort(l);
}

__device__ __forceinline__ void mma16816(float* c, const unsigned* a, const unsigned* b) {
    asm volatile("mma.sync.aligned.m16n8k16.row.col.f32.bf16.bf16.f32 "
                 "{%0,%1,%2,%3}, {%4,%5,%6,%7}, {%8,%9}, {%0,%1,%2,%3};"
                 : "+f"(c[0]), "+f"(c[1]), "+f"(c[2]), "+f"(c[3])
                 : "r"(a[0]), "r"(a[1]), "r"(a[2]), "r"(a[3]),
                   "r"(b[0]), "r"(b[1]));
}

// ---------------- CSR construction ----------------
__global__ void hist_kernel(const int* __restrict__ idx, int* __restrict__ deg, int n)
{
    int i = blockIdx.x * blockDim.x + threadIdx.x;
    if (i < n) atomicAdd(&deg[idx[i]], 1);
}

// 256 blocks x 256 threads, 4 elems/thread -> exclusive scan of 262144 chunked
__global__ void scan_chunk(const int* __restrict__ deg, int* __restrict__ offs,
                           int* __restrict__ btot)
{
    __shared__ int ts[256];
    int t = threadIdx.x;
    int base = blockIdx.x * 1024 + t * 4;
    int a0 = deg[base], a1 = deg[base+1], a2 = deg[base+2], a3 = deg[base+3];
    int s = a0 + a1 + a2 + a3;
    ts[t] = s; __syncthreads();
    for (int off = 1; off < 256; off <<= 1) {
        int v = (t >= off) ? ts[t - off] : 0;
        __syncthreads();
        ts[t] += v;
        __syncthreads();
    }
    int excl = ts[t] - s;
    offs[base]   = excl;
    offs[base+1] = excl + a0;
    offs[base+2] = excl + a0 + a1;
    offs[base+3] = excl + a0 + a1 + a2;
    if (t == 255) btot[blockIdx.x] = ts[255];
}

__global__ void scan_btot(int* __restrict__ btot)
{
    __shared__ int ts[256];
    int t = threadIdx.x;
    int v = btot[t];
    ts[t] = v; __syncthreads();
    for (int off = 1; off < 256; off <<= 1) {
        int u = (t >= off) ? ts[t - off] : 0;
        __syncthreads();
        ts[t] += u;
        __syncthreads();
    }
    btot[t] = ts[t] - v;
}

__global__ void scan_add(int* __restrict__ offs, const int* __restrict__ btot,
                         int* __restrict__ cursor, int n, int total)
{
    int i = blockIdx.x * blockDim.x + threadIdx.x;
    if (i < n) {
        int v = offs[i] + btot[i >> 10];
        offs[i] = v;
        cursor[i] = v;
    }
    if (i == 0) offs[n] = total;
}

// single block, 1024 threads, 4 elems/thread -> exclusive scan of 4096
__global__ void scan4k(const int* __restrict__ deg, int* __restrict__ offs,
                       int* __restrict__ cursor, int total)
{
    __shared__ int ts[1024];
    int t = threadIdx.x;
    int base = t * 4;
    int a0 = deg[base], a1 = deg[base+1], a2 = deg[base+2], a3 = deg[base+3];
    int s = a0 + a1 + a2 + a3;
    ts[t] = s; __syncthreads();
    for (int off = 1; off < 1024; off <<= 1) {
        int v = (t >= off) ? ts[t - off] : 0;
        __syncthreads();
        ts[t] += v;
        __syncthreads();
    }
    int excl = ts[t] - s;
    int o0 = excl, o1 = excl + a0, o2 = excl + a0 + a1, o3 = excl + a0 + a1 + a2;
    offs[base] = o0;   cursor[base] = o0;
    offs[base+1] = o1; cursor[base+1] = o1;
    offs[base+2] = o2; cursor[base+2] = o2;
    offs[base+3] = o3; cursor[base+3] = o3;
    if (t == 1023) offs[4096] = total;
}

__global__ void scatter_px(const int* __restrict__ src, const int* __restrict__ dst,
                           int* __restrict__ cursor, int* __restrict__ csr, int n)
{
    int e = blockIdx.x * blockDim.x + threadIdx.x;
    if (e < n) {
        int p = atomicAdd(&cursor[src[e]], 1);
        csr[p] = dst[e];
    }
}

__global__ void scatter_a(const int* __restrict__ asrc, const int* __restrict__ adst,
                          const float* __restrict__ aw, int* __restrict__ cursor,
                          int* __restrict__ csrs, float* __restrict__ csrw, int n)
{
    int e = blockIdx.x * blockDim.x + threadIdx.x;
    if (e < n) {
        int p = atomicAdd(&cursor[adst[e]], 1);
        csrs[p] = asrc[e];
        csrw[p] = aw[e];
    }
}

__global__ void scatter_seg(const int* __restrict__ seg, int* __restrict__ cursor,
                            int* __restrict__ csr, int n)
{
    int i = blockIdx.x * blockDim.x + threadIdx.x;
    if (i < n) {
        int p = atomicAdd(&cursor[seg[i]], 1);
        csr[p] = i;
    }
}

// ---------------- weight packing: [2][2][128][64] -> [2][128][128] ----------------
__global__ void pack_weights(const float* __restrict__ Wv, const float* __restrict__ bv,
                             const float* __restrict__ Wq, const float* __restrict__ bq,
                             float* __restrict__ wvp, float* __restrict__ bvp,
                             float* __restrict__ wqp, float* __restrict__ bqp)
{
    int idx = blockIdx.x * blockDim.x + threadIdx.x;
    if (idx >= 2 * HD * HD) return;
    int l = idx >> 14;
    int rem = idx & 16383;
    int k = rem >> 7;
    int c = rem & 127;
    int h = c >> 6;
    int j = c & 63;
    int sidx = ((l * 2 + h) * HD + k) * 64 + j;
    wvp[idx] = Wv[sidx];
    wqp[idx] = Wq[sidx];
    if (k == 0) {
        bvp[(l << 7) | c] = bv[(l * 2 + h) * 64 + j];
        bqp[(l << 7) | c] = bq[(l * 2 + h) * 64 + j];
    }
}

// ---------------- Tensor-core GEMM: C[M,128] = A[M,K] @ B[K,128] + bias ----------------
__global__ __launch_bounds__(256) void gemm_tc(
    const float* __restrict__ A, const float* __restrict__ B,
    const float* __restrict__ bias, float* __restrict__ C, int M, int K)
{
    __shared__ unsigned As_h[128 * 8];
    __shared__ unsigned As_l[128 * 8];
    __shared__ unsigned Bs_h[8 * 132];
    __shared__ unsigned Bs_l[8 * 132];

    const int tid  = threadIdx.x;
    const int lane = tid & 31;
    const int warp = tid >> 5;
    const int wm   = warp >> 2;
    const int wn   = warp & 3;
    const int m0   = blockIdx.x * 128;

    float acc[4][4][4];
#pragma unroll
    for (int mt = 0; mt < 4; mt++)
#pragma unroll
        for (int nt = 0; nt < 4; nt++)
#pragma unroll
            for (int i = 0; i < 4; i++) acc[mt][nt][i] = 0.f;

    const int lr = lane >> 2;
    const int jj = lane & 3;

    for (int k0 = 0; k0 < K; k0 += 16) {
        {
            int r  = tid & 127;
            int qb = (tid >> 7) << 1;
            const float* ap = A + (size_t)(m0 + r) * K;
#pragma unroll
            for (int qq = 0; qq < 2; qq++) {
                int q  = qb + qq;
                int kk = k0 + q * 4;
                float v0 = 0.f, v1 = 0.f, v2 = 0.f, v3 = 0.f;
                if (kk + 3 < K) {
                    float4 t = *(const float4*)(ap + kk);
                    v0 = t.x; v1 = t.y; v2 = t.z; v3 = t.w;
                } else {
                    if (kk + 0 < K) v0 = ap[kk + 0];
                    if (kk + 1 < K) v1 = ap[kk + 1];
                    if (kk + 2 < K) v2 = ap[kk + 2];
                    if (kk + 3 < K) v3 = ap[kk + 3];
                }
                unsigned h0, l0, h1, l1, h2, l2, h3, l3;
                cvt_hilo(v0, h0, l0); cvt_hilo(v1, h1, l1);
                cvt_hilo(v2, h2, l2); cvt_hilo(v3, h3, l3);
                As_h[r * 8 + q * 2 + 0] = h0 | (h1 << 16);
                As_h[r * 8 + q * 2 + 1] = h2 | (h3 << 16);
                As_l[r * 8 + q * 2 + 0] = l0 | (l1 << 16);
                As_l[r * 8 + q * 2 + 1] = l2 | (l3 << 16);
            }
        }
        {
            int kp  = tid >> 5;
            int np0 = tid & 31;
#pragma unroll
            for (int hh = 0; hh < 2; hh++) {
                int np = np0 + hh * 32;
                int n  = np * 2;
                int ka = k0 + kp * 2;
                float a = 0.f, b = 0.f, c = 0.f, d = 0.f;
                if (ka < K)     { float2 t = *(const float2*)(B + (size_t)ka * 128 + n);       a = t.x; b = t.y; }
                if (ka + 1 < K) { float2 t = *(const float2*)(B + (size_t)(ka + 1) * 128 + n); c = t.x; d = t.y; }
                unsigned ha, la, hb_, lb, hc, lc, hd, ld;
                cvt_hilo(a, ha, la); cvt_hilo(b, hb_, lb);
                cvt_hilo(c, hc, lc); cvt_hilo(d, hd, ld);
                Bs_h[kp * 132 + n + 0] = ha  | (hc << 16);
                Bs_h[kp * 132 + n + 1] = hb_ | (hd << 16);
                Bs_l[kp * 132 + n + 0] = la  | (lc << 16);
                Bs_l[kp * 132 + n + 1] = lb  | (ld << 16);
            }
        }
        __syncthreads();

        unsigned ah[4][4];
#pragma unroll
        for (int mt = 0; mt < 4; mt++) {
            int r = wm * 64 + mt * 16 + lr;
            ah[mt][0] = As_h[r * 8 + jj];
            ah[mt][1] = As_h[(r + 8) * 8 + jj];
            ah[mt][2] = As_h[r * 8 + jj + 4];
            ah[mt][3] = As_h[(r + 8) * 8 + jj + 4];
        }
        unsigned bh[4][2];
#pragma unroll
        for (int nt = 0; nt < 4; nt++) {
            int n = wn * 32 + nt * 8 + lr;
            bh[nt][0] = Bs_h[jj * 132 + n];
            bh[nt][1] = Bs_h[(jj + 4) * 132 + n];
        }
#pragma unroll
        for (int mt = 0; mt < 4; mt++)
#pragma unroll
            for (int nt = 0; nt < 4; nt++)
                mma16816(acc[mt][nt], ah[mt], bh[nt]);
        {
            unsigned bl[4][2];
#pragma unroll
            for (int nt = 0; nt < 4; nt++) {
                int n = wn * 32 + nt * 8 + lr;
                bl[nt][0] = Bs_l[jj * 132 + n];
                bl[nt][1] = Bs_l[(jj + 4) * 132 + n];
            }
#pragma unroll
            for (int mt = 0; mt < 4; mt++)
#pragma unroll
                for (int nt = 0; nt < 4; nt++)
                    mma16816(acc[mt][nt], ah[mt], bl[nt]);
        }
#pragma unroll
        for (int mt = 0; mt < 4; mt++) {
            int r = wm * 64 + mt * 16 + lr;
            ah[mt][0] = As_l[r * 8 + jj];
            ah[mt][1] = As_l[(r + 8) * 8 + jj];
            ah[mt][2] = As_l[r * 8 + jj + 4];
            ah[mt][3] = As_l[(r + 8) * 8 + jj + 4];
        }
#pragma unroll
        for (int mt = 0; mt < 4; mt++)
#pragma unroll
            for (int nt = 0; nt < 4; nt++)
                mma16816(acc[mt][nt], ah[mt], bh[nt]);
        __syncthreads();
    }

    const int lc2 = (lane & 3) * 2;
#pragma unroll
    for (int nt = 0; nt < 4; nt++) {
        int col = wn * 32 + nt * 8 + lc2;
        float b0 = bias[col], b1 = bias[col + 1];
#pragma unroll
        for (int mt = 0; mt < 4; mt++) {
            int r0 = m0 + wm * 64 + mt * 16 + lr;
            float2 o0 = make_float2(acc[mt][nt][0] + b0, acc[mt][nt][1] + b1);
            float2 o1 = make_float2(acc[mt][nt][2] + b0, acc[mt][nt][3] + b1);
            *(float2*)(C + (size_t)r0 * 128 + col)       = o0;
            *(float2*)(C + (size_t)(r0 + 8) * 128 + col) = o1;
        }
    }
}

// ---------------- BatchNorm (big, 3-kernel) ----------------
__global__ void colstats(const float* __restrict__ X, int nrows,
                         double* __restrict__ stats)
{
    int c    = threadIdx.x & 127;
    int half = threadIdx.x >> 7;
    float s = 0.f, s2 = 0.f;
    for (int r = blockIdx.x * 2 + half; r < nrows; r += gridDim.x * 2) {
        float v = X[(size_t)r * 128 + c];
        s += v;
        s2 = fmaf(v, v, s2);
    }
    __shared__ float sh[2][128], sh2[2][128];
    sh[half][c] = s; sh2[half][c] = s2;
    __syncthreads();
    if (half == 0) {
        atomicAdd(&stats[c],       (double)(s  + sh[1][c]));
        atomicAdd(&stats[128 + c], (double)(s2 + sh2[1][c]));
    }
}

__global__ void finalize_stats(const double* __restrict__ stats,
                               float* __restrict__ mean, float* __restrict__ scl,
                               double inv_n)
{
    int c = threadIdx.x;
    double m   = stats[c] * inv_n;
    double var = stats[128 + c] * inv_n - m * m;
    mean[c] = (float)m;
    scl[c]  = (float)(1.0 / sqrt(var + 1e-5));
}

__global__ void bn_apply(const float* __restrict__ X, float* __restrict__ Y,
                         const float* __restrict__ mean, const float* __restrict__ scl,
                         const float* __restrict__ g, const float* __restrict__ b,
                         int nrows, int lrelu)
{
    int total = nrows * 32;
    for (int idx = blockIdx.x * blockDim.x + threadIdx.x; idx < total;
         idx += gridDim.x * blockDim.x) {
        int c4 = idx & 31;
        float4 xv = ((const float4*)X)[idx];
        float4 m4 = ((const float4*)mean)[c4];
        float4 s4 = ((const float4*)scl)[c4];
        float4 g4 = ((const float4*)g)[c4];
        float4 b4 = ((const float4*)b)[c4];
        float4 o;
        o.x = (xv.x - m4.x) * s4.x * g4.x + b4.x;
        o.y = (xv.y - m4.y) * s4.y * g4.y + b4.y;
        o.z = (xv.z - m4.z) * s4.z * g4.z + b4.z;
        o.w = (xv.w - m4.w) * s4.w * g4.w + b4.w;
        if (lrelu) {
            o.x = o.x >= 0.f ? o.x : 0.01f * o.x;
            o.y = o.y >= 0.f ? o.y : 0.01f * o.y;
            o.z = o.z >= 0.f ? o.z : 0.01f * o.z;
            o.w = o.w >= 0.f ? o.w : 0.01f * o.w;
        }
        ((float4*)Y)[idx] = o;
    }
}

// ---------------- BatchNorm (small, fused: stats + apply + lrelu) ----------------
// grid = 32 blocks (one float4-column each), 128 threads
__global__ void bn_small(const float* __restrict__ X, float* __restrict__ Y,
                         const float* __restrict__ g, const float* __restrict__ b,
                         int nrows)
{
    int bcol = blockIdx.x;
    int t = threadIdx.x;
    float4 s  = make_float4(0.f, 0.f, 0.f, 0.f);
    float4 s2 = make_float4(0.f, 0.f, 0.f, 0.f);
    for (int r = t; r < nrows; r += 128) {
        float4 v = ((const float4*)X)[(size_t)r * 32 + bcol];
        s.x += v.x; s.y += v.y; s.z += v.z; s.w += v.w;
        s2.x = fmaf(v.x, v.x, s2.x); s2.y = fmaf(v.y, v.y, s2.y);
        s2.z = fmaf(v.z, v.z, s2.z); s2.w = fmaf(v.w, v.w, s2.w);
    }
    __shared__ float4 sh[128], sh2[128];
    sh[t] = s; sh2[t] = s2;
    __syncthreads();
    for (int off = 64; off >= 1; off >>= 1) {
        if (t < off) {
            sh[t].x += sh[t+off].x; sh[t].y += sh[t+off].y;
            sh[t].z += sh[t+off].z; sh[t].w += sh[t+off].w;
            sh2[t].x += sh2[t+off].x; sh2[t].y += sh2[t+off].y;
            sh2[t].z += sh2[t+off].z; sh2[t].w += sh2[t+off].w;
        }
        __syncthreads();
    }
    __shared__ float4 mean4, scl4;
    if (t == 0) {
        float inv = 1.f / (float)nrows;
        float4 m = make_float4(sh[0].x*inv, sh[0].y*inv, sh[0].z*inv, sh[0].w*inv);
        mean4 = m;
        scl4.x = rsqrtf(sh2[0].x*inv - m.x*m.x + 1e-5f);
        scl4.y = rsqrtf(sh2[0].y*inv - m.y*m.y + 1e-5f);
        scl4.z = rsqrtf(sh2[0].z*inv - m.z*m.z + 1e-5f);
        scl4.w = rsqrtf(sh2[0].w*inv - m.w*m.w + 1e-5f);
    }
    __syncthreads();
    float4 g4 = ((const float4*)g)[bcol];
    float4 b4 = ((const float4*)b)[bcol];
    float4 m4 = mean4, c4 = scl4;
    for (int r = t; r < nrows; r += 128) {
        float4 v = ((const float4*)X)[(size_t)r * 32 + bcol];
        float4 o;
        o.x = (v.x - m4.x) * c4.x * g4.x + b4.x;
        o.y = (v.y - m4.y) * c4.y * g4.y + b4.y;
        o.z = (v.z - m4.z) * c4.z * g4.z + b4.z;
        o.w = (v.w - m4.w) * c4.w * g4.w + b4.w;
        o.x = o.x >= 0.f ? o.x : 0.01f * o.x;
        o.y = o.y >= 0.f ? o.y : 0.01f * o.y;
        o.z = o.z >= 0.f ? o.z : 0.01f * o.z;
        o.w = o.w >= 0.f ? o.w : 0.01f * o.w;
        ((float4*)Y)[(size_t)r * 32 + bcol] = o;
    }
}

// ---------------- per-head LayerNorm over 64-wide halves (in place) ----------------
__global__ void ln_halves(float* __restrict__ q, int nrows)
{
    int warp = (blockIdx.x * blockDim.x + threadIdx.x) >> 5;
    int lane = threadIdx.x & 31;
    if (warp >= nrows) return;
    float4* qp = (float4*)q + (size_t)warp * 32;
    float4 v = qp[lane];
    float s  = v.x + v.y + v.z + v.w;
    float s2 = v.x * v.x + v.y * v.y + v.z * v.z + v.w * v.w;
#pragma unroll
    for (int off = 1; off < 16; off <<= 1) {
        s  += __shfl_xor_sync(0xffffffffu, s,  off);
        s2 += __shfl_xor_sync(0xffffffffu, s2, off);
    }
    float m   = s * (1.f / 64.f);
    float var = s2 * (1.f / 64.f) - m * m;
    float r   = rsqrtf(var + 1e-5f);
    v.x = (v.x - m) * r; v.y = (v.y - m) * r;
    v.z = (v.z - m) * r; v.w = (v.w - m) * r;
    qp[lane] = v;
}

// ---------------- fused per-node attention (online softmax, warp per node) -----
__global__ __launch_bounds__(256) void pf_attn(
    const float* __restrict__ q, const float* __restrict__ v,
    const int* __restrict__ offs, const int* __restrict__ csr,
    float* __restrict__ out)
{
    int n    = (blockIdx.x * 256 + threadIdx.x) >> 5;
    int lane = threadIdx.x & 31;
    int e0 = offs[n], e1 = offs[n + 1];
    float4 qn = ((const float4*)q)[(size_t)n * 32 + lane];
    float m = __int_as_float(0xff800000);   // -inf
    float z = 0.f;
    float4 acc = make_float4(0.f, 0.f, 0.f, 0.f);
    int d = (e0 < e1) ? csr[e0] : 0;
    for (int e = e0; e < e1; e++) {
        int dn = (e + 1 < e1) ? csr[e + 1] : d;
        float4 qd = ((const float4*)q)[(size_t)d * 32 + lane];
        float4 vd = ((const float4*)v)[(size_t)d * 32 + lane];
        float p = qn.x * qd.x + qn.y * qd.y + qn.z * qd.z + qn.w * qd.w;
        p += __shfl_xor_sync(0xffffffffu, p, 1);
        p += __shfl_xor_sync(0xffffffffu, p, 2);
        p += __shfl_xor_sync(0xffffffffu, p, 4);
        p += __shfl_xor_sync(0xffffffffu, p, 8);
        float s = p * (1.0f / 128.0f);      // per 16-lane half (head)
        float mn = fmaxf(m, s);
        float sc = __expf(m - mn);
        float ee = __expf(s - mn);
        z = z * sc + ee;
        acc.x = acc.x * sc + ee * vd.x;
        acc.y = acc.y * sc + ee * vd.y;
        acc.z = acc.z * sc + ee * vd.z;
        acc.w = acc.w * sc + ee * vd.w;
        m = mn;
        d = dn;
    }
    float iz = (z > 0.f) ? __fdividef(1.f, z) : 0.f;
    ((float4*)out)[(size_t)n * 32 + lane] =
        make_float4(acc.x * iz, acc.y * iz, acc.z * iz, acc.w * iz);
}

// ---------------- fused superpixel pooling (warp per superpixel) ----------------
__global__ __launch_bounds__(256) void pool_f(
    const float* __restrict__ x0, const int* __restrict__ offs,
    const int* __restrict__ pix, float* __restrict__ hp)
{
    int s    = (blockIdx.x * 256 + threadIdx.x) >> 5;
    int lane = threadIdx.x & 31;
    int e0 = offs[s], e1 = offs[s + 1];
    float4 acc = make_float4(0.f, 0.f, 0.f, 0.f);
    for (int e = e0; e < e1; e++) {
        int p = pix[e];
        float4 xv = ((const float4*)x0)[(size_t)p * 32 + lane];
        acc.x += xv.x; acc.y += xv.y; acc.z += xv.z; acc.w += xv.w;
    }
    float ic = 1.f / fmaxf((float)(e1 - e0), 1.f);
    ((float4*)hp)[(size_t)s * 32 + lane] =
        make_float4(acc.x * ic, acc.y * ic, acc.z * ic, acc.w * ic);
}

// ---------------- fused superpixel propagate (warp per dst node) ----------------
// mode 0: out[n] = sum w*h[src]          (x_start)
// mode 1: out[n] = (sum w*h[src] + xs[n]) / 2.9
__global__ __launch_bounds__(256) void sf_prop_f(
    const float* __restrict__ h, const int* __restrict__ offs,
    const int* __restrict__ csrs, const float* __restrict__ csrw,
    const float* __restrict__ xs, float* __restrict__ out, int mode)
{
    int n    = (blockIdx.x * 256 + threadIdx.x) >> 5;
    int lane = threadIdx.x & 31;
    int e0 = offs[n], e1 = offs[n + 1];
    float4 acc = make_float4(0.f, 0.f, 0.f, 0.f);
    for (int e = e0; e < e1; e++) {
        int s = csrs[e];
        float w = csrw[e];
        float4 hv = ((const float4*)h)[(size_t)s * 32 + lane];
        acc.x = fmaf(w, hv.x, acc.x);
        acc.y = fmaf(w, hv.y, acc.y);
        acc.z = fmaf(w, hv.z, acc.z);
        acc.w = fmaf(w, hv.w, acc.w);
    }
    if (mode == 0) {
        ((float4*)out)[(size_t)n * 32 + lane] = acc;
    } else {
        float4 x = ((const float4*)xs)[(size_t)n * 32 + lane];
        const float inv = 1.0f / 2.9f;
        ((float4*)out)[(size_t)n * 32 + lane] =
            make_float4((acc.x + x.x) * inv, (acc.y + x.y) * inv,
                        (acc.z + x.z) * inv, (acc.w + x.w) * inv);
    }
}

// ---------------- final: H1 = pf + hp[seg]; softmax(H1 @ W + b) ----------------
__global__ __launch_bounds__(256) void final_out(
    const float* __restrict__ pf, const float* __restrict__ hp,
    const int* __restrict__ seg, const float* __restrict__ Wout,
    const float* __restrict__ bout, float* __restrict__ out, int nrows)
{
    __shared__ float sWt[16 * 128];
    __shared__ float sb[16];
    for (int i = threadIdx.x; i < 2048; i += 256) {
        int k = i >> 4, c = i & 15;
        sWt[c * 128 + k] = Wout[i];
    }
    if (threadIdx.x < 16) sb[threadIdx.x] = bout[threadIdx.x];
    __syncthreads();

    int warp = (blockIdx.x * 256 + threadIdx.x) >> 5;
    int lane = threadIdx.x & 31;
    if (warp >= nrows) return;
    int s = seg[warp];
    float4 a = ((const float4*)pf)[(size_t)warp * 32 + lane];
    float4 b = ((const float4*)hp)[(size_t)s * 32 + lane];
    float4 h = make_float4(a.x + b.x, a.y + b.y, a.z + b.z, a.w + b.w);

    float lg[16];
#pragma unroll
    for (int c = 0; c < 16; c++) {
        float4 w = ((const float4*)sWt)[c * 32 + lane];
        lg[c] = h.x * w.x + h.y * w.y + h.z * w.z + h.w * w.w;
    }
#pragma unroll
    for (int off = 16; off >= 1; off >>= 1)
#pragma unroll
        for (int c = 0; c < 16; c++)
            lg[c] += __shfl_xor_sync(0xffffffffu, lg[c], off);

    if (lane < 16) {
        float mx = -1e30f;
#pragma unroll
        for (int c = 0; c < 16; c++) { lg[c] += sb[c]; mx = fmaxf(mx, lg[c]); }
        float sum = 0.f;
#pragma unroll
        for (int c = 0; c < 16; c++) { lg[c] = __expf(lg[c] - mx); sum += lg[c]; }
        float inv = __fdividef(1.0f, sum);
        float r = 0.f;
#pragma unroll
        for (int c = 0; c < 16; c++) if (lane == c) r = lg[c];
        out[(size_t)warp * 16 + lane] = r * inv;
    }
}

// ---------------- host ----------------
#define GSYM(p, sym) cudaGetSymbolAddress((void**)&p, sym)

static void run_bn(const float* X, float* Y, const float* g, const float* b,
                   int nrows, int lrelu,
                   double* stats, float* mean, float* scl)
{
    cudaMemsetAsync(stats, 0, 256 * sizeof(double));
    colstats<<<512, 256>>>(X, nrows, stats);
    finalize_stats<<<1, 128>>>(stats, mean, scl, 1.0 / (double)nrows);
    int ablocks = (nrows * 32 + 255) / 256;
    if (ablocks > 4096) ablocks = 4096;
    bn_apply<<<ablocks, 256>>>(X, Y, mean, scl, g, b, nrows, lrelu);
}

extern "C" void kernel_launch(void* const* d_in, const int* in_sizes, int n_in,
                              void* d_out, int out_size)
{
    const float* x       = (const float*)d_in[0];
    const int*   seg     = (const int*)  d_in[1];
    const int*   a_src   = (const int*)  d_in[2];
    const int*   a_dst   = (const int*)  d_in[3];
    const float* a_w     = (const float*)d_in[4];
    const int*   m_src   = (const int*)  d_in[5];
    const int*   m_dst   = (const int*)  d_in[6];
    const float* pre_W   = (const float*)d_in[7];
    const float* pre_b   = (const float*)d_in[8];
    const float* bn0_g   = (const float*)d_in[9];
    const float* bn0_b   = (const float*)d_in[10];
    const float* sf_W    = (const float*)d_in[11];
    const float* sf_b    = (const float*)d_in[12];
    const float* sf_g    = (const float*)d_in[13];
    const float* sf_beta = (const float*)d_in[14];
    const float* pf_Wv   = (const float*)d_in[15];
    const float* pf_bv   = (const float*)d_in[16];
    const float* pf_Wq   = (const float*)d_in[17];
    const float* pf_bq   = (const float*)d_in[18];
    const float* pf_g    = (const float*)d_in[19];
    const float* pf_beta = (const float*)d_in[20];
    const float* out_W   = (const float*)d_in[21];
    const float* out_b   = (const float*)d_in[22];
    float* out = (float*)d_out;

    float *x0, *pfa, *pfb, *v, *q, *att;
    float *mean, *scl, *hp, *hb, *xs, *ba, *bb, *wv, *wq, *bv, *bq;
    double *stats;
    int *deg, *cursor, *offs, *btot, *csr;
    int *adeg, *acur, *aoffs, *acsrs;
    float *acsrw;
    int *sdeg, *scur, *soffs, *spix;
    GSYM(x0, d_x0);   GSYM(pfa, d_pfa); GSYM(pfb, d_pfb);
    GSYM(v, d_v);     GSYM(q, d_q);     GSYM(att, d_att);
    GSYM(stats, d_stats); GSYM(mean, d_mean); GSYM(scl, d_scl);
    GSYM(hp, d_hp); GSYM(hb, d_hb); GSYM(xs, d_xs);
    GSYM(ba, d_ba); GSYM(bb, d_bb);
    GSYM(wv, d_wv); GSYM(wq, d_wq); GSYM(bv, d_bv); GSYM(bq, d_bq);
    GSYM(deg, d_deg); GSYM(cursor, d_cursor); GSYM(offs, d_offs);
    GSYM(btot, d_btot); GSYM(csr, d_csr);
    GSYM(adeg, d_adeg); GSYM(acur, d_acur); GSYM(aoffs, d_aoffs);
    GSYM(acsrs, d_acsrs); GSYM(acsrw, d_acsrw);
    GSYM(sdeg, d_sdeg); GSYM(scur, d_scur); GSYM(soffs, d_soffs);
    GSYM(spix, d_spix);

    // ---- build CSRs (pixel graph by src; a-graph by dst; seg lists) ----
    cudaMemsetAsync(deg, 0, NPIX * sizeof(int));
    hist_kernel<<<EME / 256, 256>>>(m_src, deg, EME);
    scan_chunk<<<256, 256>>>(deg, offs, btot);
    scan_btot<<<1, 256>>>(btot);
    scan_add<<<NPIX / 256, 256>>>(offs, btot, cursor, NPIX, EME);
    scatter_px<<<EME / 256, 256>>>(m_src, m_dst, cursor, csr, EME);

    cudaMemsetAsync(adeg, 0, SP * sizeof(int));
    hist_kernel<<<EAE / 256, 256>>>(a_dst, adeg, EAE);
    scan4k<<<1, 1024>>>(adeg, aoffs, acur, EAE);
    scatter_a<<<EAE / 256, 256>>>(a_src, a_dst, a_w, acur, acsrs, acsrw, EAE);

    cudaMemsetAsync(sdeg, 0, SP * sizeof(int));
    hist_kernel<<<NPIX / 256, 256>>>(seg, sdeg, NPIX);
    scan4k<<<1, 1024>>>(sdeg, soffs, scur, NPIX);
    scatter_seg<<<NPIX / 256, 256>>>(seg, scur, spix, NPIX);

    // pack per-head attention weights into [128,128]
    pack_weights<<<(2 * HD * HD + 255) / 256, 256>>>(pf_Wv, pf_bv, pf_Wq, pf_bq,
                                                     wv, bv, wq, bq);

    // ---- pre: x0 = BN(x @ pre_W + pre_b) ----
    gemm_tc<<<NPIX / 128, 256>>>(x, pre_W, pre_b, x0, NPIX, CIN);
    run_bn(x0, x0, bn0_g, bn0_b, NPIX, 0, stats, mean, scl);

    // ---- PF branch: 2 attention layers on the pixel graph ----
    const float* pin = x0;
    for (int l = 0; l < 2; l++) {
        float* pout = (l == 0) ? pfa : pfb;
        gemm_tc<<<NPIX / 128, 256>>>(pin, wv + l * HD * HD, bv + l * HD, v, NPIX, HD);
        gemm_tc<<<NPIX / 128, 256>>>(pin, wq + l * HD * HD, bq + l * HD, q, NPIX, HD);
        ln_halves<<<NPIX / 8, 256>>>(q, NPIX);
        pf_attn<<<NPIX / 8, 256>>>(q, v, offs, csr, att);
        run_bn(att, pout, pf_g + l * HD, pf_beta + l * HD, NPIX, 1, stats, mean, scl);
        pin = pout;
    }

    // ---- SF branch: pool -> 5 SFNet layers on superpixel graph ----
    pool_f<<<SP / 8, 256>>>(x0, soffs, spix, hp);

    for (int l = 0; l < 5; l++) {
        gemm_tc<<<SP / 128, 256>>>(hp, sf_W + l * HD * HD, sf_b + l * HD, hb, SP, HD);
        sf_prop_f<<<SP / 8, 256>>>(hb, aoffs, acsrs, acsrw, xs, xs, 0);
        const float* cur = hp;
        for (int it = 0; it < 5; it++) {
            float* nxt = (it & 1) ? bb : ba;
            sf_prop_f<<<SP / 8, 256>>>(cur, aoffs, acsrs, acsrw, xs, nxt, 1);
            cur = nxt;
        }
        bn_small<<<32, 128>>>(cur, hp, sf_g + l * HD, sf_beta + l * HD, SP);
    }

    // ---- final: softmax((pf + hp[seg]) @ out_W + out_b) ----
    final_out<<<NPIX / 8, 256>>>(pfb, hp, seg, out_W, out_b, out, NPIX);
}

// round 9
// speedup vs baseline: 1.9976x; 1.1049x over previous
#include <cuda_runtime.h>
#include <cuda_bf16.h>

#define NPIX 262144
#define CIN  200
#define HD   128
#define SP   4096
#define EAE  65536
#define EME  2097152
#define NCLS 16

// ---------------- scratch (device globals; allocation-free rule) ----------------
__device__ float  d_x0 [NPIX*HD];
__device__ float  d_pfa[NPIX*HD];
__device__ float  d_pfb[NPIX*HD];
__device__ float  d_v  [NPIX*HD];
__device__ float  d_q  [NPIX*HD];
__device__ unsigned short d_qh[NPIX*HD];   // bf16 q for edge phase
__device__ double d_stats[256];            // sums[128] | sumsq[128]
__device__ float  d_affA[3*HD];            // per-BN fused scale
__device__ float  d_affB[3*HD];            // per-BN fused shift
__device__ float  d_hp [SP*HD];
__device__ float  d_hb [SP*HD];
__device__ float  d_xs [SP*HD];
__device__ float  d_ba [SP*HD];
__device__ float  d_bb [SP*HD];
__device__ float  d_wv [2*HD*HD];
__device__ float  d_wq [2*HD*HD];
__device__ float  d_bv [2*HD];
__device__ float  d_bq [2*HD];
// CSR scratch: pixel graph (by src)
__device__ int    d_deg   [NPIX];
__device__ int    d_cursor[NPIX];
__device__ int    d_offs  [NPIX+1];
__device__ int    d_btot  [256];
__device__ int    d_csr   [EME];
// superpixel graph (by dst)
__device__ int    d_adeg [SP];
__device__ int    d_acur [SP];
__device__ int    d_aoffs[SP+1];
__device__ int    d_acsrs[EAE];
__device__ float  d_acsrw[EAE];
// seg -> pixel lists
__device__ int    d_sdeg [SP];
__device__ int    d_scur [SP];
__device__ int    d_soffs[SP+1];
__device__ int    d_spix [NPIX];

// ---------------- helpers ----------------
__device__ __forceinline__ void cvt_hilo(float v, unsigned& hi, unsigned& lo) {
    __nv_bfloat16 h = __float2bfloat16(v);
    float r = v - __bfloat162float(h);
    __nv_bfloat16 l = __float2bfloat16(r);
    hi = (unsigned)__bfloat16_as_ushort(h);
    lo = (unsigned)__bfloat16_as_ushort(l);
}

__device__ __forceinline__ void mma16816(float* c, const unsigned* a, const unsigned* b) {
    asm volatile("mma.sync.aligned.m16n8k16.row.col.f32.bf16.bf16.f32 "
                 "{%0,%1,%2,%3}, {%4,%5,%6,%7}, {%8,%9}, {%0,%1,%2,%3};"
                 : "+f"(c[0]), "+f"(c[1]), "+f"(c[2]), "+f"(c[3])
                 : "r"(a[0]), "r"(a[1]), "r"(a[2]), "r"(a[3]),
                   "r"(b[0]), "r"(b[1]));
}

__device__ __forceinline__ float lrelu1(float x) { return x >= 0.f ? x : 0.01f * x; }

// ---------------- CSR construction ----------------
__global__ void hist_kernel(const int* __restrict__ idx, int* __restrict__ deg, int n)
{
    int i = blockIdx.x * blockDim.x + threadIdx.x;
    if (i < n) atomicAdd(&deg[idx[i]], 1);
}

__global__ void scan_chunk(const int* __restrict__ deg, int* __restrict__ offs,
                           int* __restrict__ btot)
{
    __shared__ int ts[256];
    int t = threadIdx.x;
    int base = blockIdx.x * 1024 + t * 4;
    int a0 = deg[base], a1 = deg[base+1], a2 = deg[base+2], a3 = deg[base+3];
    int s = a0 + a1 + a2 + a3;
    ts[t] = s; __syncthreads();
    for (int off = 1; off < 256; off <<= 1) {
        int v = (t >= off) ? ts[t - off] : 0;
        __syncthreads();
        ts[t] += v;
        __syncthreads();
    }
    int excl = ts[t] - s;
    offs[base]   = excl;
    offs[base+1] = excl + a0;
    offs[base+2] = excl + a0 + a1;
    offs[base+3] = excl + a0 + a1 + a2;
    if (t == 255) btot[blockIdx.x] = ts[255];
}

__global__ void scan_btot(int* __restrict__ btot)
{
    __shared__ int ts[256];
    int t = threadIdx.x;
    int v = btot[t];
    ts[t] = v; __syncthreads();
    for (int off = 1; off < 256; off <<= 1) {
        int u = (t >= off) ? ts[t - off] : 0;
        __syncthreads();
        ts[t] += u;
        __syncthreads();
    }
    btot[t] = ts[t] - v;
}

__global__ void scan_add(int* __restrict__ offs, const int* __restrict__ btot,
                         int* __restrict__ cursor, int n, int total)
{
    int i = blockIdx.x * blockDim.x + threadIdx.x;
    if (i < n) {
        int v = offs[i] + btot[i >> 10];
        offs[i] = v;
        cursor[i] = v;
    }
    if (i == 0) offs[n] = total;
}

__global__ void scan4k(const int* __restrict__ deg, int* __restrict__ offs,
                       int* __restrict__ cursor, int total)
{
    __shared__ int ts[1024];
    int t = threadIdx.x;
    int base = t * 4;
    int a0 = deg[base], a1 = deg[base+1], a2 = deg[base+2], a3 = deg[base+3];
    int s = a0 + a1 + a2 + a3;
    ts[t] = s; __syncthreads();
    for (int off = 1; off < 1024; off <<= 1) {
        int v = (t >= off) ? ts[t - off] : 0;
        __syncthreads();
        ts[t] += v;
        __syncthreads();
    }
    int excl = ts[t] - s;
    int o0 = excl, o1 = excl + a0, o2 = excl + a0 + a1, o3 = excl + a0 + a1 + a2;
    offs[base] = o0;   cursor[base] = o0;
    offs[base+1] = o1; cursor[base+1] = o1;
    offs[base+2] = o2; cursor[base+2] = o2;
    offs[base+3] = o3; cursor[base+3] = o3;
    if (t == 1023) offs[4096] = total;
}

__global__ void scatter_px(const int* __restrict__ src, const int* __restrict__ dst,
                           int* __restrict__ cursor, int* __restrict__ csr, int n)
{
    int e = blockIdx.x * blockDim.x + threadIdx.x;
    if (e < n) {
        int p = atomicAdd(&cursor[src[e]], 1);
        csr[p] = dst[e];
    }
}

__global__ void scatter_a(const int* __restrict__ asrc, const int* __restrict__ adst,
                          const float* __restrict__ aw, int* __restrict__ cursor,
                          int* __restrict__ csrs, float* __restrict__ csrw, int n)
{
    int e = blockIdx.x * blockDim.x + threadIdx.x;
    if (e < n) {
        int p = atomicAdd(&cursor[adst[e]], 1);
        csrs[p] = asrc[e];
        csrw[p] = aw[e];
    }
}

__global__ void scatter_seg(const int* __restrict__ seg, int* __restrict__ cursor,
                            int* __restrict__ csr, int n)
{
    int i = blockIdx.x * blockDim.x + threadIdx.x;
    if (i < n) {
        int p = atomicAdd(&cursor[seg[i]], 1);
        csr[p] = i;
    }
}

// ---------------- weight packing: [2][2][128][64] -> [2][128][128] ----------------
__global__ void pack_weights(const float* __restrict__ Wv, const float* __restrict__ bv,
                             const float* __restrict__ Wq, const float* __restrict__ bq,
                             float* __restrict__ wvp, float* __restrict__ bvp,
                             float* __restrict__ wqp, float* __restrict__ bqp)
{
    int idx = blockIdx.x * blockDim.x + threadIdx.x;
    if (idx >= 2 * HD * HD) return;
    int l = idx >> 14;
    int rem = idx & 16383;
    int k = rem >> 7;
    int c = rem & 127;
    int h = c >> 6;
    int j = c & 63;
    int sidx = ((l * 2 + h) * HD + k) * 64 + j;
    wvp[idx] = Wv[sidx];
    wqp[idx] = Wq[sidx];
    if (k == 0) {
        bvp[(l << 7) | c] = bv[(l * 2 + h) * 64 + j];
        bqp[(l << 7) | c] = bq[(l * 2 + h) * 64 + j];
    }
}

// ---------------- Tensor-core GEMM: C[M,128] = BNaff(A)[M,K] @ B[K,128] + bias ----
// aA/aB: optional per-column fused BN affine on the A operand (y = x*aA + aB),
// lrelu applied after affine when flagged.
__global__ __launch_bounds__(256) void gemm_tc(
    const float* __restrict__ A, const float* __restrict__ B,
    const float* __restrict__ bias, float* __restrict__ C, int M, int K,
    const float* __restrict__ aA, const float* __restrict__ aB, int lrelu)
{
    __shared__ unsigned As_h[128 * 8];
    __shared__ unsigned As_l[128 * 8];
    __shared__ unsigned Bs_h[8 * 132];
    __shared__ unsigned Bs_l[8 * 132];

    const int tid  = threadIdx.x;
    const int lane = tid & 31;
    const int warp = tid >> 5;
    const int wm   = warp >> 2;
    const int wn   = warp & 3;
    const int m0   = blockIdx.x * 128;

    float acc[4][4][4];
#pragma unroll
    for (int mt = 0; mt < 4; mt++)
#pragma unroll
        for (int nt = 0; nt < 4; nt++)
#pragma unroll
            for (int i = 0; i < 4; i++) acc[mt][nt][i] = 0.f;

    const int lr = lane >> 2;
    const int jj = lane & 3;

    for (int k0 = 0; k0 < K; k0 += 16) {
        {
            int r  = tid & 127;
            int qb = (tid >> 7) << 1;
            const float* ap = A + (size_t)(m0 + r) * K;
#pragma unroll
            for (int qq = 0; qq < 2; qq++) {
                int q  = qb + qq;
                int kk = k0 + q * 4;
                float v0 = 0.f, v1 = 0.f, v2 = 0.f, v3 = 0.f;
                if (kk + 3 < K) {
                    float4 t = *(const float4*)(ap + kk);
                    v0 = t.x; v1 = t.y; v2 = t.z; v3 = t.w;
                } else {
                    if (kk + 0 < K) v0 = ap[kk + 0];
                    if (kk + 1 < K) v1 = ap[kk + 1];
                    if (kk + 2 < K) v2 = ap[kk + 2];
                    if (kk + 3 < K) v3 = ap[kk + 3];
                }
                if (aA) {
                    float4 a4 = *(const float4*)(aA + kk);
                    float4 b4 = *(const float4*)(aB + kk);
                    v0 = fmaf(v0, a4.x, b4.x);
                    v1 = fmaf(v1, a4.y, b4.y);
                    v2 = fmaf(v2, a4.z, b4.z);
                    v3 = fmaf(v3, a4.w, b4.w);
                    if (lrelu) {
                        v0 = lrelu1(v0); v1 = lrelu1(v1);
                        v2 = lrelu1(v2); v3 = lrelu1(v3);
                    }
                }
                unsigned h0, l0, h1, l1, h2, l2, h3, l3;
                cvt_hilo(v0, h0, l0); cvt_hilo(v1, h1, l1);
                cvt_hilo(v2, h2, l2); cvt_hilo(v3, h3, l3);
                As_h[r * 8 + q * 2 + 0] = h0 | (h1 << 16);
                As_h[r * 8 + q * 2 + 1] = h2 | (h3 << 16);
                As_l[r * 8 + q * 2 + 0] = l0 | (l1 << 16);
                As_l[r * 8 + q * 2 + 1] = l2 | (l3 << 16);
            }
        }
        {
            int kp  = tid >> 5;
            int np0 = tid & 31;
#pragma unroll
            for (int hh = 0; hh < 2; hh++) {
                int np = np0 + hh * 32;
                int n  = np * 2;
                int ka = k0 + kp * 2;
                float a = 0.f, b = 0.f, c = 0.f, d = 0.f;
                if (ka < K)     { float2 t = *(const float2*)(B + (size_t)ka * 128 + n);       a = t.x; b = t.y; }
                if (ka + 1 < K) { float2 t = *(const float2*)(B + (size_t)(ka + 1) * 128 + n); c = t.x; d = t.y; }
                unsigned ha, la, hb_, lb, hc, lc, hd, ld;
                cvt_hilo(a, ha, la); cvt_hilo(b, hb_, lb);
                cvt_hilo(c, hc, lc); cvt_hilo(d, hd, ld);
                Bs_h[kp * 132 + n + 0] = ha  | (hc << 16);
                Bs_h[kp * 132 + n + 1] = hb_ | (hd << 16);
                Bs_l[kp * 132 + n + 0] = la  | (lc << 16);
                Bs_l[kp * 132 + n + 1] = lb  | (ld << 16);
            }
        }
        __syncthreads();

        unsigned ah[4][4];
#pragma unroll
        for (int mt = 0; mt < 4; mt++) {
            int r = wm * 64 + mt * 16 + lr;
            ah[mt][0] = As_h[r * 8 + jj];
            ah[mt][1] = As_h[(r + 8) * 8 + jj];
            ah[mt][2] = As_h[r * 8 + jj + 4];
            ah[mt][3] = As_h[(r + 8) * 8 + jj + 4];
        }
        unsigned bh[4][2];
#pragma unroll
        for (int nt = 0; nt < 4; nt++) {
            int n = wn * 32 + nt * 8 + lr;
            bh[nt][0] = Bs_h[jj * 132 + n];
            bh[nt][1] = Bs_h[(jj + 4) * 132 + n];
        }
#pragma unroll
        for (int mt = 0; mt < 4; mt++)
#pragma unroll
            for (int nt = 0; nt < 4; nt++)
                mma16816(acc[mt][nt], ah[mt], bh[nt]);
        {
            unsigned bl[4][2];
#pragma unroll
            for (int nt = 0; nt < 4; nt++) {
                int n = wn * 32 + nt * 8 + lr;
                bl[nt][0] = Bs_l[jj * 132 + n];
                bl[nt][1] = Bs_l[(jj + 4) * 132 + n];
            }
#pragma unroll
            for (int mt = 0; mt < 4; mt++)
#pragma unroll
                for (int nt = 0; nt < 4; nt++)
                    mma16816(acc[mt][nt], ah[mt], bl[nt]);
        }
#pragma unroll
        for (int mt = 0; mt < 4; mt++) {
            int r = wm * 64 + mt * 16 + lr;
            ah[mt][0] = As_l[r * 8 + jj];
            ah[mt][1] = As_l[(r + 8) * 8 + jj];
            ah[mt][2] = As_l[r * 8 + jj + 4];
            ah[mt][3] = As_l[(r + 8) * 8 + jj + 4];
        }
#pragma unroll
        for (int mt = 0; mt < 4; mt++)
#pragma unroll
            for (int nt = 0; nt < 4; nt++)
                mma16816(acc[mt][nt], ah[mt], bh[nt]);
        __syncthreads();
    }

    const int lc2 = (lane & 3) * 2;
#pragma unroll
    for (int nt = 0; nt < 4; nt++) {
        int col = wn * 32 + nt * 8 + lc2;
        float b0 = bias[col], b1 = bias[col + 1];
#pragma unroll
        for (int mt = 0; mt < 4; mt++) {
            int r0 = m0 + wm * 64 + mt * 16 + lr;
            float2 o0 = make_float2(acc[mt][nt][0] + b0, acc[mt][nt][1] + b1);
            float2 o1 = make_float2(acc[mt][nt][2] + b0, acc[mt][nt][3] + b1);
            *(float2*)(C + (size_t)r0 * 128 + col)       = o0;
            *(float2*)(C + (size_t)(r0 + 8) * 128 + col) = o1;
        }
    }
}

// ---------------- BatchNorm stats on raw tensor -> fused affine (A,B) ----------
__global__ void colstats(const float* __restrict__ X, int nrows,
                         double* __restrict__ stats)
{
    int c    = threadIdx.x & 127;
    int half = threadIdx.x >> 7;
    float s = 0.f, s2 = 0.f;
    for (int r = blockIdx.x * 2 + half; r < nrows; r += gridDim.x * 2) {
        float v = X[(size_t)r * 128 + c];
        s += v;
        s2 = fmaf(v, v, s2);
    }
    __shared__ float sh[2][128], sh2[2][128];
    sh[half][c] = s; sh2[half][c] = s2;
    __syncthreads();
    if (half == 0) {
        atomicAdd(&stats[c],       (double)(s  + sh[1][c]));
        atomicAdd(&stats[128 + c], (double)(s2 + sh2[1][c]));
    }
}

__global__ void finalize_aff(const double* __restrict__ stats,
                             const float* __restrict__ g, const float* __restrict__ b,
                             float* __restrict__ affA, float* __restrict__ affB,
                             double inv_n)
{
    int c = threadIdx.x;
    double m   = stats[c] * inv_n;
    double var = stats[128 + c] * inv_n - m * m;
    float A = (float)(1.0 / sqrt(var + 1e-5)) * g[c];
    affA[c] = A;
    affB[c] = b[c] - (float)m * A;
}

// ---------------- BatchNorm (small, fused: stats + apply + lrelu) ----------------
__global__ void bn_small(const float* __restrict__ X, float* __restrict__ Y,
                         const float* __restrict__ g, const float* __restrict__ b,
                         int nrows)
{
    int bcol = blockIdx.x;
    int t = threadIdx.x;
    float4 s  = make_float4(0.f, 0.f, 0.f, 0.f);
    float4 s2 = make_float4(0.f, 0.f, 0.f, 0.f);
    for (int r = t; r < nrows; r += 128) {
        float4 v = ((const float4*)X)[(size_t)r * 32 + bcol];
        s.x += v.x; s.y += v.y; s.z += v.z; s.w += v.w;
        s2.x = fmaf(v.x, v.x, s2.x); s2.y = fmaf(v.y, v.y, s2.y);
        s2.z = fmaf(v.z, v.z, s2.z); s2.w = fmaf(v.w, v.w, s2.w);
    }
    __shared__ float4 sh[128], sh2[128];
    sh[t] = s; sh2[t] = s2;
    __syncthreads();
    for (int off = 64; off >= 1; off >>= 1) {
        if (t < off) {
            sh[t].x += sh[t+off].x; sh[t].y += sh[t+off].y;
            sh[t].z += sh[t+off].z; sh[t].w += sh[t+off].w;
            sh2[t].x += sh2[t+off].x; sh2[t].y += sh2[t+off].y;
            sh2[t].z += sh2[t+off].z; sh2[t].w += sh2[t+off].w;
        }
        __syncthreads();
    }
    __shared__ float4 mean4, scl4;
    if (t == 0) {
        float inv = 1.f / (float)nrows;
        float4 m = make_float4(sh[0].x*inv, sh[0].y*inv, sh[0].z*inv, sh[0].w*inv);
        mean4 = m;
        scl4.x = rsqrtf(sh2[0].x*inv - m.x*m.x + 1e-5f);
        scl4.y = rsqrtf(sh2[0].y*inv - m.y*m.y + 1e-5f);
        scl4.z = rsqrtf(sh2[0].z*inv - m.z*m.z + 1e-5f);
        scl4.w = rsqrtf(sh2[0].w*inv - m.w*m.w + 1e-5f);
    }
    __syncthreads();
    float4 g4 = ((const float4*)g)[bcol];
    float4 b4 = ((const float4*)b)[bcol];
    float4 m4 = mean4, c4 = scl4;
    for (int r = t; r < nrows; r += 128) {
        float4 v = ((const float4*)X)[(size_t)r * 32 + bcol];
        float4 o;
        o.x = lrelu1((v.x - m4.x) * c4.x * g4.x + b4.x);
        o.y = lrelu1((v.y - m4.y) * c4.y * g4.y + b4.y);
        o.z = lrelu1((v.z - m4.z) * c4.z * g4.z + b4.z);
        o.w = lrelu1((v.w - m4.w) * c4.w * g4.w + b4.w);
        ((float4*)Y)[(size_t)r * 32 + bcol] = o;
    }
}

// ---------------- per-head LayerNorm over 64-wide halves -> bf16 out ------------
__global__ void ln_halves(const float* __restrict__ q, unsigned short* __restrict__ qh,
                          int nrows)
{
    int warp = (blockIdx.x * blockDim.x + threadIdx.x) >> 5;
    int lane = threadIdx.x & 31;
    if (warp >= nrows) return;
    const float4* qp = (const float4*)q + (size_t)warp * 32;
    float4 v = qp[lane];
    float s  = v.x + v.y + v.z + v.w;
    float s2 = v.x * v.x + v.y * v.y + v.z * v.z + v.w * v.w;
#pragma unroll
    for (int off = 1; off < 16; off <<= 1) {
        s  += __shfl_xor_sync(0xffffffffu, s,  off);
        s2 += __shfl_xor_sync(0xffffffffu, s2, off);
    }
    float m   = s * (1.f / 64.f);
    float var = s2 * (1.f / 64.f) - m * m;
    float r   = rsqrtf(var + 1e-5f);
    __nv_bfloat162 p0 = __float22bfloat162_rn(make_float2((v.x - m) * r, (v.y - m) * r));
    __nv_bfloat162 p1 = __float22bfloat162_rn(make_float2((v.z - m) * r, (v.w - m) * r));
    uint2 o;
    o.x = *(unsigned*)&p0;
    o.y = *(unsigned*)&p1;
    ((uint2*)qh)[(size_t)warp * 32 + lane] = o;
}

// ---------------- fused per-node attention (online softmax, warp per node) -----
__global__ __launch_bounds__(256) void pf_attn(
    const unsigned short* __restrict__ qh, const float* __restrict__ v,
    const int* __restrict__ offs, const int* __restrict__ csr,
    float* __restrict__ out)
{
    int n    = (blockIdx.x * 256 + threadIdx.x) >> 5;
    int lane = threadIdx.x & 31;
    int e0 = offs[n], e1 = offs[n + 1];
    uint2 qn2 = ((const uint2*)qh)[(size_t)n * 32 + lane];
    float2 qn0 = __bfloat1622float2(*(__nv_bfloat162*)&qn2.x);
    float2 qn1 = __bfloat1622float2(*(__nv_bfloat162*)&qn2.y);
    float m = __int_as_float(0xff800000);   // -inf
    float z = 0.f;
    float4 acc = make_float4(0.f, 0.f, 0.f, 0.f);
    int d = (e0 < e1) ? csr[e0] : 0;
    for (int e = e0; e < e1; e++) {
        int dn = (e + 1 < e1) ? csr[e + 1] : d;
        uint2 qd2 = ((const uint2*)qh)[(size_t)d * 32 + lane];
        float4 vd = ((const float4*)v)[(size_t)d * 32 + lane];
        float2 qd0 = __bfloat1622float2(*(__nv_bfloat162*)&qd2.x);
        float2 qd1 = __bfloat1622float2(*(__nv_bfloat162*)&qd2.y);
        float p = qn0.x * qd0.x + qn0.y * qd0.y + qn1.x * qd1.x + qn1.y * qd1.y;
        p += __shfl_xor_sync(0xffffffffu, p, 1);
        p += __shfl_xor_sync(0xffffffffu, p, 2);
        p += __shfl_xor_sync(0xffffffffu, p, 4);
        p += __shfl_xor_sync(0xffffffffu, p, 8);
        float s = p * (1.0f / 128.0f);      // per 16-lane half (head)
        float mn = fmaxf(m, s);
        float sc = __expf(m - mn);
        float ee = __expf(s - mn);
        z = z * sc + ee;
        acc.x = acc.x * sc + ee * vd.x;
        acc.y = acc.y * sc + ee * vd.y;
        acc.z = acc.z * sc + ee * vd.z;
        acc.w = acc.w * sc + ee * vd.w;
        m = mn;
        d = dn;
    }
    float iz = (z > 0.f) ? __fdividef(1.f, z) : 0.f;
    ((float4*)out)[(size_t)n * 32 + lane] =
        make_float4(acc.x * iz, acc.y * iz, acc.z * iz, acc.w * iz);
}

// ---------------- fused superpixel pooling (affine on x0 applied on load) -------
__global__ __launch_bounds__(256) void pool_f(
    const float* __restrict__ x0, const int* __restrict__ offs,
    const int* __restrict__ pix, const float* __restrict__ affA,
    const float* __restrict__ affB, float* __restrict__ hp)
{
    int s    = (blockIdx.x * 256 + threadIdx.x) >> 5;
    int lane = threadIdx.x & 31;
    int e0 = offs[s], e1 = offs[s + 1];
    float4 a4 = ((const float4*)affA)[lane];
    float4 b4 = ((const float4*)affB)[lane];
    float4 acc = make_float4(0.f, 0.f, 0.f, 0.f);
    for (int e = e0; e < e1; e++) {
        int p = pix[e];
        float4 xv = ((const float4*)x0)[(size_t)p * 32 + lane];
        acc.x += fmaf(xv.x, a4.x, b4.x);
        acc.y += fmaf(xv.y, a4.y, b4.y);
        acc.z += fmaf(xv.z, a4.z, b4.z);
        acc.w += fmaf(xv.w, a4.w, b4.w);
    }
    float ic = 1.f / fmaxf((float)(e1 - e0), 1.f);
    ((float4*)hp)[(size_t)s * 32 + lane] =
        make_float4(acc.x * ic, acc.y * ic, acc.z * ic, acc.w * ic);
}

// ---------------- fused superpixel propagate (warp per dst node) ----------------
__global__ __launch_bounds__(256) void sf_prop_f(
    const float* __restrict__ h, const int* __restrict__ offs,
    const int* __restrict__ csrs, const float* __restrict__ csrw,
    const float* __restrict__ xs, float* __restrict__ out, int mode)
{
    int n    = (blockIdx.x * 256 + threadIdx.x) >> 5;
    int lane = threadIdx.x & 31;
    int e0 = offs[n], e1 = offs[n + 1];
    float4 acc = make_float4(0.f, 0.f, 0.f, 0.f);
    for (int e = e0; e < e1; e++) {
        int s = csrs[e];
        float w = csrw[e];
        float4 hv = ((const float4*)h)[(size_t)s * 32 + lane];
        acc.x = fmaf(w, hv.x, acc.x);
        acc.y = fmaf(w, hv.y, acc.y);
        acc.z = fmaf(w, hv.z, acc.z);
        acc.w = fmaf(w, hv.w, acc.w);
    }
    if (mode == 0) {
        ((float4*)out)[(size_t)n * 32 + lane] = acc;
    } else {
        float4 x = ((const float4*)xs)[(size_t)n * 32 + lane];
        const float inv = 1.0f / 2.9f;
        ((float4*)out)[(size_t)n * 32 + lane] =
            make_float4((acc.x + x.x) * inv, (acc.y + x.y) * inv,
                        (acc.z + x.z) * inv, (acc.w + x.w) * inv);
    }
}

// ---------------- final: H1 = BNaff(pfb) + hp[seg]; softmax(H1 @ W + b) ---------
__global__ __launch_bounds__(256) void final_out(
    const float* __restrict__ pf, const float* __restrict__ hp,
    const int* __restrict__ seg, const float* __restrict__ Wout,
    const float* __restrict__ bout, const float* __restrict__ affA,
    const float* __restrict__ affB, float* __restrict__ out, int nrows)
{
    __shared__ float sWt[16 * 128];
    __shared__ float sb[16];
    for (int i = threadIdx.x; i < 2048; i += 256) {
        int k = i >> 4, c = i & 15;
        sWt[c * 128 + k] = Wout[i];
    }
    if (threadIdx.x < 16) sb[threadIdx.x] = bout[threadIdx.x];
    __syncthreads();

    int warp = (blockIdx.x * 256 + threadIdx.x) >> 5;
    int lane = threadIdx.x & 31;
    if (warp >= nrows) return;
    int s = seg[warp];
    float4 aA = ((const float4*)affA)[lane];
    float4 aB = ((const float4*)affB)[lane];
    float4 a = ((const float4*)pf)[(size_t)warp * 32 + lane];
    float4 b = ((const float4*)hp)[(size_t)s * 32 + lane];
    float4 h;
    h.x = lrelu1(fmaf(a.x, aA.x, aB.x)) + b.x;
    h.y = lrelu1(fmaf(a.y, aA.y, aB.y)) + b.y;
    h.z = lrelu1(fmaf(a.z, aA.z, aB.z)) + b.z;
    h.w = lrelu1(fmaf(a.w, aA.w, aB.w)) + b.w;

    float lg[16];
#pragma unroll
    for (int c = 0; c < 16; c++) {
        float4 w = ((const float4*)sWt)[c * 32 + lane];
        lg[c] = h.x * w.x + h.y * w.y + h.z * w.z + h.w * w.w;
    }
#pragma unroll
    for (int off = 16; off >= 1; off >>= 1)
#pragma unroll
        for (int c = 0; c < 16; c++)
            lg[c] += __shfl_xor_sync(0xffffffffu, lg[c], off);

    if (lane < 16) {
        float mx = -1e30f;
#pragma unroll
        for (int c = 0; c < 16; c++) { lg[c] += sb[c]; mx = fmaxf(mx, lg[c]); }
        float sum = 0.f;
#pragma unroll
        for (int c = 0; c < 16; c++) { lg[c] = __expf(lg[c] - mx); sum += lg[c]; }
        float inv = __fdividef(1.0f, sum);
        float r = 0.f;
#pragma unroll
        for (int c = 0; c < 16; c++) if (lane == c) r = lg[c];
        out[(size_t)warp * 16 + lane] = r * inv;
    }
}

// ---------------- host ----------------
#define GSYM(p, sym) cudaGetSymbolAddress((void**)&p, sym)

static void run_stats(const float* X, int nrows, const float* g, const float* b,
                      double* stats, float* affA, float* affB)
{
    cudaMemsetAsync(stats, 0, 256 * sizeof(double));
    colstats<<<512, 256>>>(X, nrows, stats);
    finalize_aff<<<1, 128>>>(stats, g, b, affA, affB, 1.0 / (double)nrows);
}

extern "C" void kernel_launch(void* const* d_in, const int* in_sizes, int n_in,
                              void* d_out, int out_size)
{
    const float* x       = (const float*)d_in[0];
    const int*   seg     = (const int*)  d_in[1];
    const int*   a_src   = (const int*)  d_in[2];
    const int*   a_dst   = (const int*)  d_in[3];
    const float* a_w     = (const float*)d_in[4];
    const int*   m_src   = (const int*)  d_in[5];
    const int*   m_dst   = (const int*)  d_in[6];
    const float* pre_W   = (const float*)d_in[7];
    const float* pre_b   = (const float*)d_in[8];
    const float* bn0_g   = (const float*)d_in[9];
    const float* bn0_b   = (const float*)d_in[10];
    const float* sf_W    = (const float*)d_in[11];
    const float* sf_b    = (const float*)d_in[12];
    const float* sf_g    = (const float*)d_in[13];
    const float* sf_beta = (const float*)d_in[14];
    const float* pf_Wv   = (const float*)d_in[15];
    const float* pf_bv   = (const float*)d_in[16];
    const float* pf_Wq   = (const float*)d_in[17];
    const float* pf_bq   = (const float*)d_in[18];
    const float* pf_g    = (const float*)d_in[19];
    const float* pf_beta = (const float*)d_in[20];
    const float* out_W   = (const float*)d_in[21];
    const float* out_b   = (const float*)d_in[22];
    float* out = (float*)d_out;

    float *x0, *pfa, *pfb, *v, *q;
    unsigned short *qh;
    float *affA, *affB, *hp, *hb, *xs, *ba, *bb, *wv, *wq, *bv, *bq;
    double *stats;
    int *deg, *cursor, *offs, *btot, *csr;
    int *adeg, *acur, *aoffs, *acsrs;
    float *acsrw;
    int *sdeg, *scur, *soffs, *spix;
    GSYM(x0, d_x0);   GSYM(pfa, d_pfa); GSYM(pfb, d_pfb);
    GSYM(v, d_v);     GSYM(q, d_q);     GSYM(qh, d_qh);
    GSYM(stats, d_stats); GSYM(affA, d_affA); GSYM(affB, d_affB);
    GSYM(hp, d_hp); GSYM(hb, d_hb); GSYM(xs, d_xs);
    GSYM(ba, d_ba); GSYM(bb, d_bb);
    GSYM(wv, d_wv); GSYM(wq, d_wq); GSYM(bv, d_bv); GSYM(bq, d_bq);
    GSYM(deg, d_deg); GSYM(cursor, d_cursor); GSYM(offs, d_offs);
    GSYM(btot, d_btot); GSYM(csr, d_csr);
    GSYM(adeg, d_adeg); GSYM(acur, d_acur); GSYM(aoffs, d_aoffs);
    GSYM(acsrs, d_acsrs); GSYM(acsrw, d_acsrw);
    GSYM(sdeg, d_sdeg); GSYM(scur, d_scur); GSYM(soffs, d_soffs);
    GSYM(spix, d_spix);

    // ---- build CSRs (pixel graph by src; a-graph by dst; seg lists) ----
    cudaMemsetAsync(deg, 0, NPIX * sizeof(int));
    hist_kernel<<<EME / 256, 256>>>(m_src, deg, EME);
    scan_chunk<<<256, 256>>>(deg, offs, btot);
    scan_btot<<<1, 256>>>(btot);
    scan_add<<<NPIX / 256, 256>>>(offs, btot, cursor, NPIX, EME);
    scatter_px<<<EME / 256, 256>>>(m_src, m_dst, cursor, csr, EME);

    cudaMemsetAsync(adeg, 0, SP * sizeof(int));
    hist_kernel<<<EAE / 256, 256>>>(a_dst, adeg, EAE);
    scan4k<<<1, 1024>>>(adeg, aoffs, acur, EAE);
    scatter_a<<<EAE / 256, 256>>>(a_src, a_dst, a_w, acur, acsrs, acsrw, EAE);

    cudaMemsetAsync(sdeg, 0, SP * sizeof(int));
    hist_kernel<<<NPIX / 256, 256>>>(seg, sdeg, NPIX);
    scan4k<<<1, 1024>>>(sdeg, soffs, scur, NPIX);
    scatter_seg<<<NPIX / 256, 256>>>(seg, scur, spix, NPIX);

    // pack per-head attention weights into [128,128]
    pack_weights<<<(2 * HD * HD + 255) / 256, 256>>>(pf_Wv, pf_bv, pf_Wq, pf_bq,
                                                     wv, bv, wq, bq);

    // ---- pre: x0raw = x @ pre_W + pre_b; BN folded into consumers (slot 0) ----
    gemm_tc<<<NPIX / 128, 256>>>(x, pre_W, pre_b, x0, NPIX, CIN,
                                 (const float*)0, (const float*)0, 0);
    run_stats(x0, NPIX, bn0_g, bn0_b, stats, affA, affB);

    // ---- PF branch: 2 attention layers on the pixel graph ----
    const float* pin = x0;
    for (int l = 0; l < 2; l++) {
        float* pout = (l == 0) ? pfa : pfb;
        const float* aA = affA + l * HD;
        const float* aB = affB + l * HD;
        int lr = (l > 0);
        gemm_tc<<<NPIX / 128, 256>>>(pin, wv + l * HD * HD, bv + l * HD, v,
                                     NPIX, HD, aA, aB, lr);
        gemm_tc<<<NPIX / 128, 256>>>(pin, wq + l * HD * HD, bq + l * HD, q,
                                     NPIX, HD, aA, aB, lr);
        ln_halves<<<NPIX / 8, 256>>>(q, qh, NPIX);
        pf_attn<<<NPIX / 8, 256>>>(qh, v, offs, csr, pout);
        run_stats(pout, NPIX, pf_g + l * HD, pf_beta + l * HD, stats,
                  affA + (l + 1) * HD, affB + (l + 1) * HD);
        pin = pout;
    }

    // ---- SF branch: pool (bn0 affine fused) -> 5 SFNet layers ----
    pool_f<<<SP / 8, 256>>>(x0, soffs, spix, affA, affB, hp);

    for (int l = 0; l < 5; l++) {
        gemm_tc<<<SP / 128, 256>>>(hp, sf_W + l * HD * HD, sf_b + l * HD, hb,
                                   SP, HD, (const float*)0, (const float*)0, 0);
        sf_prop_f<<<SP / 8, 256>>>(hb, aoffs, acsrs, acsrw, xs, xs, 0);
        const float* cur = hp;
        for (int it = 0; it < 5; it++) {
            float* nxt = (it & 1) ? bb : ba;
            sf_prop_f<<<SP / 8, 256>>>(cur, aoffs, acsrs, acsrw, xs, nxt, 1);
            cur = nxt;
        }
        bn_small<<<32, 128>>>(cur, hp, sf_g + l * HD, sf_beta + l * HD, SP);
    }

    // ---- final: softmax((BNaff(pfb) + hp[seg]) @ out_W + out_b) ----
    final_out<<<NPIX / 8, 256>>>(pfb, hp, seg, out_W, out_b,
                                 affA + 2 * HD, affB + 2 * HD, out, NPIX);
}

// round 10
// speedup vs baseline: 2.0024x; 1.0024x over previous
#include <cuda_runtime.h>
#include <cuda_bf16.h>

#define NPIX 262144
#define CIN  200
#define HD   128
#define SP   4096
#define EAE  65536
#define EME  2097152
#define NCLS 16

// ---------------- scratch (device globals; allocation-free rule) ----------------
__device__ float  d_x0 [NPIX*HD];
__device__ float  d_pfa[NPIX*HD];
__device__ float  d_pfb[NPIX*HD];
__device__ unsigned short d_qh[NPIX*HD];   // bf16 q (layer-normed)
__device__ unsigned short d_vh[NPIX*HD];   // bf16 v
__device__ double d_stats[256];            // sums[128] | sumsq[128]
__device__ float  d_affA[3*HD];            // per-BN fused scale
__device__ float  d_affB[3*HD];            // per-BN fused shift
__device__ float  d_hp [SP*HD];
__device__ float  d_hb [SP*HD];
__device__ float  d_xs [SP*HD];
__device__ float  d_ba [SP*HD];
__device__ float  d_bb [SP*HD];
__device__ float  d_wv [2*HD*HD];
__device__ float  d_wq [2*HD*HD];
__device__ float  d_bv [2*HD];
__device__ float  d_bq [2*HD];
// CSR scratch: pixel graph (by src)
__device__ int    d_deg   [NPIX];
__device__ int    d_cursor[NPIX];
__device__ int    d_offs  [NPIX+1];
__device__ int    d_btot  [256];
__device__ int    d_csr   [EME];
// superpixel graph (by dst)
__device__ int    d_adeg [SP];
__device__ int    d_acur [SP];
__device__ int    d_aoffs[SP+1];
__device__ int    d_acsrs[EAE];
__device__ float  d_acsrw[EAE];
// seg -> pixel lists
__device__ int    d_sdeg [SP];
__device__ int    d_scur [SP];
__device__ int    d_soffs[SP+1];
__device__ int    d_spix [NPIX];

// ---------------- helpers ----------------
__device__ __forceinline__ void cvt_hilo(float v, unsigned& hi, unsigned& lo) {
    __nv_bfloat16 h = __float2bfloat16(v);
    float r = v - __bfloat162float(h);
    __nv_bfloat16 l = __float2bfloat16(r);
    hi = (unsigned)__bfloat16_as_ushort(h);
    lo = (unsigned)__bfloat16_as_ushort(l);
}

__device__ __forceinline__ void mma16816(float* c, const unsigned* a, const unsigned* b) {
    asm volatile("mma.sync.aligned.m16n8k16.row.col.f32.bf16.bf16.f32 "
                 "{%0,%1,%2,%3}, {%4,%5,%6,%7}, {%8,%9}, {%0,%1,%2,%3};"
                 : "+f"(c[0]), "+f"(c[1]), "+f"(c[2]), "+f"(c[3])
                 : "r"(a[0]), "r"(a[1]), "r"(a[2]), "r"(a[3]),
                   "r"(b[0]), "r"(b[1]));
}

__device__ __forceinline__ float lrelu1(float x) { return x >= 0.f ? x : 0.01f * x; }

// ---------------- CSR construction ----------------
__global__ void hist_kernel(const int* __restrict__ idx, int* __restrict__ deg, int n)
{
    int i = blockIdx.x * blockDim.x + threadIdx.x;
    if (i < n) atomicAdd(&deg[idx[i]], 1);
}

__global__ void scan_chunk(const int* __restrict__ deg, int* __restrict__ offs,
                           int* __restrict__ btot)
{
    __shared__ int ts[256];
    int t = threadIdx.x;
    int base = blockIdx.x * 1024 + t * 4;
    int a0 = deg[base], a1 = deg[base+1], a2 = deg[base+2], a3 = deg[base+3];
    int s = a0 + a1 + a2 + a3;
    ts[t] = s; __syncthreads();
    for (int off = 1; off < 256; off <<= 1) {
        int v = (t >= off) ? ts[t - off] : 0;
        __syncthreads();
        ts[t] += v;
        __syncthreads();
    }
    int excl = ts[t] - s;
    offs[base]   = excl;
    offs[base+1] = excl + a0;
    offs[base+2] = excl + a0 + a1;
    offs[base+3] = excl + a0 + a1 + a2;
    if (t == 255) btot[blockIdx.x] = ts[255];
}

__global__ void scan_btot(int* __restrict__ btot)
{
    __shared__ int ts[256];
    int t = threadIdx.x;
    int v = btot[t];
    ts[t] = v; __syncthreads();
    for (int off = 1; off < 256; off <<= 1) {
        int u = (t >= off) ? ts[t - off] : 0;
        __syncthreads();
        ts[t] += u;
        __syncthreads();
    }
    btot[t] = ts[t] - v;
}

__global__ void scan_add(int* __restrict__ offs, const int* __restrict__ btot,
                         int* __restrict__ cursor, int n, int total)
{
    int i = blockIdx.x * blockDim.x + threadIdx.x;
    if (i < n) {
        int v = offs[i] + btot[i >> 10];
        offs[i] = v;
        cursor[i] = v;
    }
    if (i == 0) offs[n] = total;
}

__global__ void scan4k(const int* __restrict__ deg, int* __restrict__ offs,
                       int* __restrict__ cursor, int total)
{
    __shared__ int ts[1024];
    int t = threadIdx.x;
    int base = t * 4;
    int a0 = deg[base], a1 = deg[base+1], a2 = deg[base+2], a3 = deg[base+3];
    int s = a0 + a1 + a2 + a3;
    ts[t] = s; __syncthreads();
    for (int off = 1; off < 1024; off <<= 1) {
        int v = (t >= off) ? ts[t - off] : 0;
        __syncthreads();
        ts[t] += v;
        __syncthreads();
    }
    int excl = ts[t] - s;
    int o0 = excl, o1 = excl + a0, o2 = excl + a0 + a1, o3 = excl + a0 + a1 + a2;
    offs[base] = o0;   cursor[base] = o0;
    offs[base+1] = o1; cursor[base+1] = o1;
    offs[base+2] = o2; cursor[base+2] = o2;
    offs[base+3] = o3; cursor[base+3] = o3;
    if (t == 1023) offs[4096] = total;
}

__global__ void scatter_px(const int* __restrict__ src, const int* __restrict__ dst,
                           int* __restrict__ cursor, int* __restrict__ csr, int n)
{
    int e = blockIdx.x * blockDim.x + threadIdx.x;
    if (e < n) {
        int p = atomicAdd(&cursor[src[e]], 1);
        csr[p] = dst[e];
    }
}

__global__ void scatter_a(const int* __restrict__ asrc, const int* __restrict__ adst,
                          const float* __restrict__ aw, int* __restrict__ cursor,
                          int* __restrict__ csrs, float* __restrict__ csrw, int n)
{
    int e = blockIdx.x * blockDim.x + threadIdx.x;
    if (e < n) {
        int p = atomicAdd(&cursor[adst[e]], 1);
        csrs[p] = asrc[e];
        csrw[p] = aw[e];
    }
}

__global__ void scatter_seg(const int* __restrict__ seg, int* __restrict__ cursor,
                            int* __restrict__ csr, int n)
{
    int i = blockIdx.x * blockDim.x + threadIdx.x;
    if (i < n) {
        int p = atomicAdd(&cursor[seg[i]], 1);
        csr[p] = i;
    }
}

// ---------------- weight packing: [2][2][128][64] -> [2][128][128] ----------------
__global__ void pack_weights(const float* __restrict__ Wv, const float* __restrict__ bv,
                             const float* __restrict__ Wq, const float* __restrict__ bq,
                             float* __restrict__ wvp, float* __restrict__ bvp,
                             float* __restrict__ wqp, float* __restrict__ bqp)
{
    int idx = blockIdx.x * blockDim.x + threadIdx.x;
    if (idx >= 2 * HD * HD) return;
    int l = idx >> 14;
    int rem = idx & 16383;
    int k = rem >> 7;
    int c = rem & 127;
    int h = c >> 6;
    int j = c & 63;
    int sidx = ((l * 2 + h) * HD + k) * 64 + j;
    wvp[idx] = Wv[sidx];
    wqp[idx] = Wq[sidx];
    if (k == 0) {
        bvp[(l << 7) | c] = bv[(l * 2 + h) * 64 + j];
        bqp[(l << 7) | c] = bq[(l * 2 + h) * 64 + j];
    }
}

// ---------------- generic TC GEMM: C[M,128] = BNaff(A)[M,K] @ B[K,128] + bias ----
__global__ __launch_bounds__(256) void gemm_tc(
    const float* __restrict__ A, const float* __restrict__ B,
    const float* __restrict__ bias, float* __restrict__ C, int M, int K,
    const float* __restrict__ aA, const float* __restrict__ aB, int lrelu)
{
    __shared__ unsigned As_h[128 * 8];
    __shared__ unsigned As_l[128 * 8];
    __shared__ unsigned Bs_h[8 * 132];
    __shared__ unsigned Bs_l[8 * 132];

    const int tid  = threadIdx.x;
    const int lane = tid & 31;
    const int warp = tid >> 5;
    const int wm   = warp >> 2;
    const int wn   = warp & 3;
    const int m0   = blockIdx.x * 128;

    float acc[4][4][4];
#pragma unroll
    for (int mt = 0; mt < 4; mt++)
#pragma unroll
        for (int nt = 0; nt < 4; nt++)
#pragma unroll
            for (int i = 0; i < 4; i++) acc[mt][nt][i] = 0.f;

    const int lr = lane >> 2;
    const int jj = lane & 3;

    for (int k0 = 0; k0 < K; k0 += 16) {
        {
            int r  = tid & 127;
            int qb = (tid >> 7) << 1;
            const float* ap = A + (size_t)(m0 + r) * K;
#pragma unroll
            for (int qq = 0; qq < 2; qq++) {
                int q  = qb + qq;
                int kk = k0 + q * 4;
                float v0 = 0.f, v1 = 0.f, v2 = 0.f, v3 = 0.f;
                if (kk + 3 < K) {
                    float4 t = *(const float4*)(ap + kk);
                    v0 = t.x; v1 = t.y; v2 = t.z; v3 = t.w;
                } else {
                    if (kk + 0 < K) v0 = ap[kk + 0];
                    if (kk + 1 < K) v1 = ap[kk + 1];
                    if (kk + 2 < K) v2 = ap[kk + 2];
                    if (kk + 3 < K) v3 = ap[kk + 3];
                }
                if (aA) {
                    float4 a4 = *(const float4*)(aA + kk);
                    float4 b4 = *(const float4*)(aB + kk);
                    v0 = fmaf(v0, a4.x, b4.x);
                    v1 = fmaf(v1, a4.y, b4.y);
                    v2 = fmaf(v2, a4.z, b4.z);
                    v3 = fmaf(v3, a4.w, b4.w);
                    if (lrelu) {
                        v0 = lrelu1(v0); v1 = lrelu1(v1);
                        v2 = lrelu1(v2); v3 = lrelu1(v3);
                    }
                }
                unsigned h0, l0, h1, l1, h2, l2, h3, l3;
                cvt_hilo(v0, h0, l0); cvt_hilo(v1, h1, l1);
                cvt_hilo(v2, h2, l2); cvt_hilo(v3, h3, l3);
                As_h[r * 8 + q * 2 + 0] = h0 | (h1 << 16);
                As_h[r * 8 + q * 2 + 1] = h2 | (h3 << 16);
                As_l[r * 8 + q * 2 + 0] = l0 | (l1 << 16);
                As_l[r * 8 + q * 2 + 1] = l2 | (l3 << 16);
            }
        }
        {
            int kp  = tid >> 5;
            int np0 = tid & 31;
#pragma unroll
            for (int hh = 0; hh < 2; hh++) {
                int np = np0 + hh * 32;
                int n  = np * 2;
                int ka = k0 + kp * 2;
                float a = 0.f, b = 0.f, c = 0.f, d = 0.f;
                if (ka < K)     { float2 t = *(const float2*)(B + (size_t)ka * 128 + n);       a = t.x; b = t.y; }
                if (ka + 1 < K) { float2 t = *(const float2*)(B + (size_t)(ka + 1) * 128 + n); c = t.x; d = t.y; }
                unsigned ha, la, hb_, lb, hc, lc, hd, ld;
                cvt_hilo(a, ha, la); cvt_hilo(b, hb_, lb);
                cvt_hilo(c, hc, lc); cvt_hilo(d, hd, ld);
                Bs_h[kp * 132 + n + 0] = ha  | (hc << 16);
                Bs_h[kp * 132 + n + 1] = hb_ | (hd << 16);
                Bs_l[kp * 132 + n + 0] = la  | (lc << 16);
                Bs_l[kp * 132 + n + 1] = lb  | (ld << 16);
            }
        }
        __syncthreads();

        unsigned ah[4][4];
#pragma unroll
        for (int mt = 0; mt < 4; mt++) {
            int r = wm * 64 + mt * 16 + lr;
            ah[mt][0] = As_h[r * 8 + jj];
            ah[mt][1] = As_h[(r + 8) * 8 + jj];
            ah[mt][2] = As_h[r * 8 + jj + 4];
            ah[mt][3] = As_h[(r + 8) * 8 + jj + 4];
        }
        unsigned bh[4][2];
#pragma unroll
        for (int nt = 0; nt < 4; nt++) {
            int n = wn * 32 + nt * 8 + lr;
            bh[nt][0] = Bs_h[jj * 132 + n];
            bh[nt][1] = Bs_h[(jj + 4) * 132 + n];
        }
#pragma unroll
        for (int mt = 0; mt < 4; mt++)
#pragma unroll
            for (int nt = 0; nt < 4; nt++)
                mma16816(acc[mt][nt], ah[mt], bh[nt]);
        {
            unsigned bl[4][2];
#pragma unroll
            for (int nt = 0; nt < 4; nt++) {
                int n = wn * 32 + nt * 8 + lr;
                bl[nt][0] = Bs_l[jj * 132 + n];
                bl[nt][1] = Bs_l[(jj + 4) * 132 + n];
            }
#pragma unroll
            for (int mt = 0; mt < 4; mt++)
#pragma unroll
                for (int nt = 0; nt < 4; nt++)
                    mma16816(acc[mt][nt], ah[mt], bl[nt]);
        }
#pragma unroll
        for (int mt = 0; mt < 4; mt++) {
            int r = wm * 64 + mt * 16 + lr;
            ah[mt][0] = As_l[r * 8 + jj];
            ah[mt][1] = As_l[(r + 8) * 8 + jj];
            ah[mt][2] = As_l[r * 8 + jj + 4];
            ah[mt][3] = As_l[(r + 8) * 8 + jj + 4];
        }
#pragma unroll
        for (int mt = 0; mt < 4; mt++)
#pragma unroll
            for (int nt = 0; nt < 4; nt++)
                mma16816(acc[mt][nt], ah[mt], bh[nt]);
        __syncthreads();
    }

    const int lc2 = (lane & 3) * 2;
#pragma unroll
    for (int nt = 0; nt < 4; nt++) {
        int col = wn * 32 + nt * 8 + lc2;
        float b0 = bias[col], b1 = bias[col + 1];
#pragma unroll
        for (int mt = 0; mt < 4; mt++) {
            int r0 = m0 + wm * 64 + mt * 16 + lr;
            float2 o0 = make_float2(acc[mt][nt][0] + b0, acc[mt][nt][1] + b1);
            float2 o1 = make_float2(acc[mt][nt][2] + b0, acc[mt][nt][3] + b1);
            *(float2*)(C + (size_t)r0 * 128 + col)       = o0;
            *(float2*)(C + (size_t)(r0 + 8) * 128 + col) = o1;
        }
    }
}

// ---------------- fused q/v GEMM (K=128). Even blocks: v -> bf16.
// Odd blocks: q -> per-64-half LayerNorm -> bf16. Paired blocks share A via L2.
__global__ __launch_bounds__(256) void gemm_qv(
    const float* __restrict__ A, const float* __restrict__ Bv,
    const float* __restrict__ Bq, const float* __restrict__ biasv,
    const float* __restrict__ biasq, unsigned short* __restrict__ vh,
    unsigned short* __restrict__ qh,
    const float* __restrict__ aA, const float* __restrict__ aB, int lrelu)
{
    __shared__ unsigned As_h[128 * 8];
    __shared__ unsigned As_l[128 * 8];
    __shared__ unsigned Bs_h[8 * 132];
    __shared__ unsigned Bs_l[8 * 132];
    __shared__ float lns[128][2][2];
    __shared__ float lnq[128][2][2];

    const int tid  = threadIdx.x;
    const int lane = tid & 31;
    const int warp = tid >> 5;
    const int wm   = warp >> 2;
    const int wn   = warp & 3;
    const int isq  = blockIdx.x & 1;
    const int m0   = (blockIdx.x >> 1) * 128;
    const float* B    = isq ? Bq : Bv;
    const float* bias = isq ? biasq : biasv;

    float acc[4][4][4];
#pragma unroll
    for (int mt = 0; mt < 4; mt++)
#pragma unroll
        for (int nt = 0; nt < 4; nt++)
#pragma unroll
            for (int i = 0; i < 4; i++) acc[mt][nt][i] = 0.f;

    const int lr = lane >> 2;
    const int jj = lane & 3;

    for (int k0 = 0; k0 < 128; k0 += 16) {
        {
            int r  = tid & 127;
            int qb = (tid >> 7) << 1;
            const float* ap = A + (size_t)(m0 + r) * 128;
#pragma unroll
            for (int qq = 0; qq < 2; qq++) {
                int q  = qb + qq;
                int kk = k0 + q * 4;
                float4 t = *(const float4*)(ap + kk);
                float4 a4 = *(const float4*)(aA + kk);
                float4 b4 = *(const float4*)(aB + kk);
                float v0 = fmaf(t.x, a4.x, b4.x);
                float v1 = fmaf(t.y, a4.y, b4.y);
                float v2 = fmaf(t.z, a4.z, b4.z);
                float v3 = fmaf(t.w, a4.w, b4.w);
                if (lrelu) {
                    v0 = lrelu1(v0); v1 = lrelu1(v1);
                    v2 = lrelu1(v2); v3 = lrelu1(v3);
                }
                unsigned h0, l0, h1, l1, h2, l2, h3, l3;
                cvt_hilo(v0, h0, l0); cvt_hilo(v1, h1, l1);
                cvt_hilo(v2, h2, l2); cvt_hilo(v3, h3, l3);
                As_h[r * 8 + q * 2 + 0] = h0 | (h1 << 16);
                As_h[r * 8 + q * 2 + 1] = h2 | (h3 << 16);
                As_l[r * 8 + q * 2 + 0] = l0 | (l1 << 16);
                As_l[r * 8 + q * 2 + 1] = l2 | (l3 << 16);
            }
        }
        {
            int kp  = tid >> 5;
            int np0 = tid & 31;
#pragma unroll
            for (int hh = 0; hh < 2; hh++) {
                int np = np0 + hh * 32;
                int n  = np * 2;
                int ka = k0 + kp * 2;
                float2 t0 = *(const float2*)(B + (size_t)ka * 128 + n);
                float2 t1 = *(const float2*)(B + (size_t)(ka + 1) * 128 + n);
                unsigned ha, la, hb_, lb, hc, lc_, hd, ld;
                cvt_hilo(t0.x, ha, la); cvt_hilo(t0.y, hb_, lb);
                cvt_hilo(t1.x, hc, lc_); cvt_hilo(t1.y, hd, ld);
                Bs_h[kp * 132 + n + 0] = ha  | (hc << 16);
                Bs_h[kp * 132 + n + 1] = hb_ | (hd << 16);
                Bs_l[kp * 132 + n + 0] = la  | (lc_ << 16);
                Bs_l[kp * 132 + n + 1] = lb  | (ld << 16);
            }
        }
        __syncthreads();

        unsigned ah[4][4];
#pragma unroll
        for (int mt = 0; mt < 4; mt++) {
            int r = wm * 64 + mt * 16 + lr;
            ah[mt][0] = As_h[r * 8 + jj];
            ah[mt][1] = As_h[(r + 8) * 8 + jj];
            ah[mt][2] = As_h[r * 8 + jj + 4];
            ah[mt][3] = As_h[(r + 8) * 8 + jj + 4];
        }
        unsigned bh[4][2];
#pragma unroll
        for (int nt = 0; nt < 4; nt++) {
            int n = wn * 32 + nt * 8 + lr;
            bh[nt][0] = Bs_h[jj * 132 + n];
            bh[nt][1] = Bs_h[(jj + 4) * 132 + n];
        }
#pragma unroll
        for (int mt = 0; mt < 4; mt++)
#pragma unroll
            for (int nt = 0; nt < 4; nt++)
                mma16816(acc[mt][nt], ah[mt], bh[nt]);
        {
            unsigned bl[4][2];
#pragma unroll
            for (int nt = 0; nt < 4; nt++) {
                int n = wn * 32 + nt * 8 + lr;
                bl[nt][0] = Bs_l[jj * 132 + n];
                bl[nt][1] = Bs_l[(jj + 4) * 132 + n];
            }
#pragma unroll
            for (int mt = 0; mt < 4; mt++)
#pragma unroll
                for (int nt = 0; nt < 4; nt++)
                    mma16816(acc[mt][nt], ah[mt], bl[nt]);
        }
#pragma unroll
        for (int mt = 0; mt < 4; mt++) {
            int r = wm * 64 + mt * 16 + lr;
            ah[mt][0] = As_l[r * 8 + jj];
            ah[mt][1] = As_l[(r + 8) * 8 + jj];
            ah[mt][2] = As_l[r * 8 + jj + 4];
            ah[mt][3] = As_l[(r + 8) * 8 + jj + 4];
        }
#pragma unroll
        for (int mt = 0; mt < 4; mt++)
#pragma unroll
            for (int nt = 0; nt < 4; nt++)
                mma16816(acc[mt][nt], ah[mt], bh[nt]);
        __syncthreads();
    }

    // ---- bias into acc ----
#pragma unroll
    for (int nt = 0; nt < 4; nt++) {
        int col = wn * 32 + nt * 8 + jj * 2;
        float b0 = bias[col], b1 = bias[col + 1];
#pragma unroll
        for (int mt = 0; mt < 4; mt++) {
            acc[mt][nt][0] += b0; acc[mt][nt][1] += b1;
            acc[mt][nt][2] += b0; acc[mt][nt][3] += b1;
        }
    }

    if (!isq) {
        // ---- v path: bf16 store ----
#pragma unroll
        for (int nt = 0; nt < 4; nt++) {
            int col = wn * 32 + nt * 8 + jj * 2;
#pragma unroll
            for (int mt = 0; mt < 4; mt++) {
                int r0 = m0 + wm * 64 + mt * 16 + lr;
                __nv_bfloat162 p0 = __float22bfloat162_rn(
                    make_float2(acc[mt][nt][0], acc[mt][nt][1]));
                __nv_bfloat162 p1 = __float22bfloat162_rn(
                    make_float2(acc[mt][nt][2], acc[mt][nt][3]));
                *(unsigned*)&vh[(size_t)r0 * 128 + col]       = *(unsigned*)&p0;
                *(unsigned*)&vh[(size_t)(r0 + 8) * 128 + col] = *(unsigned*)&p1;
            }
        }
    } else {
        // ---- q path: per-64-half LayerNorm, then bf16 store ----
        int half = wn >> 1, slot = wn & 1;
#pragma unroll
        for (int mt = 0; mt < 4; mt++) {
#pragma unroll
            for (int sub = 0; sub < 2; sub++) {
                float s = 0.f, sq = 0.f;
#pragma unroll
                for (int nt = 0; nt < 4; nt++) {
                    float a = acc[mt][nt][sub * 2], b = acc[mt][nt][sub * 2 + 1];
                    s += a + b;
                    sq += a * a + b * b;
                }
                s  += __shfl_xor_sync(0xffffffffu, s, 1);
                sq += __shfl_xor_sync(0xffffffffu, sq, 1);
                s  += __shfl_xor_sync(0xffffffffu, s, 2);
                sq += __shfl_xor_sync(0xffffffffu, sq, 2);
                int row = wm * 64 + mt * 16 + sub * 8 + lr;
                if (jj == 0) { lns[row][half][slot] = s; lnq[row][half][slot] = sq; }
            }
        }
        __syncthreads();
        {
            int row = tid >> 1, hh = tid & 1;
            float s  = lns[row][hh][0] + lns[row][hh][1];
            float sq = lnq[row][hh][0] + lnq[row][hh][1];
            float m  = s * (1.f / 64.f);
            float var = sq * (1.f / 64.f) - m * m;
            float r  = rsqrtf(var + 1e-5f);
            lns[row][hh][0] = m;
            lns[row][hh][1] = r;
        }
        __syncthreads();
#pragma unroll
        for (int nt = 0; nt < 4; nt++) {
            int col = wn * 32 + nt * 8 + jj * 2;
#pragma unroll
            for (int mt = 0; mt < 4; mt++) {
                int lrow0 = wm * 64 + mt * 16 + lr;
                int lrow1 = lrow0 + 8;
                float m0_ = lns[lrow0][half][0], r0_ = lns[lrow0][half][1];
                float m1_ = lns[lrow1][half][0], r1_ = lns[lrow1][half][1];
                __nv_bfloat162 p0 = __float22bfloat162_rn(
                    make_float2((acc[mt][nt][0] - m0_) * r0_,
                                (acc[mt][nt][1] - m0_) * r0_));
                __nv_bfloat162 p1 = __float22bfloat162_rn(
                    make_float2((acc[mt][nt][2] - m1_) * r1_,
                                (acc[mt][nt][3] - m1_) * r1_));
                *(unsigned*)&qh[(size_t)(m0 + lrow0) * 128 + col] = *(unsigned*)&p0;
                *(unsigned*)&qh[(size_t)(m0 + lrow1) * 128 + col] = *(unsigned*)&p1;
            }
        }
    }
}

// ---------------- BatchNorm stats on raw tensor -> fused affine (A,B) ----------
__global__ void colstats(const float* __restrict__ X, int nrows,
                         double* __restrict__ stats)
{
    int c    = threadIdx.x & 127;
    int half = threadIdx.x >> 7;
    float s = 0.f, s2 = 0.f;
    for (int r = blockIdx.x * 2 + half; r < nrows; r += gridDim.x * 2) {
        float v = X[(size_t)r * 128 + c];
        s += v;
        s2 = fmaf(v, v, s2);
    }
    __shared__ float sh[2][128], sh2[2][128];
    sh[half][c] = s; sh2[half][c] = s2;
    __syncthreads();
    if (half == 0) {
        atomicAdd(&stats[c],       (double)(s  + sh[1][c]));
        atomicAdd(&stats[128 + c], (double)(s2 + sh2[1][c]));
    }
}

__global__ void finalize_aff(const double* __restrict__ stats,
                             const float* __restrict__ g, const float* __restrict__ b,
                             float* __restrict__ affA, float* __restrict__ affB,
                             double inv_n)
{
    int c = threadIdx.x;
    double m   = stats[c] * inv_n;
    double var = stats[128 + c] * inv_n - m * m;
    float A = (float)(1.0 / sqrt(var + 1e-5)) * g[c];
    affA[c] = A;
    affB[c] = b[c] - (float)m * A;
}

// ---------------- BatchNorm (small, fused: stats + apply + lrelu) ----------------
__global__ void bn_small(const float* __restrict__ X, float* __restrict__ Y,
                         const float* __restrict__ g, const float* __restrict__ b,
                         int nrows)
{
    int bcol = blockIdx.x;
    int t = threadIdx.x;
    float4 s  = make_float4(0.f, 0.f, 0.f, 0.f);
    float4 s2 = make_float4(0.f, 0.f, 0.f, 0.f);
    for (int r = t; r < nrows; r += 128) {
        float4 v = ((const float4*)X)[(size_t)r * 32 + bcol];
        s.x += v.x; s.y += v.y; s.z += v.z; s.w += v.w;
        s2.x = fmaf(v.x, v.x, s2.x); s2.y = fmaf(v.y, v.y, s2.y);
        s2.z = fmaf(v.z, v.z, s2.z); s2.w = fmaf(v.w, v.w, s2.w);
    }
    __shared__ float4 sh[128], sh2[128];
    sh[t] = s; sh2[t] = s2;
    __syncthreads();
    for (int off = 64; off >= 1; off >>= 1) {
        if (t < off) {
            sh[t].x += sh[t+off].x; sh[t].y += sh[t+off].y;
            sh[t].z += sh[t+off].z; sh[t].w += sh[t+off].w;
            sh2[t].x += sh2[t+off].x; sh2[t].y += sh2[t+off].y;
            sh2[t].z += sh2[t+off].z; sh2[t].w += sh2[t+off].w;
        }
        __syncthreads();
    }
    __shared__ float4 mean4, scl4;
    if (t == 0) {
        float inv = 1.f / (float)nrows;
        float4 m = make_float4(sh[0].x*inv, sh[0].y*inv, sh[0].z*inv, sh[0].w*inv);
        mean4 = m;
        scl4.x = rsqrtf(sh2[0].x*inv - m.x*m.x + 1e-5f);
        scl4.y = rsqrtf(sh2[0].y*inv - m.y*m.y + 1e-5f);
        scl4.z = rsqrtf(sh2[0].z*inv - m.z*m.z + 1e-5f);
        scl4.w = rsqrtf(sh2[0].w*inv - m.w*m.w + 1e-5f);
    }
    __syncthreads();
    float4 g4 = ((const float4*)g)[bcol];
    float4 b4 = ((const float4*)b)[bcol];
    float4 m4 = mean4, c4 = scl4;
    for (int r = t; r < nrows; r += 128) {
        float4 v = ((const float4*)X)[(size_t)r * 32 + bcol];
        float4 o;
        o.x = lrelu1((v.x - m4.x) * c4.x * g4.x + b4.x);
        o.y = lrelu1((v.y - m4.y) * c4.y * g4.y + b4.y);
        o.z = lrelu1((v.z - m4.z) * c4.z * g4.z + b4.z);
        o.w = lrelu1((v.w - m4.w) * c4.w * g4.w + b4.w);
        ((float4*)Y)[(size_t)r * 32 + bcol] = o;
    }
}

// ---------------- fused per-node attention (online softmax, warp per node) -----
__global__ __launch_bounds__(256) void pf_attn(
    const unsigned short* __restrict__ qh, const unsigned short* __restrict__ vh,
    const int* __restrict__ offs, const int* __restrict__ csr,
    float* __restrict__ out)
{
    int n    = (blockIdx.x * 256 + threadIdx.x) >> 5;
    int lane = threadIdx.x & 31;
    int e0 = offs[n], e1 = offs[n + 1];
    uint2 qn2 = ((const uint2*)qh)[(size_t)n * 32 + lane];
    float2 qn0 = __bfloat1622float2(*(__nv_bfloat162*)&qn2.x);
    float2 qn1 = __bfloat1622float2(*(__nv_bfloat162*)&qn2.y);
    float m = __int_as_float(0xff800000);   // -inf
    float z = 0.f;
    float4 acc = make_float4(0.f, 0.f, 0.f, 0.f);
    int d = (e0 < e1) ? csr[e0] : 0;
    for (int e = e0; e < e1; e++) {
        int dn = (e + 1 < e1) ? csr[e + 1] : d;
        uint2 qd2 = ((const uint2*)qh)[(size_t)d * 32 + lane];
        uint2 vd2 = ((const uint2*)vh)[(size_t)d * 32 + lane];
        float2 qd0 = __bfloat1622float2(*(__nv_bfloat162*)&qd2.x);
        float2 qd1 = __bfloat1622float2(*(__nv_bfloat162*)&qd2.y);
        float2 v0  = __bfloat1622float2(*(__nv_bfloat162*)&vd2.x);
        float2 v1  = __bfloat1622float2(*(__nv_bfloat162*)&vd2.y);
        float p = qn0.x * qd0.x + qn0.y * qd0.y + qn1.x * qd1.x + qn1.y * qd1.y;
        p += __shfl_xor_sync(0xffffffffu, p, 1);
        p += __shfl_xor_sync(0xffffffffu, p, 2);
        p += __shfl_xor_sync(0xffffffffu, p, 4);
        p += __shfl_xor_sync(0xffffffffu, p, 8);
        float s = p * (1.0f / 128.0f);      // per 16-lane half (head)
        float mn = fmaxf(m, s);
        float sc = __expf(m - mn);
        float ee = __expf(s - mn);
        z = z * sc + ee;
        acc.x = acc.x * sc + ee * v0.x;
        acc.y = acc.y * sc + ee * v0.y;
        acc.z = acc.z * sc + ee * v1.x;
        acc.w = acc.w * sc + ee * v1.y;
        m = mn;
        d = dn;
    }
    float iz = (z > 0.f) ? __fdividef(1.f, z) : 0.f;
    ((float4*)out)[(size_t)n * 32 + lane] =
        make_float4(acc.x * iz, acc.y * iz, acc.z * iz, acc.w * iz);
}

// ---------------- fused superpixel pooling (affine on x0 applied on load) -------
__global__ __launch_bounds__(256) void pool_f(
    const float* __restrict__ x0, const int* __restrict__ offs,
    const int* __restrict__ pix, const float* __restrict__ affA,
    const float* __restrict__ affB, float* __restrict__ hp)
{
    int s    = (blockIdx.x * 256 + threadIdx.x) >> 5;
    int lane = threadIdx.x & 31;
    int e0 = offs[s], e1 = offs[s + 1];
    float4 a4 = ((const float4*)affA)[lane];
    float4 b4 = ((const float4*)affB)[lane];
    float4 acc = make_float4(0.f, 0.f, 0.f, 0.f);
    for (int e = e0; e < e1; e++) {
        int p = pix[e];
        float4 xv = ((const float4*)x0)[(size_t)p * 32 + lane];
        acc.x += fmaf(xv.x, a4.x, b4.x);
        acc.y += fmaf(xv.y, a4.y, b4.y);
        acc.z += fmaf(xv.z, a4.z, b4.z);
        acc.w += fmaf(xv.w, a4.w, b4.w);
    }
    float ic = 1.f / fmaxf((float)(e1 - e0), 1.f);
    ((float4*)hp)[(size_t)s * 32 + lane] =
        make_float4(acc.x * ic, acc.y * ic, acc.z * ic, acc.w * ic);
}

// ---------------- fused superpixel propagate (warp per dst node) ----------------
__global__ __launch_bounds__(256) void sf_prop_f(
    const float* __restrict__ h, const int* __restrict__ offs,
    const int* __restrict__ csrs, const float* __restrict__ csrw,
    const float* __restrict__ xs, float* __restrict__ out, int mode)
{
    int n    = (blockIdx.x * 256 + threadIdx.x) >> 5;
    int lane = threadIdx.x & 31;
    int e0 = offs[n], e1 = offs[n + 1];
    float4 acc = make_float4(0.f, 0.f, 0.f, 0.f);
    for (int e = e0; e < e1; e++) {
        int s = csrs[e];
        float w = csrw[e];
        float4 hv = ((const float4*)h)[(size_t)s * 32 + lane];
        acc.x = fmaf(w, hv.x, acc.x);
        acc.y = fmaf(w, hv.y, acc.y);
        acc.z = fmaf(w, hv.z, acc.z);
        acc.w = fmaf(w, hv.w, acc.w);
    }
    if (mode == 0) {
        ((float4*)out)[(size_t)n * 32 + lane] = acc;
    } else {
        float4 x = ((const float4*)xs)[(size_t)n * 32 + lane];
        const float inv = 1.0f / 2.9f;
        ((float4*)out)[(size_t)n * 32 + lane] =
            make_float4((acc.x + x.x) * inv, (acc.y + x.y) * inv,
                        (acc.z + x.z) * inv, (acc.w + x.w) * inv);
    }
}

// ---------------- final: H1 = BNaff(pfb) + hp[seg]; softmax(H1 @ W + b) ---------
__global__ __launch_bounds__(256) void final_out(
    const float* __restrict__ pf, const float* __restrict__ hp,
    const int* __restrict__ seg, const float* __restrict__ Wout,
    const float* __restrict__ bout, const float* __restrict__ affA,
    const float* __restrict__ affB, float* __restrict__ out, int nrows)
{
    __shared__ float sWt[16 * 128];
    __shared__ float sb[16];
    for (int i = threadIdx.x; i < 2048; i += 256) {
        int k = i >> 4, c = i & 15;
        sWt[c * 128 + k] = Wout[i];
    }
    if (threadIdx.x < 16) sb[threadIdx.x] = bout[threadIdx.x];
    __syncthreads();

    int warp = (blockIdx.x * 256 + threadIdx.x) >> 5;
    int lane = threadIdx.x & 31;
    if (warp >= nrows) return;
    int s = seg[warp];
    float4 aA = ((const float4*)affA)[lane];
    float4 aB = ((const float4*)affB)[lane];
    float4 a = ((const float4*)pf)[(size_t)warp * 32 + lane];
    float4 b = ((const float4*)hp)[(size_t)s * 32 + lane];
    float4 h;
    h.x = lrelu1(fmaf(a.x, aA.x, aB.x)) + b.x;
    h.y = lrelu1(fmaf(a.y, aA.y, aB.y)) + b.y;
    h.z = lrelu1(fmaf(a.z, aA.z, aB.z)) + b.z;
    h.w = lrelu1(fmaf(a.w, aA.w, aB.w)) + b.w;

    float lg[16];
#pragma unroll
    for (int c = 0; c < 16; c++) {
        float4 w = ((const float4*)sWt)[c * 32 + lane];
        lg[c] = h.x * w.x + h.y * w.y + h.z * w.z + h.w * w.w;
    }
#pragma unroll
    for (int off = 16; off >= 1; off >>= 1)
#pragma unroll
        for (int c = 0; c < 16; c++)
            lg[c] += __shfl_xor_sync(0xffffffffu, lg[c], off);

    if (lane < 16) {
        float mx = -1e30f;
#pragma unroll
        for (int c = 0; c < 16; c++) { lg[c] += sb[c]; mx = fmaxf(mx, lg[c]); }
        float sum = 0.f;
#pragma unroll
        for (int c = 0; c < 16; c++) { lg[c] = __expf(lg[c] - mx); sum += lg[c]; }
        float inv = __fdividef(1.0f, sum);
        float r = 0.f;
#pragma unroll
        for (int c = 0; c < 16; c++) if (lane == c) r = lg[c];
        out[(size_t)warp * 16 + lane] = r * inv;
    }
}

// ---------------- host ----------------
#define GSYM(p, sym) cudaGetSymbolAddress((void**)&p, sym)

static void run_stats(const float* X, int nrows, const float* g, const float* b,
                      double* stats, float* affA, float* affB)
{
    cudaMemsetAsync(stats, 0, 256 * sizeof(double));
    colstats<<<512, 256>>>(X, nrows, stats);
    finalize_aff<<<1, 128>>>(stats, g, b, affA, affB, 1.0 / (double)nrows);
}

extern "C" void kernel_launch(void* const* d_in, const int* in_sizes, int n_in,
                              void* d_out, int out_size)
{
    const float* x       = (const float*)d_in[0];
    const int*   seg     = (const int*)  d_in[1];
    const int*   a_src   = (const int*)  d_in[2];
    const int*   a_dst   = (const int*)  d_in[3];
    const float* a_w     = (const float*)d_in[4];
    const int*   m_src   = (const int*)  d_in[5];
    const int*   m_dst   = (const int*)  d_in[6];
    const float* pre_W   = (const float*)d_in[7];
    const float* pre_b   = (const float*)d_in[8];
    const float* bn0_g   = (const float*)d_in[9];
    const float* bn0_b   = (const float*)d_in[10];
    const float* sf_W    = (const float*)d_in[11];
    const float* sf_b    = (const float*)d_in[12];
    const float* sf_g    = (const float*)d_in[13];
    const float* sf_beta = (const float*)d_in[14];
    const float* pf_Wv   = (const float*)d_in[15];
    const float* pf_bv   = (const float*)d_in[16];
    const float* pf_Wq   = (const float*)d_in[17];
    const float* pf_bq   = (const float*)d_in[18];
    const float* pf_g    = (const float*)d_in[19];
    const float* pf_beta = (const float*)d_in[20];
    const float* out_W   = (const float*)d_in[21];
    const float* out_b   = (const float*)d_in[22];
    float* out = (float*)d_out;

    float *x0, *pfa, *pfb;
    unsigned short *qh, *vh;
    float *affA, *affB, *hp, *hb, *xs, *ba, *bb, *wv, *wq, *bv, *bq;
    double *stats;
    int *deg, *cursor, *offs, *btot, *csr;
    int *adeg, *acur, *aoffs, *acsrs;
    float *acsrw;
    int *sdeg, *scur, *soffs, *spix;
    GSYM(x0, d_x0);   GSYM(pfa, d_pfa); GSYM(pfb, d_pfb);
    GSYM(qh, d_qh);   GSYM(vh, d_vh);
    GSYM(stats, d_stats); GSYM(affA, d_affA); GSYM(affB, d_affB);
    GSYM(hp, d_hp); GSYM(hb, d_hb); GSYM(xs, d_xs);
    GSYM(ba, d_ba); GSYM(bb, d_bb);
    GSYM(wv, d_wv); GSYM(wq, d_wq); GSYM(bv, d_bv); GSYM(bq, d_bq);
    GSYM(deg, d_deg); GSYM(cursor, d_cursor); GSYM(offs, d_offs);
    GSYM(btot, d_btot); GSYM(csr, d_csr);
    GSYM(adeg, d_adeg); GSYM(acur, d_acur); GSYM(aoffs, d_aoffs);
    GSYM(acsrs, d_acsrs); GSYM(acsrw, d_acsrw);
    GSYM(sdeg, d_sdeg); GSYM(scur, d_scur); GSYM(soffs, d_soffs);
    GSYM(spix, d_spix);

    // ---- build CSRs (pixel graph by src; a-graph by dst; seg lists) ----
    cudaMemsetAsync(deg, 0, NPIX * sizeof(int));
    hist_kernel<<<EME / 256, 256>>>(m_src, deg, EME);
    scan_chunk<<<256, 256>>>(deg, offs, btot);
    scan_btot<<<1, 256>>>(btot);
    scan_add<<<NPIX / 256, 256>>>(offs, btot, cursor, NPIX, EME);
    scatter_px<<<EME / 256, 256>>>(m_src, m_dst, cursor, csr, EME);

    cudaMemsetAsync(adeg, 0, SP * sizeof(int));
    hist_kernel<<<EAE / 256, 256>>>(a_dst, adeg, EAE);
    scan4k<<<1, 1024>>>(adeg, aoffs, acur, EAE);
    scatter_a<<<EAE / 256, 256>>>(a_src, a_dst, a_w, acur, acsrs, acsrw, EAE);

    cudaMemsetAsync(sdeg, 0, SP * sizeof(int));
    hist_kernel<<<NPIX / 256, 256>>>(seg, sdeg, NPIX);
    scan4k<<<1, 1024>>>(sdeg, soffs, scur, NPIX);
    scatter_seg<<<NPIX / 256, 256>>>(seg, scur, spix, NPIX);

    // pack per-head attention weights into [128,128]
    pack_weights<<<(2 * HD * HD + 255) / 256, 256>>>(pf_Wv, pf_bv, pf_Wq, pf_bq,
                                                     wv, bv, wq, bq);

    // ---- pre: x0raw = x @ pre_W + pre_b; BN folded into consumers (slot 0) ----
    gemm_tc<<<NPIX / 128, 256>>>(x, pre_W, pre_b, x0, NPIX, CIN,
                                 (const float*)0, (const float*)0, 0);
    run_stats(x0, NPIX, bn0_g, bn0_b, stats, affA, affB);

    // ---- PF branch: 2 attention layers on the pixel graph ----
    const float* pin = x0;
    for (int l = 0; l < 2; l++) {
        float* pout = (l == 0) ? pfa : pfb;
        const float* aA = affA + l * HD;
        const float* aB = affB + l * HD;
        int lr = (l > 0);
        gemm_qv<<<NPIX / 128 * 2, 256>>>(pin, wv + l * HD * HD, wq + l * HD * HD,
                                         bv + l * HD, bq + l * HD, vh, qh, aA, aB, lr);
        pf_attn<<<NPIX / 8, 256>>>(qh, vh, offs, csr, pout);
        run_stats(pout, NPIX, pf_g + l * HD, pf_beta + l * HD, stats,
                  affA + (l + 1) * HD, affB + (l + 1) * HD);
        pin = pout;
    }

    // ---- SF branch: pool (bn0 affine fused) -> 5 SFNet layers ----
    pool_f<<<SP / 8, 256>>>(x0, soffs, spix, affA, affB, hp);

    for (int l = 0; l < 5; l++) {
        gemm_tc<<<SP / 128, 256>>>(hp, sf_W + l * HD * HD, sf_b + l * HD, hb,
                                   SP, HD, (const float*)0, (const float*)0, 0);
        sf_prop_f<<<SP / 8, 256>>>(hb, aoffs, acsrs, acsrw, xs, xs, 0);
        const float* cur = hp;
        for (int it = 0; it < 5; it++) {
            float* nxt = (it & 1) ? bb : ba;
            sf_prop_f<<<SP / 8, 256>>>(cur, aoffs, acsrs, acsrw, xs, nxt, 1);
            cur = nxt;
        }
        bn_small<<<32, 128>>>(cur, hp, sf_g + l * HD, sf_beta + l * HD, SP);
    }

    // ---- final: softmax((BNaff(pfb) + hp[seg]) @ out_W + out_b) ----
    final_out<<<NPIX / 8, 256>>>(pfb, hp, seg, out_W, out_b,
                                 affA + 2 * HD, affB + 2 * HD, out, NPIX);
}

// round 11
// speedup vs baseline: 2.6642x; 1.3305x over previous
#include <cuda_runtime.h>
#include <cuda_bf16.h>
#include <cuda_fp16.h>

#define NPIX 262144
#define CIN  200
#define HD   128
#define SP   4096
#define EAE  65536
#define EME  2097152
#define NCLS 16

// ---------------- scratch (device globals; allocation-free rule) ----------------
__device__ float  d_x0 [NPIX*HD];
__device__ float  d_pfa[NPIX*HD];
__device__ float  d_pfb[NPIX*HD];
__device__ unsigned short d_qh[NPIX*HD];   // bf16 q (layer-normed)
__device__ unsigned short d_vh[NPIX*HD];   // fp16 v
__device__ double d_stats[32*256];         // 32-way spread: [i][c]=sum, [i][128+c]=sumsq
__device__ float  d_affA[3*HD];            // per-BN fused scale
__device__ float  d_affB[3*HD];            // per-BN fused shift
__device__ float  d_hp [SP*HD];
__device__ float  d_hb [SP*HD];
__device__ float  d_xs [SP*HD];
__device__ float  d_ba [SP*HD];
__device__ float  d_bb [SP*HD];
__device__ float  d_wv [2*HD*HD];
__device__ float  d_wq [2*HD*HD];
__device__ float  d_bv [2*HD];
__device__ float  d_bq [2*HD];
// CSR scratch: pixel graph (by src)
__device__ int    d_deg   [NPIX];
__device__ int    d_cursor[NPIX];
__device__ int    d_offs  [NPIX+1];
__device__ int    d_btot  [256];
__device__ int    d_csr   [EME];
// superpixel graph (by dst)
__device__ int    d_adeg [SP];
__device__ int    d_acur [SP];
__device__ int    d_aoffs[SP+1];
__device__ int    d_acsrs[EAE];
__device__ float  d_acsrw[EAE];
// seg -> pixel lists
__device__ int    d_sdeg [SP];
__device__ int    d_scur [SP];
__device__ int    d_soffs[SP+1];
__device__ int    d_spix [NPIX];

// ---------------- helpers ----------------
__device__ __forceinline__ void cvt_hilo(float v, unsigned& hi, unsigned& lo) {
    __nv_bfloat16 h = __float2bfloat16(v);
    float r = v - __bfloat162float(h);
    __nv_bfloat16 l = __float2bfloat16(r);
    hi = (unsigned)__bfloat16_as_ushort(h);
    lo = (unsigned)__bfloat16_as_ushort(l);
}

__device__ __forceinline__ void mma16816(float* c, const unsigned* a, const unsigned* b) {
    asm volatile("mma.sync.aligned.m16n8k16.row.col.f32.bf16.bf16.f32 "
                 "{%0,%1,%2,%3}, {%4,%5,%6,%7}, {%8,%9}, {%0,%1,%2,%3};"
                 : "+f"(c[0]), "+f"(c[1]), "+f"(c[2]), "+f"(c[3])
                 : "r"(a[0]), "r"(a[1]), "r"(a[2]), "r"(a[3]),
                   "r"(b[0]), "r"(b[1]));
}

__device__ __forceinline__ float lrelu1(float x) { return x >= 0.f ? x : 0.01f * x; }

// ---------------- CSR construction ----------------
__global__ void hist_kernel(const int* __restrict__ idx, int* __restrict__ deg, int n)
{
    int i = blockIdx.x * blockDim.x + threadIdx.x;
    if (i < n) atomicAdd(&deg[idx[i]], 1);
}

__global__ void scan_chunk(const int* __restrict__ deg, int* __restrict__ offs,
                           int* __restrict__ btot)
{
    __shared__ int ts[256];
    int t = threadIdx.x;
    int base = blockIdx.x * 1024 + t * 4;
    int a0 = deg[base], a1 = deg[base+1], a2 = deg[base+2], a3 = deg[base+3];
    int s = a0 + a1 + a2 + a3;
    ts[t] = s; __syncthreads();
    for (int off = 1; off < 256; off <<= 1) {
        int v = (t >= off) ? ts[t - off] : 0;
        __syncthreads();
        ts[t] += v;
        __syncthreads();
    }
    int excl = ts[t] - s;
    offs[base]   = excl;
    offs[base+1] = excl + a0;
    offs[base+2] = excl + a0 + a1;
    offs[base+3] = excl + a0 + a1 + a2;
    if (t == 255) btot[blockIdx.x] = ts[255];
}

__global__ void scan_btot(int* __restrict__ btot)
{
    __shared__ int ts[256];
    int t = threadIdx.x;
    int v = btot[t];
    ts[t] = v; __syncthreads();
    for (int off = 1; off < 256; off <<= 1) {
        int u = (t >= off) ? ts[t - off] : 0;
        __syncthreads();
        ts[t] += u;
        __syncthreads();
    }
    btot[t] = ts[t] - v;
}

__global__ void scan_add(int* __restrict__ offs, const int* __restrict__ btot,
                         int* __restrict__ cursor, int n, int total)
{
    int i = blockIdx.x * blockDim.x + threadIdx.x;
    if (i < n) {
        int v = offs[i] + btot[i >> 10];
        offs[i] = v;
        cursor[i] = v;
    }
    if (i == 0) offs[n] = total;
}

__global__ void scan4k(const int* __restrict__ deg, int* __restrict__ offs,
                       int* __restrict__ cursor, int total)
{
    __shared__ int ts[1024];
    int t = threadIdx.x;
    int base = t * 4;
    int a0 = deg[base], a1 = deg[base+1], a2 = deg[base+2], a3 = deg[base+3];
    int s = a0 + a1 + a2 + a3;
    ts[t] = s; __syncthreads();
    for (int off = 1; off < 1024; off <<= 1) {
        int v = (t >= off) ? ts[t - off] : 0;
        __syncthreads();
        ts[t] += v;
        __syncthreads();
    }
    int excl = ts[t] - s;
    int o0 = excl, o1 = excl + a0, o2 = excl + a0 + a1, o3 = excl + a0 + a1 + a2;
    offs[base] = o0;   cursor[base] = o0;
    offs[base+1] = o1; cursor[base+1] = o1;
    offs[base+2] = o2; cursor[base+2] = o2;
    offs[base+3] = o3; cursor[base+3] = o3;
    if (t == 1023) offs[4096] = total;
}

__global__ void scatter_px(const int* __restrict__ src, const int* __restrict__ dst,
                           int* __restrict__ cursor, int* __restrict__ csr, int n)
{
    int e = blockIdx.x * blockDim.x + threadIdx.x;
    if (e < n) {
        int p = atomicAdd(&cursor[src[e]], 1);
        csr[p] = dst[e];
    }
}

__global__ void scatter_a(const int* __restrict__ asrc, const int* __restrict__ adst,
                          const float* __restrict__ aw, int* __restrict__ cursor,
                          int* __restrict__ csrs, float* __restrict__ csrw, int n)
{
    int e = blockIdx.x * blockDim.x + threadIdx.x;
    if (e < n) {
        int p = atomicAdd(&cursor[adst[e]], 1);
        csrs[p] = asrc[e];
        csrw[p] = aw[e];
    }
}

__global__ void scatter_seg(const int* __restrict__ seg, int* __restrict__ cursor,
                            int* __restrict__ csr, int n)
{
    int i = blockIdx.x * blockDim.x + threadIdx.x;
    if (i < n) {
        int p = atomicAdd(&cursor[seg[i]], 1);
        csr[p] = i;
    }
}

// ---------------- weight packing: [2][2][128][64] -> [2][128][128] ----------------
__global__ void pack_weights(const float* __restrict__ Wv, const float* __restrict__ bv,
                             const float* __restrict__ Wq, const float* __restrict__ bq,
                             float* __restrict__ wvp, float* __restrict__ bvp,
                             float* __restrict__ wqp, float* __restrict__ bqp)
{
    int idx = blockIdx.x * blockDim.x + threadIdx.x;
    if (idx >= 2 * HD * HD) return;
    int l = idx >> 14;
    int rem = idx & 16383;
    int k = rem >> 7;
    int c = rem & 127;
    int h = c >> 6;
    int j = c & 63;
    int sidx = ((l * 2 + h) * HD + k) * 64 + j;
    wvp[idx] = Wv[sidx];
    wqp[idx] = Wq[sidx];
    if (k == 0) {
        bvp[(l << 7) | c] = bv[(l * 2 + h) * 64 + j];
        bqp[(l << 7) | c] = bq[(l * 2 + h) * 64 + j];
    }
}

// ---------------- generic TC GEMM: C[M,128] = A[M,K] @ B[K,128] + bias ----------
// Optional fused column-stats accumulation into spread double buffer.
__global__ __launch_bounds__(256) void gemm_tc(
    const float* __restrict__ A, const float* __restrict__ B,
    const float* __restrict__ bias, float* __restrict__ C, int M, int K,
    double* __restrict__ stats)
{
    __shared__ unsigned As_h[128 * 8];
    __shared__ unsigned As_l[128 * 8];
    __shared__ unsigned Bs_h[8 * 132];
    __shared__ unsigned Bs_l[8 * 132];

    const int tid  = threadIdx.x;
    const int lane = tid & 31;
    const int warp = tid >> 5;
    const int wm   = warp >> 2;
    const int wn   = warp & 3;
    const int m0   = blockIdx.x * 128;

    float acc[4][4][4];
#pragma unroll
    for (int mt = 0; mt < 4; mt++)
#pragma unroll
        for (int nt = 0; nt < 4; nt++)
#pragma unroll
            for (int i = 0; i < 4; i++) acc[mt][nt][i] = 0.f;

    const int lr = lane >> 2;
    const int jj = lane & 3;

    for (int k0 = 0; k0 < K; k0 += 16) {
        {
            int r  = tid & 127;
            int qb = (tid >> 7) << 1;
            const float* ap = A + (size_t)(m0 + r) * K;
#pragma unroll
            for (int qq = 0; qq < 2; qq++) {
                int q  = qb + qq;
                int kk = k0 + q * 4;
                float v0 = 0.f, v1 = 0.f, v2 = 0.f, v3 = 0.f;
                if (kk + 3 < K) {
                    float4 t = *(const float4*)(ap + kk);
                    v0 = t.x; v1 = t.y; v2 = t.z; v3 = t.w;
                } else {
                    if (kk + 0 < K) v0 = ap[kk + 0];
                    if (kk + 1 < K) v1 = ap[kk + 1];
                    if (kk + 2 < K) v2 = ap[kk + 2];
                    if (kk + 3 < K) v3 = ap[kk + 3];
                }
                unsigned h0, l0, h1, l1, h2, l2, h3, l3;
                cvt_hilo(v0, h0, l0); cvt_hilo(v1, h1, l1);
                cvt_hilo(v2, h2, l2); cvt_hilo(v3, h3, l3);
                As_h[r * 8 + q * 2 + 0] = h0 | (h1 << 16);
                As_h[r * 8 + q * 2 + 1] = h2 | (h3 << 16);
                As_l[r * 8 + q * 2 + 0] = l0 | (l1 << 16);
                As_l[r * 8 + q * 2 + 1] = l2 | (l3 << 16);
            }
        }
        {
            int kp  = tid >> 5;
            int np0 = tid & 31;
#pragma unroll
            for (int hh = 0; hh < 2; hh++) {
                int np = np0 + hh * 32;
                int n  = np * 2;
                int ka = k0 + kp * 2;
                float a = 0.f, b = 0.f, c = 0.f, d = 0.f;
                if (ka < K)     { float2 t = *(const float2*)(B + (size_t)ka * 128 + n);       a = t.x; b = t.y; }
                if (ka + 1 < K) { float2 t = *(const float2*)(B + (size_t)(ka + 1) * 128 + n); c = t.x; d = t.y; }
                unsigned ha, la, hb_, lb, hc, lc, hd, ld;
                cvt_hilo(a, ha, la); cvt_hilo(b, hb_, lb);
                cvt_hilo(c, hc, lc); cvt_hilo(d, hd, ld);
                Bs_h[kp * 132 + n + 0] = ha  | (hc << 16);
                Bs_h[kp * 132 + n + 1] = hb_ | (hd << 16);
                Bs_l[kp * 132 + n + 0] = la  | (lc << 16);
                Bs_l[kp * 132 + n + 1] = lb  | (ld << 16);
            }
        }
        __syncthreads();

        unsigned ah[4][4];
#pragma unroll
        for (int mt = 0; mt < 4; mt++) {
            int r = wm * 64 + mt * 16 + lr;
            ah[mt][0] = As_h[r * 8 + jj];
            ah[mt][1] = As_h[(r + 8) * 8 + jj];
            ah[mt][2] = As_h[r * 8 + jj + 4];
            ah[mt][3] = As_h[(r + 8) * 8 + jj + 4];
        }
        unsigned bh[4][2];
#pragma unroll
        for (int nt = 0; nt < 4; nt++) {
            int n = wn * 32 + nt * 8 + lr;
            bh[nt][0] = Bs_h[jj * 132 + n];
            bh[nt][1] = Bs_h[(jj + 4) * 132 + n];
        }
#pragma unroll
        for (int mt = 0; mt < 4; mt++)
#pragma unroll
            for (int nt = 0; nt < 4; nt++)
                mma16816(acc[mt][nt], ah[mt], bh[nt]);
        {
            unsigned bl[4][2];
#pragma unroll
            for (int nt = 0; nt < 4; nt++) {
                int n = wn * 32 + nt * 8 + lr;
                bl[nt][0] = Bs_l[jj * 132 + n];
                bl[nt][1] = Bs_l[(jj + 4) * 132 + n];
            }
#pragma unroll
            for (int mt = 0; mt < 4; mt++)
#pragma unroll
                for (int nt = 0; nt < 4; nt++)
                    mma16816(acc[mt][nt], ah[mt], bl[nt]);
        }
#pragma unroll
        for (int mt = 0; mt < 4; mt++) {
            int r = wm * 64 + mt * 16 + lr;
            ah[mt][0] = As_l[r * 8 + jj];
            ah[mt][1] = As_l[(r + 8) * 8 + jj];
            ah[mt][2] = As_l[r * 8 + jj + 4];
            ah[mt][3] = As_l[(r + 8) * 8 + jj + 4];
        }
#pragma unroll
        for (int mt = 0; mt < 4; mt++)
#pragma unroll
            for (int nt = 0; nt < 4; nt++)
                mma16816(acc[mt][nt], ah[mt], bh[nt]);
        __syncthreads();
    }

    // ---- bias into acc, store ----
#pragma unroll
    for (int nt = 0; nt < 4; nt++) {
        int col = wn * 32 + nt * 8 + jj * 2;
        float b0 = bias[col], b1 = bias[col + 1];
#pragma unroll
        for (int mt = 0; mt < 4; mt++) {
            acc[mt][nt][0] += b0; acc[mt][nt][1] += b1;
            acc[mt][nt][2] += b0; acc[mt][nt][3] += b1;
        }
    }
#pragma unroll
    for (int nt = 0; nt < 4; nt++) {
        int col = wn * 32 + nt * 8 + jj * 2;
#pragma unroll
        for (int mt = 0; mt < 4; mt++) {
            int r0 = m0 + wm * 64 + mt * 16 + lr;
            *(float2*)(C + (size_t)r0 * 128 + col)       = make_float2(acc[mt][nt][0], acc[mt][nt][1]);
            *(float2*)(C + (size_t)(r0 + 8) * 128 + col) = make_float2(acc[mt][nt][2], acc[mt][nt][3]);
        }
    }

    // ---- fused column stats (sum, sumsq) ----
    if (stats) {
        float cs[4][2], cq[4][2];
#pragma unroll
        for (int nt = 0; nt < 4; nt++)
#pragma unroll
            for (int p = 0; p < 2; p++) {
                float s = 0.f, q = 0.f;
#pragma unroll
                for (int mt = 0; mt < 4; mt++) {
                    float a = acc[mt][nt][p], c = acc[mt][nt][p + 2];
                    s += a + c;
                    q += a * a + c * c;
                }
                cs[nt][p] = s; cq[nt][p] = q;
            }
        // reduce over lr (lane bits 2..4)
#pragma unroll
        for (int mk = 4; mk <= 16; mk <<= 1)
#pragma unroll
            for (int nt = 0; nt < 4; nt++)
#pragma unroll
                for (int p = 0; p < 2; p++) {
                    cs[nt][p] += __shfl_xor_sync(0xffffffffu, cs[nt][p], mk);
                    cq[nt][p] += __shfl_xor_sync(0xffffffffu, cq[nt][p], mk);
                }
        float* sS = (float*)As_h;
        float* sQ = (float*)As_l;
        if (tid < 128) { sS[tid] = 0.f; sQ[tid] = 0.f; }
        __syncthreads();
        if (lr == 0) {  // one lane per jj group per warp
#pragma unroll
            for (int nt = 0; nt < 4; nt++)
#pragma unroll
                for (int p = 0; p < 2; p++) {
                    int col = wn * 32 + nt * 8 + jj * 2 + p;
                    atomicAdd(&sS[col], cs[nt][p]);
                    atomicAdd(&sQ[col], cq[nt][p]);
                }
        }
        __syncthreads();
        if (tid < 128) {
            int sl = (blockIdx.x & 31) * 256;
            atomicAdd(&stats[sl + tid],       (double)sS[tid]);
            atomicAdd(&stats[sl + 128 + tid], (double)sQ[tid]);
        }
    }
}

// ---------------- fused q/v GEMM (K=128). Even blocks: v -> fp16.
// Odd blocks: q -> per-64-half LayerNorm -> bf16. Paired blocks share A via L2.
__global__ __launch_bounds__(256) void gemm_qv(
    const float* __restrict__ A, const float* __restrict__ Bv,
    const float* __restrict__ Bq, const float* __restrict__ biasv,
    const float* __restrict__ biasq, unsigned short* __restrict__ vh,
    unsigned short* __restrict__ qh,
    const float* __restrict__ aA, const float* __restrict__ aB, int lrelu)
{
    __shared__ unsigned As_h[128 * 8];
    __shared__ unsigned As_l[128 * 8];
    __shared__ unsigned Bs_h[8 * 132];
    __shared__ unsigned Bs_l[8 * 132];
    __shared__ float lns[128][2][2];
    __shared__ float lnq[128][2][2];

    const int tid  = threadIdx.x;
    const int lane = tid & 31;
    const int warp = tid >> 5;
    const int wm   = warp >> 2;
    const int wn   = warp & 3;
    const int isq  = blockIdx.x & 1;
    const int m0   = (blockIdx.x >> 1) * 128;
    const float* B    = isq ? Bq : Bv;
    const float* bias = isq ? biasq : biasv;

    float acc[4][4][4];
#pragma unroll
    for (int mt = 0; mt < 4; mt++)
#pragma unroll
        for (int nt = 0; nt < 4; nt++)
#pragma unroll
            for (int i = 0; i < 4; i++) acc[mt][nt][i] = 0.f;

    const int lr = lane >> 2;
    const int jj = lane & 3;

    for (int k0 = 0; k0 < 128; k0 += 16) {
        {
            int r  = tid & 127;
            int qb = (tid >> 7) << 1;
            const float* ap = A + (size_t)(m0 + r) * 128;
#pragma unroll
            for (int qq = 0; qq < 2; qq++) {
                int q  = qb + qq;
                int kk = k0 + q * 4;
                float4 t = *(const float4*)(ap + kk);
                float4 a4 = *(const float4*)(aA + kk);
                float4 b4 = *(const float4*)(aB + kk);
                float v0 = fmaf(t.x, a4.x, b4.x);
                float v1 = fmaf(t.y, a4.y, b4.y);
                float v2 = fmaf(t.z, a4.z, b4.z);
                float v3 = fmaf(t.w, a4.w, b4.w);
                if (lrelu) {
                    v0 = lrelu1(v0); v1 = lrelu1(v1);
                    v2 = lrelu1(v2); v3 = lrelu1(v3);
                }
                unsigned h0, l0, h1, l1, h2, l2, h3, l3;
                cvt_hilo(v0, h0, l0); cvt_hilo(v1, h1, l1);
                cvt_hilo(v2, h2, l2); cvt_hilo(v3, h3, l3);
                As_h[r * 8 + q * 2 + 0] = h0 | (h1 << 16);
                As_h[r * 8 + q * 2 + 1] = h2 | (h3 << 16);
                As_l[r * 8 + q * 2 + 0] = l0 | (l1 << 16);
                As_l[r * 8 + q * 2 + 1] = l2 | (l3 << 16);
            }
        }
        {
            int kp  = tid >> 5;
            int np0 = tid & 31;
#pragma unroll
            for (int hh = 0; hh < 2; hh++) {
                int np = np0 + hh * 32;
                int n  = np * 2;
                int ka = k0 + kp * 2;
                float2 t0 = *(const float2*)(B + (size_t)ka * 128 + n);
                float2 t1 = *(const float2*)(B + (size_t)(ka + 1) * 128 + n);
                unsigned ha, la, hb_, lb, hc, lc_, hd, ld;
                cvt_hilo(t0.x, ha, la); cvt_hilo(t0.y, hb_, lb);
                cvt_hilo(t1.x, hc, lc_); cvt_hilo(t1.y, hd, ld);
                Bs_h[kp * 132 + n + 0] = ha  | (hc << 16);
                Bs_h[kp * 132 + n + 1] = hb_ | (hd << 16);
                Bs_l[kp * 132 + n + 0] = la  | (lc_ << 16);
                Bs_l[kp * 132 + n + 1] = lb  | (ld << 16);
            }
        }
        __syncthreads();

        unsigned ah[4][4];
#pragma unroll
        for (int mt = 0; mt < 4; mt++) {
            int r = wm * 64 + mt * 16 + lr;
            ah[mt][0] = As_h[r * 8 + jj];
            ah[mt][1] = As_h[(r + 8) * 8 + jj];
            ah[mt][2] = As_h[r * 8 + jj + 4];
            ah[mt][3] = As_h[(r + 8) * 8 + jj + 4];
        }
        unsigned bh[4][2];
#pragma unroll
        for (int nt = 0; nt < 4; nt++) {
            int n = wn * 32 + nt * 8 + lr;
            bh[nt][0] = Bs_h[jj * 132 + n];
            bh[nt][1] = Bs_h[(jj + 4) * 132 + n];
        }
#pragma unroll
        for (int mt = 0; mt < 4; mt++)
#pragma unroll
            for (int nt = 0; nt < 4; nt++)
                mma16816(acc[mt][nt], ah[mt], bh[nt]);
        {
            unsigned bl[4][2];
#pragma unroll
            for (int nt = 0; nt < 4; nt++) {
                int n = wn * 32 + nt * 8 + lr;
                bl[nt][0] = Bs_l[jj * 132 + n];
                bl[nt][1] = Bs_l[(jj + 4) * 132 + n];
            }
#pragma unroll
            for (int mt = 0; mt < 4; mt++)
#pragma unroll
                for (int nt = 0; nt < 4; nt++)
                    mma16816(acc[mt][nt], ah[mt], bl[nt]);
        }
#pragma unroll
        for (int mt = 0; mt < 4; mt++) {
            int r = wm * 64 + mt * 16 + lr;
            ah[mt][0] = As_l[r * 8 + jj];
            ah[mt][1] = As_l[(r + 8) * 8 + jj];
            ah[mt][2] = As_l[r * 8 + jj + 4];
            ah[mt][3] = As_l[(r + 8) * 8 + jj + 4];
        }
#pragma unroll
        for (int mt = 0; mt < 4; mt++)
#pragma unroll
            for (int nt = 0; nt < 4; nt++)
                mma16816(acc[mt][nt], ah[mt], bh[nt]);
        __syncthreads();
    }

    // ---- bias into acc ----
#pragma unroll
    for (int nt = 0; nt < 4; nt++) {
        int col = wn * 32 + nt * 8 + jj * 2;
        float b0 = bias[col], b1 = bias[col + 1];
#pragma unroll
        for (int mt = 0; mt < 4; mt++) {
            acc[mt][nt][0] += b0; acc[mt][nt][1] += b1;
            acc[mt][nt][2] += b0; acc[mt][nt][3] += b1;
        }
    }

    if (!isq) {
        // ---- v path: fp16 store ----
#pragma unroll
        for (int nt = 0; nt < 4; nt++) {
            int col = wn * 32 + nt * 8 + jj * 2;
#pragma unroll
            for (int mt = 0; mt < 4; mt++) {
                int r0 = m0 + wm * 64 + mt * 16 + lr;
                __half2 p0 = __float22half2_rn(make_float2(acc[mt][nt][0], acc[mt][nt][1]));
                __half2 p1 = __float22half2_rn(make_float2(acc[mt][nt][2], acc[mt][nt][3]));
                *(unsigned*)&vh[(size_t)r0 * 128 + col]       = *(unsigned*)&p0;
                *(unsigned*)&vh[(size_t)(r0 + 8) * 128 + col] = *(unsigned*)&p1;
            }
        }
    } else {
        // ---- q path: per-64-half LayerNorm, then bf16 store ----
        int half = wn >> 1, slot = wn & 1;
#pragma unroll
        for (int mt = 0; mt < 4; mt++) {
#pragma unroll
            for (int sub = 0; sub < 2; sub++) {
                float s = 0.f, sq = 0.f;
#pragma unroll
                for (int nt = 0; nt < 4; nt++) {
                    float a = acc[mt][nt][sub * 2], b = acc[mt][nt][sub * 2 + 1];
                    s += a + b;
                    sq += a * a + b * b;
                }
                s  += __shfl_xor_sync(0xffffffffu, s, 1);
                sq += __shfl_xor_sync(0xffffffffu, sq, 1);
                s  += __shfl_xor_sync(0xffffffffu, s, 2);
                sq += __shfl_xor_sync(0xffffffffu, sq, 2);
                int row = wm * 64 + mt * 16 + sub * 8 + lr;
                if (jj == 0) { lns[row][half][slot] = s; lnq[row][half][slot] = sq; }
            }
        }
        __syncthreads();
        {
            int row = tid >> 1, hh = tid & 1;
            float s  = lns[row][hh][0] + lns[row][hh][1];
            float sq = lnq[row][hh][0] + lnq[row][hh][1];
            float m  = s * (1.f / 64.f);
            float var = sq * (1.f / 64.f) - m * m;
            float r  = rsqrtf(var + 1e-5f);
            lns[row][hh][0] = m;
            lns[row][hh][1] = r;
        }
        __syncthreads();
#pragma unroll
        for (int nt = 0; nt < 4; nt++) {
            int col = wn * 32 + nt * 8 + jj * 2;
#pragma unroll
            for (int mt = 0; mt < 4; mt++) {
                int lrow0 = wm * 64 + mt * 16 + lr;
                int lrow1 = lrow0 + 8;
                float m0_ = lns[lrow0][half][0], r0_ = lns[lrow0][half][1];
                float m1_ = lns[lrow1][half][0], r1_ = lns[lrow1][half][1];
                __nv_bfloat162 p0 = __float22bfloat162_rn(
                    make_float2((acc[mt][nt][0] - m0_) * r0_,
                                (acc[mt][nt][1] - m0_) * r0_));
                __nv_bfloat162 p1 = __float22bfloat162_rn(
                    make_float2((acc[mt][nt][2] - m1_) * r1_,
                                (acc[mt][nt][3] - m1_) * r1_));
                *(unsigned*)&qh[(size_t)(m0 + lrow0) * 128 + col] = *(unsigned*)&p0;
                *(unsigned*)&qh[(size_t)(m0 + lrow1) * 128 + col] = *(unsigned*)&p1;
            }
        }
    }
}

// ---------------- finalize: sum 32 spread partials -> fused BN affine ----------
__global__ void finalize_aff(const double* __restrict__ stats,
                             const float* __restrict__ g, const float* __restrict__ b,
                             float* __restrict__ affA, float* __restrict__ affB,
                             double inv_n)
{
    int c = threadIdx.x;
    double s = 0.0, q = 0.0;
#pragma unroll 4
    for (int i = 0; i < 32; i++) {
        s += stats[i * 256 + c];
        q += stats[i * 256 + 128 + c];
    }
    double m   = s * inv_n;
    double var = q * inv_n - m * m;
    float A = (float)(1.0 / sqrt(var + 1e-5)) * g[c];
    affA[c] = A;
    affB[c] = b[c] - (float)m * A;
}

// ---------------- BatchNorm (small, fused: stats + apply + lrelu) ----------------
__global__ void bn_small(const float* __restrict__ X, float* __restrict__ Y,
                         const float* __restrict__ g, const float* __restrict__ b,
                         int nrows)
{
    int bcol = blockIdx.x;
    int t = threadIdx.x;
    float4 s  = make_float4(0.f, 0.f, 0.f, 0.f);
    float4 s2 = make_float4(0.f, 0.f, 0.f, 0.f);
    for (int r = t; r < nrows; r += 128) {
        float4 v = ((const float4*)X)[(size_t)r * 32 + bcol];
        s.x += v.x; s.y += v.y; s.z += v.z; s.w += v.w;
        s2.x = fmaf(v.x, v.x, s2.x); s2.y = fmaf(v.y, v.y, s2.y);
        s2.z = fmaf(v.z, v.z, s2.z); s2.w = fmaf(v.w, v.w, s2.w);
    }
    __shared__ float4 sh[128], sh2[128];
    sh[t] = s; sh2[t] = s2;
    __syncthreads();
    for (int off = 64; off >= 1; off >>= 1) {
        if (t < off) {
            sh[t].x += sh[t+off].x; sh[t].y += sh[t+off].y;
            sh[t].z += sh[t+off].z; sh[t].w += sh[t+off].w;
            sh2[t].x += sh2[t+off].x; sh2[t].y += sh2[t+off].y;
            sh2[t].z += sh2[t+off].z; sh2[t].w += sh2[t+off].w;
        }
        __syncthreads();
    }
    __shared__ float4 mean4, scl4;
    if (t == 0) {
        float inv = 1.f / (float)nrows;
        float4 m = make_float4(sh[0].x*inv, sh[0].y*inv, sh[0].z*inv, sh[0].w*inv);
        mean4 = m;
        scl4.x = rsqrtf(sh2[0].x*inv - m.x*m.x + 1e-5f);
        scl4.y = rsqrtf(sh2[0].y*inv - m.y*m.y + 1e-5f);
        scl4.z = rsqrtf(sh2[0].z*inv - m.z*m.z + 1e-5f);
        scl4.w = rsqrtf(sh2[0].w*inv - m.w*m.w + 1e-5f);
    }
    __syncthreads();
    float4 g4 = ((const float4*)g)[bcol];
    float4 b4 = ((const float4*)b)[bcol];
    float4 m4 = mean4, c4 = scl4;
    for (int r = t; r < nrows; r += 128) {
        float4 v = ((const float4*)X)[(size_t)r * 32 + bcol];
        float4 o;
        o.x = lrelu1((v.x - m4.x) * c4.x * g4.x + b4.x);
        o.y = lrelu1((v.y - m4.y) * c4.y * g4.y + b4.y);
        o.z = lrelu1((v.z - m4.z) * c4.z * g4.z + b4.z);
        o.w = lrelu1((v.w - m4.w) * c4.w * g4.w + b4.w);
        ((float4*)Y)[(size_t)r * 32 + bcol] = o;
    }
}

// ---------------- fused per-node attention (online softmax, warp per node) -----
// 2-edge unrolled for memory-level parallelism; fused column stats.
__global__ __launch_bounds__(256) void pf_attn(
    const unsigned short* __restrict__ qh, const unsigned short* __restrict__ vh,
    const int* __restrict__ offs, const int* __restrict__ csr,
    float* __restrict__ out, double* __restrict__ stats)
{
    __shared__ float sh[8][128];
    int w    = threadIdx.x >> 5;
    int n    = blockIdx.x * 8 + w;
    int lane = threadIdx.x & 31;
    int e0 = offs[n], e1 = offs[n + 1];
    uint2 qn2 = ((const uint2*)qh)[(size_t)n * 32 + lane];
    float2 qn0 = __bfloat1622float2(*(__nv_bfloat162*)&qn2.x);
    float2 qn1 = __bfloat1622float2(*(__nv_bfloat162*)&qn2.y);
    float m = __int_as_float(0xff800000);   // -inf
    float z = 0.f;
    float4 acc = make_float4(0.f, 0.f, 0.f, 0.f);

    int e = e0;
    for (; e + 2 <= e1; e += 2) {
        int d0 = csr[e], d1 = csr[e + 1];
        uint2 qa2 = ((const uint2*)qh)[(size_t)d0 * 32 + lane];
        uint2 qb2 = ((const uint2*)qh)[(size_t)d1 * 32 + lane];
        uint2 va2 = ((const uint2*)vh)[(size_t)d0 * 32 + lane];
        uint2 vb2 = ((const uint2*)vh)[(size_t)d1 * 32 + lane];
        float2 qa0 = __bfloat1622float2(*(__nv_bfloat162*)&qa2.x);
        float2 qa1 = __bfloat1622float2(*(__nv_bfloat162*)&qa2.y);
        float2 qb0 = __bfloat1622float2(*(__nv_bfloat162*)&qb2.x);
        float2 qb1 = __bfloat1622float2(*(__nv_bfloat162*)&qb2.y);
        float p0 = qn0.x * qa0.x + qn0.y * qa0.y + qn1.x * qa1.x + qn1.y * qa1.y;
        float p1 = qn0.x * qb0.x + qn0.y * qb0.y + qn1.x * qb1.x + qn1.y * qb1.y;
#pragma unroll
        for (int mk = 1; mk <= 8; mk <<= 1) {
            p0 += __shfl_xor_sync(0xffffffffu, p0, mk);
            p1 += __shfl_xor_sync(0xffffffffu, p1, mk);
        }
        float s0 = p0 * (1.0f / 128.0f);
        float s1 = p1 * (1.0f / 128.0f);
        float2 va0 = __half22float2(*(__half2*)&va2.x);
        float2 va1 = __half22float2(*(__half2*)&va2.y);
        float2 vb0 = __half22float2(*(__half2*)&vb2.x);
        float2 vb1 = __half22float2(*(__half2*)&vb2.y);
        float mn = fmaxf(m, fmaxf(s0, s1));
        float sc = __expf(m - mn);
        float ea = __expf(s0 - mn);
        float eb = __expf(s1 - mn);
        z = z * sc + ea + eb;
        acc.x = acc.x * sc + ea * va0.x + eb * vb0.x;
        acc.y = acc.y * sc + ea * va0.y + eb * vb0.y;
        acc.z = acc.z * sc + ea * va1.x + eb * vb1.x;
        acc.w = acc.w * sc + ea * va1.y + eb * vb1.y;
        m = mn;
    }
    if (e < e1) {
        int d0 = csr[e];
        uint2 qa2 = ((const uint2*)qh)[(size_t)d0 * 32 + lane];
        uint2 va2 = ((const uint2*)vh)[(size_t)d0 * 32 + lane];
        float2 qa0 = __bfloat1622float2(*(__nv_bfloat162*)&qa2.x);
        float2 qa1 = __bfloat1622float2(*(__nv_bfloat162*)&qa2.y);
        float p0 = qn0.x * qa0.x + qn0.y * qa0.y + qn1.x * qa1.x + qn1.y * qa1.y;
#pragma unroll
        for (int mk = 1; mk <= 8; mk <<= 1)
            p0 += __shfl_xor_sync(0xffffffffu, p0, mk);
        float s0 = p0 * (1.0f / 128.0f);
        float2 va0 = __half22float2(*(__half2*)&va2.x);
        float2 va1 = __half22float2(*(__half2*)&va2.y);
        float mn = fmaxf(m, s0);
        float sc = __expf(m - mn);
        float ea = __expf(s0 - mn);
        z = z * sc + ea;
        acc.x = acc.x * sc + ea * va0.x;
        acc.y = acc.y * sc + ea * va0.y;
        acc.z = acc.z * sc + ea * va1.x;
        acc.w = acc.w * sc + ea * va1.y;
        m = mn;
    }
    float iz = (z > 0.f) ? __fdividef(1.f, z) : 0.f;
    float4 o = make_float4(acc.x * iz, acc.y * iz, acc.z * iz, acc.w * iz);
    ((float4*)out)[(size_t)n * 32 + lane] = o;

    // ---- fused column stats ----
    ((float4*)sh[w])[lane] = o;
    __syncthreads();
    if (threadIdx.x < 128) {
        float s = 0.f, q = 0.f;
#pragma unroll
        for (int r = 0; r < 8; r++) {
            float v = sh[r][threadIdx.x];
            s += v;
            q = fmaf(v, v, q);
        }
        int sl = (blockIdx.x & 31) * 256;
        atomicAdd(&stats[sl + threadIdx.x],       (double)s);
        atomicAdd(&stats[sl + 128 + threadIdx.x], (double)q);
    }
}

// ---------------- fused superpixel pooling (affine on x0 applied on load) -------
__global__ __launch_bounds__(256) void pool_f(
    const float* __restrict__ x0, const int* __restrict__ offs,
    const int* __restrict__ pix, const float* __restrict__ affA,
    const float* __restrict__ affB, float* __restrict__ hp)
{
    int s    = (blockIdx.x * 256 + threadIdx.x) >> 5;
    int lane = threadIdx.x & 31;
    int e0 = offs[s], e1 = offs[s + 1];
    float4 a4 = ((const float4*)affA)[lane];
    float4 b4 = ((const float4*)affB)[lane];
    float4 acc = make_float4(0.f, 0.f, 0.f, 0.f);
    for (int e = e0; e < e1; e++) {
        int p = pix[e];
        float4 xv = ((const float4*)x0)[(size_t)p * 32 + lane];
        acc.x += fmaf(xv.x, a4.x, b4.x);
        acc.y += fmaf(xv.y, a4.y, b4.y);
        acc.z += fmaf(xv.z, a4.z, b4.z);
        acc.w += fmaf(xv.w, a4.w, b4.w);
    }
    float ic = 1.f / fmaxf((float)(e1 - e0), 1.f);
    ((float4*)hp)[(size_t)s * 32 + lane] =
        make_float4(acc.x * ic, acc.y * ic, acc.z * ic, acc.w * ic);
}

// ---------------- fused superpixel propagate (warp per dst node) ----------------
__global__ __launch_bounds__(256) void sf_prop_f(
    const float* __restrict__ h, const int* __restrict__ offs,
    const int* __restrict__ csrs, const float* __restrict__ csrw,
    const float* __restrict__ xs, float* __restrict__ out, int mode)
{
    int n    = (blockIdx.x * 256 + threadIdx.x) >> 5;
    int lane = threadIdx.x & 31;
    int e0 = offs[n], e1 = offs[n + 1];
    float4 acc = make_float4(0.f, 0.f, 0.f, 0.f);
    for (int e = e0; e < e1; e++) {
        int s = csrs[e];
        float w = csrw[e];
        float4 hv = ((const float4*)h)[(size_t)s * 32 + lane];
        acc.x = fmaf(w, hv.x, acc.x);
        acc.y = fmaf(w, hv.y, acc.y);
        acc.z = fmaf(w, hv.z, acc.z);
        acc.w = fmaf(w, hv.w, acc.w);
    }
    if (mode == 0) {
        ((float4*)out)[(size_t)n * 32 + lane] = acc;
    } else {
        float4 x = ((const float4*)xs)[(size_t)n * 32 + lane];
        const float inv = 1.0f / 2.9f;
        ((float4*)out)[(size_t)n * 32 + lane] =
            make_float4((acc.x + x.x) * inv, (acc.y + x.y) * inv,
                        (acc.z + x.z) * inv, (acc.w + x.w) * inv);
    }
}

// ---------------- final: H1 = BNaff(pfb) + hp[seg]; softmax(H1 @ W + b) ---------
__global__ __launch_bounds__(256) void final_out(
    const float* __restrict__ pf, const float* __restrict__ hp,
    const int* __restrict__ seg, const float* __restrict__ Wout,
    const float* __restrict__ bout, const float* __restrict__ affA,
    const float* __restrict__ affB, float* __restrict__ out, int nrows)
{
    __shared__ float sWt[16 * 128];
    __shared__ float sb[16];
    for (int i = threadIdx.x; i < 2048; i += 256) {
        int k = i >> 4, c = i & 15;
        sWt[c * 128 + k] = Wout[i];
    }
    if (threadIdx.x < 16) sb[threadIdx.x] = bout[threadIdx.x];
    __syncthreads();

    int warp = (blockIdx.x * 256 + threadIdx.x) >> 5;
    int lane = threadIdx.x & 31;
    if (warp >= nrows) return;
    int s = seg[warp];
    float4 aA = ((const float4*)affA)[lane];
    float4 aB = ((const float4*)affB)[lane];
    float4 a = ((const float4*)pf)[(size_t)warp * 32 + lane];
    float4 b = ((const float4*)hp)[(size_t)s * 32 + lane];
    float4 h;
    h.x = lrelu1(fmaf(a.x, aA.x, aB.x)) + b.x;
    h.y = lrelu1(fmaf(a.y, aA.y, aB.y)) + b.y;
    h.z = lrelu1(fmaf(a.z, aA.z, aB.z)) + b.z;
    h.w = lrelu1(fmaf(a.w, aA.w, aB.w)) + b.w;

    float lg[16];
#pragma unroll
    for (int c = 0; c < 16; c++) {
        float4 w = ((const float4*)sWt)[c * 32 + lane];
        lg[c] = h.x * w.x + h.y * w.y + h.z * w.z + h.w * w.w;
    }
#pragma unroll
    for (int off = 16; off >= 1; off >>= 1)
#pragma unroll
        for (int c = 0; c < 16; c++)
            lg[c] += __shfl_xor_sync(0xffffffffu, lg[c], off);

    if (lane < 16) {
        float mx = -1e30f;
#pragma unroll
        for (int c = 0; c < 16; c++) { lg[c] += sb[c]; mx = fmaxf(mx, lg[c]); }
        float sum = 0.f;
#pragma unroll
        for (int c = 0; c < 16; c++) { lg[c] = __expf(lg[c] - mx); sum += lg[c]; }
        float inv = __fdividef(1.0f, sum);
        float r = 0.f;
#pragma unroll
        for (int c = 0; c < 16; c++) if (lane == c) r = lg[c];
        out[(size_t)warp * 16 + lane] = r * inv;
    }
}

// ---------------- host ----------------
#define GSYM(p, sym) cudaGetSymbolAddress((void**)&p, sym)

extern "C" void kernel_launch(void* const* d_in, const int* in_sizes, int n_in,
                              void* d_out, int out_size)
{
    const float* x       = (const float*)d_in[0];
    const int*   seg     = (const int*)  d_in[1];
    const int*   a_src   = (const int*)  d_in[2];
    const int*   a_dst   = (const int*)  d_in[3];
    const float* a_w     = (const float*)d_in[4];
    const int*   m_src   = (const int*)  d_in[5];
    const int*   m_dst   = (const int*)  d_in[6];
    const float* pre_W   = (const float*)d_in[7];
    const float* pre_b   = (const float*)d_in[8];
    const float* bn0_g   = (const float*)d_in[9];
    const float* bn0_b   = (const float*)d_in[10];
    const float* sf_W    = (const float*)d_in[11];
    const float* sf_b    = (const float*)d_in[12];
    const float* sf_g    = (const float*)d_in[13];
    const float* sf_beta = (const float*)d_in[14];
    const float* pf_Wv   = (const float*)d_in[15];
    const float* pf_bv   = (const float*)d_in[16];
    const float* pf_Wq   = (const float*)d_in[17];
    const float* pf_bq   = (const float*)d_in[18];
    const float* pf_g    = (const float*)d_in[19];
    const float* pf_beta = (const float*)d_in[20];
    const float* out_W   = (const float*)d_in[21];
    const float* out_b   = (const float*)d_in[22];
    float* out = (float*)d_out;

    float *x0, *pfa, *pfb;
    unsigned short *qh, *vh;
    float *affA, *affB, *hp, *hb, *xs, *ba, *bb, *wv, *wq, *bv, *bq;
    double *stats;
    int *deg, *cursor, *offs, *btot, *csr;
    int *adeg, *acur, *aoffs, *acsrs;
    float *acsrw;
    int *sdeg, *scur, *soffs, *spix;
    GSYM(x0, d_x0);   GSYM(pfa, d_pfa); GSYM(pfb, d_pfb);
    GSYM(qh, d_qh);   GSYM(vh, d_vh);
    GSYM(stats, d_stats); GSYM(affA, d_affA); GSYM(affB, d_affB);
    GSYM(hp, d_hp); GSYM(hb, d_hb); GSYM(xs, d_xs);
    GSYM(ba, d_ba); GSYM(bb, d_bb);
    GSYM(wv, d_wv); GSYM(wq, d_wq); GSYM(bv, d_bv); GSYM(bq, d_bq);
    GSYM(deg, d_deg); GSYM(cursor, d_cursor); GSYM(offs, d_offs);
    GSYM(btot, d_btot); GSYM(csr, d_csr);
    GSYM(adeg, d_adeg); GSYM(acur, d_acur); GSYM(aoffs, d_aoffs);
    GSYM(acsrs, d_acsrs); GSYM(acsrw, d_acsrw);
    GSYM(sdeg, d_sdeg); GSYM(scur, d_scur); GSYM(soffs, d_soffs);
    GSYM(spix, d_spix);

    // ---- build CSRs (pixel graph by src; a-graph by dst; seg lists) ----
    cudaMemsetAsync(deg, 0, NPIX * sizeof(int));
    hist_kernel<<<EME / 256, 256>>>(m_src, deg, EME);
    scan_chunk<<<256, 256>>>(deg, offs, btot);
    scan_btot<<<1, 256>>>(btot);
    scan_add<<<NPIX / 256, 256>>>(offs, btot, cursor, NPIX, EME);
    scatter_px<<<EME / 256, 256>>>(m_src, m_dst, cursor, csr, EME);

    cudaMemsetAsync(adeg, 0, SP * sizeof(int));
    hist_kernel<<<EAE / 256, 256>>>(a_dst, adeg, EAE);
    scan4k<<<1, 1024>>>(adeg, aoffs, acur, EAE);
    scatter_a<<<EAE / 256, 256>>>(a_src, a_dst, a_w, acur, acsrs, acsrw, EAE);

    cudaMemsetAsync(sdeg, 0, SP * sizeof(int));
    hist_kernel<<<NPIX / 256, 256>>>(seg, sdeg, NPIX);
    scan4k<<<1, 1024>>>(sdeg, soffs, scur, NPIX);
    scatter_seg<<<NPIX / 256, 256>>>(seg, scur, spix, NPIX);

    // pack per-head attention weights into [128,128]
    pack_weights<<<(2 * HD * HD + 255) / 256, 256>>>(pf_Wv, pf_bv, pf_Wq, pf_bq,
                                                     wv, bv, wq, bq);

    // ---- pre: x0raw = x @ pre_W + pre_b; stats fused in epilogue (slot 0) ----
    cudaMemsetAsync(stats, 0, 32 * 256 * sizeof(double));
    gemm_tc<<<NPIX / 128, 256>>>(x, pre_W, pre_b, x0, NPIX, CIN, stats);
    finalize_aff<<<1, 128>>>(stats, bn0_g, bn0_b, affA, affB, 1.0 / (double)NPIX);

    // ---- PF branch: 2 attention layers on the pixel graph ----
    const float* pin = x0;
    for (int l = 0; l < 2; l++) {
        float* pout = (l == 0) ? pfa : pfb;
        const float* aA = affA + l * HD;
        const float* aB = affB + l * HD;
        int lr = (l > 0);
        cudaMemsetAsync(stats, 0, 32 * 256 * sizeof(double));
        gemm_qv<<<NPIX / 128 * 2, 256>>>(pin, wv + l * HD * HD, wq + l * HD * HD,
                                         bv + l * HD, bq + l * HD, vh, qh, aA, aB, lr);
        pf_attn<<<NPIX / 8, 256>>>(qh, vh, offs, csr, pout, stats);
        finalize_aff<<<1, 128>>>(stats, pf_g + l * HD, pf_beta + l * HD,
                                 affA + (l + 1) * HD, affB + (l + 1) * HD,
                                 1.0 / (double)NPIX);
        pin = pout;
    }

    // ---- SF branch: pool (bn0 affine fused) -> 5 SFNet layers ----
    pool_f<<<SP / 8, 256>>>(x0, soffs, spix, affA, affB, hp);

    for (int l = 0; l < 5; l++) {
        gemm_tc<<<SP / 128, 256>>>(hp, sf_W + l * HD * HD, sf_b + l * HD, hb,
                                   SP, HD, (double*)0);
        sf_prop_f<<<SP / 8, 256>>>(hb, aoffs, acsrs, acsrw, xs, xs, 0);
        const float* cur = hp;
        for (int it = 0; it < 5; it++) {
            float* nxt = (it & 1) ? bb : ba;
            sf_prop_f<<<SP / 8, 256>>>(cur, aoffs, acsrs, acsrw, xs, nxt, 1);
            cur = nxt;
        }
        bn_small<<<32, 128>>>(cur, hp, sf_g + l * HD, sf_beta + l * HD, SP);
    }

    // ---- final: softmax((BNaff(pfb) + hp[seg]) @ out_W + out_b) ----
    final_out<<<NPIX / 8, 256>>>(pfb, hp, seg, out_W, out_b,
                                 affA + 2 * HD, affB + 2 * HD, out, NPIX);
}

// round 15
// speedup vs baseline: 2.6709x; 1.0025x over previous
#include <cuda_runtime.h>
#include <cuda_bf16.h>
#include <cuda_fp16.h>

#define NPIX 262144
#define CIN  200
#define HD   128
#define SP   4096
#define EAE  65536
#define EME  2097152
#define NCLS 16

// ---------------- scratch (device globals; allocation-free rule) ----------------
__device__ float  d_x0 [NPIX*HD];
__device__ float  d_pfa[NPIX*HD];
__device__ float  d_pfb[NPIX*HD];
__device__ unsigned short d_qh[NPIX*HD];   // bf16 q (layer-normed)
__device__ unsigned short d_vh[NPIX*HD];   // fp16 v
__device__ double d_stats[32*256];         // 32-way spread: [i][c]=sum, [i][128+c]=sumsq
__device__ float  d_affA[3*HD];            // per-BN fused scale
__device__ float  d_affB[3*HD];            // per-BN fused shift
__device__ float  d_hp [SP*HD];
__device__ float  d_hb [SP*HD];
__device__ float  d_xs [SP*HD];
__device__ float  d_ba [SP*HD];
__device__ float  d_bb [SP*HD];
__device__ float  d_wv [2*HD*HD];
__device__ float  d_wq [2*HD*HD];
__device__ float  d_bv [2*HD];
__device__ float  d_bq [2*HD];
// CSR scratch: pixel graph (by src)
__device__ int    d_deg   [NPIX];
__device__ int    d_cursor[NPIX];
__device__ int    d_offs  [NPIX+1];
__device__ int    d_btot  [256];
__device__ int    d_csr   [EME];
// superpixel graph (by dst)
__device__ int    d_adeg [SP];
__device__ int    d_acur [SP];
__device__ int    d_aoffs[SP+1];
__device__ int    d_acsrs[EAE];
__device__ float  d_acsrw[EAE];
// seg -> pixel lists
__device__ int    d_sdeg [SP];
__device__ int    d_scur [SP];
__device__ int    d_soffs[SP+1];
__device__ int    d_spix [NPIX];

// ---------------- helpers ----------------
__device__ __forceinline__ void cvt_hilo(float v, unsigned& hi, unsigned& lo) {
    __nv_bfloat16 h = __float2bfloat16(v);
    float r = v - __bfloat162float(h);
    __nv_bfloat16 l = __float2bfloat16(r);
    hi = (unsigned)__bfloat16_as_ushort(h);
    lo = (unsigned)__bfloat16_as_ushort(l);
}

__device__ __forceinline__ void mma16816(float* c, const unsigned* a, const unsigned* b) {
    asm volatile("mma.sync.aligned.m16n8k16.row.col.f32.bf16.bf16.f32 "
                 "{%0,%1,%2,%3}, {%4,%5,%6,%7}, {%8,%9}, {%0,%1,%2,%3};"
                 : "+f"(c[0]), "+f"(c[1]), "+f"(c[2]), "+f"(c[3])
                 : "r"(a[0]), "r"(a[1]), "r"(a[2]), "r"(a[3]),
                   "r"(b[0]), "r"(b[1]));
}

__device__ __forceinline__ float lrelu1(float x) { return x >= 0.f ? x : 0.01f * x; }

// ---------------- CSR construction ----------------
__global__ void hist_kernel(const int* __restrict__ idx, int* __restrict__ deg, int n)
{
    int i = blockIdx.x * blockDim.x + threadIdx.x;
    if (i < n) atomicAdd(&deg[idx[i]], 1);
}

__global__ void scan_chunk(const int* __restrict__ deg, int* __restrict__ offs,
                           int* __restrict__ btot)
{
    __shared__ int ts[256];
    int t = threadIdx.x;
    int base = blockIdx.x * 1024 + t * 4;
    int a0 = deg[base], a1 = deg[base+1], a2 = deg[base+2], a3 = deg[base+3];
    int s = a0 + a1 + a2 + a3;
    ts[t] = s; __syncthreads();
    for (int off = 1; off < 256; off <<= 1) {
        int v = (t >= off) ? ts[t - off] : 0;
        __syncthreads();
        ts[t] += v;
        __syncthreads();
    }
    int excl = ts[t] - s;
    offs[base]   = excl;
    offs[base+1] = excl + a0;
    offs[base+2] = excl + a0 + a1;
    offs[base+3] = excl + a0 + a1 + a2;
    if (t == 255) btot[blockIdx.x] = ts[255];
}

__global__ void scan_btot(int* __restrict__ btot)
{
    __shared__ int ts[256];
    int t = threadIdx.x;
    int v = btot[t];
    ts[t] = v; __syncthreads();
    for (int off = 1; off < 256; off <<= 1) {
        int u = (t >= off) ? ts[t - off] : 0;
        __syncthreads();
        ts[t] += u;
        __syncthreads();
    }
    btot[t] = ts[t] - v;
}

__global__ void scan_add(int* __restrict__ offs, const int* __restrict__ btot,
                         int* __restrict__ cursor, int n, int total)
{
    int i = blockIdx.x * blockDim.x + threadIdx.x;
    if (i < n) {
        int v = offs[i] + btot[i >> 10];
        offs[i] = v;
        cursor[i] = v;
    }
    if (i == 0) offs[n] = total;
}

__global__ void scan4k(const int* __restrict__ deg, int* __restrict__ offs,
                       int* __restrict__ cursor, int total)
{
    __shared__ int ts[1024];
    int t = threadIdx.x;
    int base = t * 4;
    int a0 = deg[base], a1 = deg[base+1], a2 = deg[base+2], a3 = deg[base+3];
    int s = a0 + a1 + a2 + a3;
    ts[t] = s; __syncthreads();
    for (int off = 1; off < 1024; off <<= 1) {
        int v = (t >= off) ? ts[t - off] : 0;
        __syncthreads();
        ts[t] += v;
        __syncthreads();
    }
    int excl = ts[t] - s;
    int o0 = excl, o1 = excl + a0, o2 = excl + a0 + a1, o3 = excl + a0 + a1 + a2;
    offs[base] = o0;   cursor[base] = o0;
    offs[base+1] = o1; cursor[base+1] = o1;
    offs[base+2] = o2; cursor[base+2] = o2;
    offs[base+3] = o3; cursor[base+3] = o3;
    if (t == 1023) offs[4096] = total;
}

__global__ void scatter_px(const int* __restrict__ src, const int* __restrict__ dst,
                           int* __restrict__ cursor, int* __restrict__ csr, int n)
{
    int e = blockIdx.x * blockDim.x + threadIdx.x;
    if (e < n) {
        int p = atomicAdd(&cursor[src[e]], 1);
        csr[p] = dst[e];
    }
}

__global__ void scatter_a(const int* __restrict__ asrc, const int* __restrict__ adst,
                          const float* __restrict__ aw, int* __restrict__ cursor,
                          int* __restrict__ csrs, float* __restrict__ csrw, int n)
{
    int e = blockIdx.x * blockDim.x + threadIdx.x;
    if (e < n) {
        int p = atomicAdd(&cursor[adst[e]], 1);
        csrs[p] = asrc[e];
        csrw[p] = aw[e];
    }
}

__global__ void scatter_seg(const int* __restrict__ seg, int* __restrict__ cursor,
                            int* __restrict__ csr, int n)
{
    int i = blockIdx.x * blockDim.x + threadIdx.x;
    if (i < n) {
        int p = atomicAdd(&cursor[seg[i]], 1);
        csr[p] = i;
    }
}

// ---------------- weight packing: [2][2][128][64] -> [2][128][128] ----------------
__global__ void pack_weights(const float* __restrict__ Wv, const float* __restrict__ bv,
                             const float* __restrict__ Wq, const float* __restrict__ bq,
                             float* __restrict__ wvp, float* __restrict__ bvp,
                             float* __restrict__ wqp, float* __restrict__ bqp)
{
    int idx = blockIdx.x * blockDim.x + threadIdx.x;
    if (idx >= 2 * HD * HD) return;
    int l = idx >> 14;
    int rem = idx & 16383;
    int k = rem >> 7;
    int c = rem & 127;
    int h = c >> 6;
    int j = c & 63;
    int sidx = ((l * 2 + h) * HD + k) * 64 + j;
    wvp[idx] = Wv[sidx];
    wqp[idx] = Wq[sidx];
    if (k == 0) {
        bvp[(l << 7) | c] = bv[(l * 2 + h) * 64 + j];
        bqp[(l << 7) | c] = bq[(l * 2 + h) * 64 + j];
    }
}

// ---------------- generic TC GEMM: C[M,128] = A[M,K] @ B[K,128] + bias ----------
// Optional fused column-stats accumulation into spread double buffer.
__global__ __launch_bounds__(256) void gemm_tc(
    const float* __restrict__ A, const float* __restrict__ B,
    const float* __restrict__ bias, float* __restrict__ C, int M, int K,
    double* __restrict__ stats)
{
    __shared__ unsigned As_h[128 * 8];
    __shared__ unsigned As_l[128 * 8];
    __shared__ unsigned Bs_h[8 * 132];
    __shared__ unsigned Bs_l[8 * 132];

    const int tid  = threadIdx.x;
    const int lane = tid & 31;
    const int warp = tid >> 5;
    const int wm   = warp >> 2;
    const int wn   = warp & 3;
    const int m0   = blockIdx.x * 128;

    float acc[4][4][4];
#pragma unroll
    for (int mt = 0; mt < 4; mt++)
#pragma unroll
        for (int nt = 0; nt < 4; nt++)
#pragma unroll
            for (int i = 0; i < 4; i++) acc[mt][nt][i] = 0.f;

    const int lr = lane >> 2;
    const int jj = lane & 3;

    for (int k0 = 0; k0 < K; k0 += 16) {
        {
            int r  = tid & 127;
            int qb = (tid >> 7) << 1;
            const float* ap = A + (size_t)(m0 + r) * K;
#pragma unroll
            for (int qq = 0; qq < 2; qq++) {
                int q  = qb + qq;
                int kk = k0 + q * 4;
                float v0 = 0.f, v1 = 0.f, v2 = 0.f, v3 = 0.f;
                if (kk + 3 < K) {
                    float4 t = *(const float4*)(ap + kk);
                    v0 = t.x; v1 = t.y; v2 = t.z; v3 = t.w;
                } else {
                    if (kk + 0 < K) v0 = ap[kk + 0];
                    if (kk + 1 < K) v1 = ap[kk + 1];
                    if (kk + 2 < K) v2 = ap[kk + 2];
                    if (kk + 3 < K) v3 = ap[kk + 3];
                }
                unsigned h0, l0, h1, l1, h2, l2, h3, l3;
                cvt_hilo(v0, h0, l0); cvt_hilo(v1, h1, l1);
                cvt_hilo(v2, h2, l2); cvt_hilo(v3, h3, l3);
                As_h[r * 8 + q * 2 + 0] = h0 | (h1 << 16);
                As_h[r * 8 + q * 2 + 1] = h2 | (h3 << 16);
                As_l[r * 8 + q * 2 + 0] = l0 | (l1 << 16);
                As_l[r * 8 + q * 2 + 1] = l2 | (l3 << 16);
            }
        }
        {
            int kp  = tid >> 5;
            int np0 = tid & 31;
#pragma unroll
            for (int hh = 0; hh < 2; hh++) {
                int np = np0 + hh * 32;
                int n  = np * 2;
                int ka = k0 + kp * 2;
                float a = 0.f, b = 0.f, c = 0.f, d = 0.f;
                if (ka < K)     { float2 t = *(const float2*)(B + (size_t)ka * 128 + n);       a = t.x; b = t.y; }
                if (ka + 1 < K) { float2 t = *(const float2*)(B + (size_t)(ka + 1) * 128 + n); c = t.x; d = t.y; }
                unsigned ha, la, hb_, lb, hc, lc, hd, ld;
                cvt_hilo(a, ha, la); cvt_hilo(b, hb_, lb);
                cvt_hilo(c, hc, lc); cvt_hilo(d, hd, ld);
                Bs_h[kp * 132 + n + 0] = ha  | (hc << 16);
                Bs_h[kp * 132 + n + 1] = hb_ | (hd << 16);
                Bs_l[kp * 132 + n + 0] = la  | (lc << 16);
                Bs_l[kp * 132 + n + 1] = lb  | (ld << 16);
            }
        }
        __syncthreads();

        unsigned ah[4][4];
#pragma unroll
        for (int mt = 0; mt < 4; mt++) {
            int r = wm * 64 + mt * 16 + lr;
            ah[mt][0] = As_h[r * 8 + jj];
            ah[mt][1] = As_h[(r + 8) * 8 + jj];
            ah[mt][2] = As_h[r * 8 + jj + 4];
            ah[mt][3] = As_h[(r + 8) * 8 + jj + 4];
        }
        unsigned bh[4][2];
#pragma unroll
        for (int nt = 0; nt < 4; nt++) {
            int n = wn * 32 + nt * 8 + lr;
            bh[nt][0] = Bs_h[jj * 132 + n];
            bh[nt][1] = Bs_h[(jj + 4) * 132 + n];
        }
#pragma unroll
        for (int mt = 0; mt < 4; mt++)
#pragma unroll
            for (int nt = 0; nt < 4; nt++)
                mma16816(acc[mt][nt], ah[mt], bh[nt]);
        {
            unsigned bl[4][2];
#pragma unroll
            for (int nt = 0; nt < 4; nt++) {
                int n = wn * 32 + nt * 8 + lr;
                bl[nt][0] = Bs_l[jj * 132 + n];
                bl[nt][1] = Bs_l[(jj + 4) * 132 + n];
            }
#pragma unroll
            for (int mt = 0; mt < 4; mt++)
#pragma unroll
                for (int nt = 0; nt < 4; nt++)
                    mma16816(acc[mt][nt], ah[mt], bl[nt]);
        }
#pragma unroll
        for (int mt = 0; mt < 4; mt++) {
            int r = wm * 64 + mt * 16 + lr;
            ah[mt][0] = As_l[r * 8 + jj];
            ah[mt][1] = As_l[(r + 8) * 8 + jj];
            ah[mt][2] = As_l[r * 8 + jj + 4];
            ah[mt][3] = As_l[(r + 8) * 8 + jj + 4];
        }
#pragma unroll
        for (int mt = 0; mt < 4; mt++)
#pragma unroll
            for (int nt = 0; nt < 4; nt++)
                mma16816(acc[mt][nt], ah[mt], bh[nt]);
        __syncthreads();
    }

    // ---- bias into acc, store ----
#pragma unroll
    for (int nt = 0; nt < 4; nt++) {
        int col = wn * 32 + nt * 8 + jj * 2;
        float b0 = bias[col], b1 = bias[col + 1];
#pragma unroll
        for (int mt = 0; mt < 4; mt++) {
            acc[mt][nt][0] += b0; acc[mt][nt][1] += b1;
            acc[mt][nt][2] += b0; acc[mt][nt][3] += b1;
        }
    }
#pragma unroll
    for (int nt = 0; nt < 4; nt++) {
        int col = wn * 32 + nt * 8 + jj * 2;
#pragma unroll
        for (int mt = 0; mt < 4; mt++) {
            int r0 = m0 + wm * 64 + mt * 16 + lr;
            *(float2*)(C + (size_t)r0 * 128 + col)       = make_float2(acc[mt][nt][0], acc[mt][nt][1]);
            *(float2*)(C + (size_t)(r0 + 8) * 128 + col) = make_float2(acc[mt][nt][2], acc[mt][nt][3]);
        }
    }

    // ---- fused column stats (sum, sumsq) ----
    if (stats) {
        float cs[4][2], cq[4][2];
#pragma unroll
        for (int nt = 0; nt < 4; nt++)
#pragma unroll
            for (int p = 0; p < 2; p++) {
                float s = 0.f, q = 0.f;
#pragma unroll
                for (int mt = 0; mt < 4; mt++) {
                    float a = acc[mt][nt][p], c = acc[mt][nt][p + 2];
                    s += a + c;
                    q += a * a + c * c;
                }
                cs[nt][p] = s; cq[nt][p] = q;
            }
#pragma unroll
        for (int mk = 4; mk <= 16; mk <<= 1)
#pragma unroll
            for (int nt = 0; nt < 4; nt++)
#pragma unroll
                for (int p = 0; p < 2; p++) {
                    cs[nt][p] += __shfl_xor_sync(0xffffffffu, cs[nt][p], mk);
                    cq[nt][p] += __shfl_xor_sync(0xffffffffu, cq[nt][p], mk);
                }
        float* sS = (float*)As_h;
        float* sQ = (float*)As_l;
        if (tid < 128) { sS[tid] = 0.f; sQ[tid] = 0.f; }
        __syncthreads();
        if (lr == 0) {
#pragma unroll
            for (int nt = 0; nt < 4; nt++)
#pragma unroll
                for (int p = 0; p < 2; p++) {
                    int col = wn * 32 + nt * 8 + jj * 2 + p;
                    atomicAdd(&sS[col], cs[nt][p]);
                    atomicAdd(&sQ[col], cq[nt][p]);
                }
        }
        __syncthreads();
        if (tid < 128) {
            int sl = (blockIdx.x & 31) * 256;
            atomicAdd(&stats[sl + tid],       (double)sS[tid]);
            atomicAdd(&stats[sl + 128 + tid], (double)sQ[tid]);
        }
    }
}

// ---------------- fused q/v GEMM (K=128). Even blocks: v -> fp16.
// Odd blocks: q -> per-64-half LayerNorm -> bf16. Paired blocks share A via L2.
__global__ __launch_bounds__(256) void gemm_qv(
    const float* __restrict__ A, const float* __restrict__ Bv,
    const float* __restrict__ Bq, const float* __restrict__ biasv,
    const float* __restrict__ biasq, unsigned short* __restrict__ vh,
    unsigned short* __restrict__ qh,
    const float* __restrict__ aA, const float* __restrict__ aB, int lrelu)
{
    __shared__ unsigned As_h[128 * 8];
    __shared__ unsigned As_l[128 * 8];
    __shared__ unsigned Bs_h[8 * 132];
    __shared__ unsigned Bs_l[8 * 132];
    __shared__ float lns[128][2][2];
    __shared__ float lnq[128][2][2];

    const int tid  = threadIdx.x;
    const int lane = tid & 31;
    const int warp = tid >> 5;
    const int wm   = warp >> 2;
    const int wn   = warp & 3;
    const int isq  = blockIdx.x & 1;
    const int m0   = (blockIdx.x >> 1) * 128;
    const float* B    = isq ? Bq : Bv;
    const float* bias = isq ? biasq : biasv;

    float acc[4][4][4];
#pragma unroll
    for (int mt = 0; mt < 4; mt++)
#pragma unroll
        for (int nt = 0; nt < 4; nt++)
#pragma unroll
            for (int i = 0; i < 4; i++) acc[mt][nt][i] = 0.f;

    const int lr = lane >> 2;
    const int jj = lane & 3;

    for (int k0 = 0; k0 < 128; k0 += 16) {
        {
            int r  = tid & 127;
            int qb = (tid >> 7) << 1;
            const float* ap = A + (size_t)(m0 + r) * 128;
#pragma unroll
            for (int qq = 0; qq < 2; qq++) {
                int q  = qb + qq;
                int kk = k0 + q * 4;
                float4 t = *(const float4*)(ap + kk);
                float4 a4 = *(const float4*)(aA + kk);
                float4 b4 = *(const float4*)(aB + kk);
                float v0 = fmaf(t.x, a4.x, b4.x);
                float v1 = fmaf(t.y, a4.y, b4.y);
                float v2 = fmaf(t.z, a4.z, b4.z);
                float v3 = fmaf(t.w, a4.w, b4.w);
                if (lrelu) {
                    v0 = lrelu1(v0); v1 = lrelu1(v1);
                    v2 = lrelu1(v2); v3 = lrelu1(v3);
                }
                unsigned h0, l0, h1, l1, h2, l2, h3, l3;
                cvt_hilo(v0, h0, l0); cvt_hilo(v1, h1, l1);
                cvt_hilo(v2, h2, l2); cvt_hilo(v3, h3, l3);
                As_h[r * 8 + q * 2 + 0] = h0 | (h1 << 16);
                As_h[r * 8 + q * 2 + 1] = h2 | (h3 << 16);
                As_l[r * 8 + q * 2 + 0] = l0 | (l1 << 16);
                As_l[r * 8 + q * 2 + 1] = l2 | (l3 << 16);
            }
        }
        {
            int kp  = tid >> 5;
            int np0 = tid & 31;
#pragma unroll
            for (int hh = 0; hh < 2; hh++) {
                int np = np0 + hh * 32;
                int n  = np * 2;
                int ka = k0 + kp * 2;
                float2 t0 = *(const float2*)(B + (size_t)ka * 128 + n);
                float2 t1 = *(const float2*)(B + (size_t)(ka + 1) * 128 + n);
                unsigned ha, la, hb_, lb, hc, lc_, hd, ld;
                cvt_hilo(t0.x, ha, la); cvt_hilo(t0.y, hb_, lb);
                cvt_hilo(t1.x, hc, lc_); cvt_hilo(t1.y, hd, ld);
                Bs_h[kp * 132 + n + 0] = ha  | (hc << 16);
                Bs_h[kp * 132 + n + 1] = hb_ | (hd << 16);
                Bs_l[kp * 132 + n + 0] = la  | (lc_ << 16);
                Bs_l[kp * 132 + n + 1] = lb  | (ld << 16);
            }
        }
        __syncthreads();

        unsigned ah[4][4];
#pragma unroll
        for (int mt = 0; mt < 4; mt++) {
            int r = wm * 64 + mt * 16 + lr;
            ah[mt][0] = As_h[r * 8 + jj];
            ah[mt][1] = As_h[(r + 8) * 8 + jj];
            ah[mt][2] = As_h[r * 8 + jj + 4];
            ah[mt][3] = As_h[(r + 8) * 8 + jj + 4];
        }
        unsigned bh[4][2];
#pragma unroll
        for (int nt = 0; nt < 4; nt++) {
            int n = wn * 32 + nt * 8 + lr;
            bh[nt][0] = Bs_h[jj * 132 + n];
            bh[nt][1] = Bs_h[(jj + 4) * 132 + n];
        }
#pragma unroll
        for (int mt = 0; mt < 4; mt++)
#pragma unroll
            for (int nt = 0; nt < 4; nt++)
                mma16816(acc[mt][nt], ah[mt], bh[nt]);
        {
            unsigned bl[4][2];
#pragma unroll
            for (int nt = 0; nt < 4; nt++) {
                int n = wn * 32 + nt * 8 + lr;
                bl[nt][0] = Bs_l[jj * 132 + n];
                bl[nt][1] = Bs_l[(jj + 4) * 132 + n];
            }
#pragma unroll
            for (int mt = 0; mt < 4; mt++)
#pragma unroll
                for (int nt = 0; nt < 4; nt++)
                    mma16816(acc[mt][nt], ah[mt], bl[nt]);
        }
#pragma unroll
        for (int mt = 0; mt < 4; mt++) {
            int r = wm * 64 + mt * 16 + lr;
            ah[mt][0] = As_l[r * 8 + jj];
            ah[mt][1] = As_l[(r + 8) * 8 + jj];
            ah[mt][2] = As_l[r * 8 + jj + 4];
            ah[mt][3] = As_l[(r + 8) * 8 + jj + 4];
        }
#pragma unroll
        for (int mt = 0; mt < 4; mt++)
#pragma unroll
            for (int nt = 0; nt < 4; nt++)
                mma16816(acc[mt][nt], ah[mt], bh[nt]);
        __syncthreads();
    }

    // ---- bias into acc ----
#pragma unroll
    for (int nt = 0; nt < 4; nt++) {
        int col = wn * 32 + nt * 8 + jj * 2;
        float b0 = bias[col], b1 = bias[col + 1];
#pragma unroll
        for (int mt = 0; mt < 4; mt++) {
            acc[mt][nt][0] += b0; acc[mt][nt][1] += b1;
            acc[mt][nt][2] += b0; acc[mt][nt][3] += b1;
        }
    }

    if (!isq) {
        // ---- v path: fp16 store ----
#pragma unroll
        for (int nt = 0; nt < 4; nt++) {
            int col = wn * 32 + nt * 8 + jj * 2;
#pragma unroll
            for (int mt = 0; mt < 4; mt++) {
                int r0 = m0 + wm * 64 + mt * 16 + lr;
                __half2 p0 = __float22half2_rn(make_float2(acc[mt][nt][0], acc[mt][nt][1]));
                __half2 p1 = __float22half2_rn(make_float2(acc[mt][nt][2], acc[mt][nt][3]));
                *(unsigned*)&vh[(size_t)r0 * 128 + col]       = *(unsigned*)&p0;
                *(unsigned*)&vh[(size_t)(r0 + 8) * 128 + col] = *(unsigned*)&p1;
            }
        }
    } else {
        // ---- q path: per-64-half LayerNorm, then bf16 store ----
        int half = wn >> 1, slot = wn & 1;
#pragma unroll
        for (int mt = 0; mt < 4; mt++) {
#pragma unroll
            for (int sub = 0; sub < 2; sub++) {
                float s = 0.f, sq = 0.f;
#pragma unroll
                for (int nt = 0; nt < 4; nt++) {
                    float a = acc[mt][nt][sub * 2], b = acc[mt][nt][sub * 2 + 1];
                    s += a + b;
                    sq += a * a + b * b;
                }
                s  += __shfl_xor_sync(0xffffffffu, s, 1);
                sq += __shfl_xor_sync(0xffffffffu, sq, 1);
                s  += __shfl_xor_sync(0xffffffffu, s, 2);
                sq += __shfl_xor_sync(0xffffffffu, sq, 2);
                int row = wm * 64 + mt * 16 + sub * 8 + lr;
                if (jj == 0) { lns[row][half][slot] = s; lnq[row][half][slot] = sq; }
            }
        }
        __syncthreads();
        {
            int row = tid >> 1, hh = tid & 1;
            float s  = lns[row][hh][0] + lns[row][hh][1];
            float sq = lnq[row][hh][0] + lnq[row][hh][1];
            float m  = s * (1.f / 64.f);
            float var = sq * (1.f / 64.f) - m * m;
            float r  = rsqrtf(var + 1e-5f);
            lns[row][hh][0] = m;
            lns[row][hh][1] = r;
        }
        __syncthreads();
#pragma unroll
        for (int nt = 0; nt < 4; nt++) {
            int col = wn * 32 + nt * 8 + jj * 2;
#pragma unroll
            for (int mt = 0; mt < 4; mt++) {
                int lrow0 = wm * 64 + mt * 16 + lr;
                int lrow1 = lrow0 + 8;
                float m0_ = lns[lrow0][half][0], r0_ = lns[lrow0][half][1];
                float m1_ = lns[lrow1][half][0], r1_ = lns[lrow1][half][1];
                __nv_bfloat162 p0 = __float22bfloat162_rn(
                    make_float2((acc[mt][nt][0] - m0_) * r0_,
                                (acc[mt][nt][1] - m0_) * r0_));
                __nv_bfloat162 p1 = __float22bfloat162_rn(
                    make_float2((acc[mt][nt][2] - m1_) * r1_,
                                (acc[mt][nt][3] - m1_) * r1_));
                *(unsigned*)&qh[(size_t)(m0 + lrow0) * 128 + col] = *(unsigned*)&p0;
                *(unsigned*)&qh[(size_t)(m0 + lrow1) * 128 + col] = *(unsigned*)&p1;
            }
        }
    }
}

// ---------------- finalize: sum 32 spread partials -> fused BN affine ----------
__global__ void finalize_aff(const double* __restrict__ stats,
                             const float* __restrict__ g, const float* __restrict__ b,
                             float* __restrict__ affA, float* __restrict__ affB,
                             double inv_n)
{
    int c = threadIdx.x;
    double s = 0.0, q = 0.0;
#pragma unroll 4
    for (int i = 0; i < 32; i++) {
        s += stats[i * 256 + c];
        q += stats[i * 256 + 128 + c];
    }
    double m   = s * inv_n;
    double var = q * inv_n - m * m;
    float A = (float)(1.0 / sqrt(var + 1e-5)) * g[c];
    affA[c] = A;
    affB[c] = b[c] - (float)m * A;
}

// ---------------- BatchNorm (small, fused: stats + apply + lrelu) ----------------
__global__ void bn_small(const float* __restrict__ X, float* __restrict__ Y,
                         const float* __restrict__ g, const float* __restrict__ b,
                         int nrows)
{
    int bcol = blockIdx.x;
    int t = threadIdx.x;
    float4 s  = make_float4(0.f, 0.f, 0.f, 0.f);
    float4 s2 = make_float4(0.f, 0.f, 0.f, 0.f);
    for (int r = t; r < nrows; r += 128) {
        float4 v = ((const float4*)X)[(size_t)r * 32 + bcol];
        s.x += v.x; s.y += v.y; s.z += v.z; s.w += v.w;
        s2.x = fmaf(v.x, v.x, s2.x); s2.y = fmaf(v.y, v.y, s2.y);
        s2.z = fmaf(v.z, v.z, s2.z); s2.w = fmaf(v.w, v.w, s2.w);
    }
    __shared__ float4 sh[128], sh2[128];
    sh[t] = s; sh2[t] = s2;
    __syncthreads();
    for (int off = 64; off >= 1; off >>= 1) {
        if (t < off) {
            sh[t].x += sh[t+off].x; sh[t].y += sh[t+off].y;
            sh[t].z += sh[t+off].z; sh[t].w += sh[t+off].w;
            sh2[t].x += sh2[t+off].x; sh2[t].y += sh2[t+off].y;
            sh2[t].z += sh2[t+off].z; sh2[t].w += sh2[t+off].w;
        }
        __syncthreads();
    }
    __shared__ float4 mean4, scl4;
    if (t == 0) {
        float inv = 1.f / (float)nrows;
        float4 m = make_float4(sh[0].x*inv, sh[0].y*inv, sh[0].z*inv, sh[0].w*inv);
        mean4 = m;
        scl4.x = rsqrtf(sh2[0].x*inv - m.x*m.x + 1e-5f);
        scl4.y = rsqrtf(sh2[0].y*inv - m.y*m.y + 1e-5f);
        scl4.z = rsqrtf(sh2[0].z*inv - m.z*m.z + 1e-5f);
        scl4.w = rsqrtf(sh2[0].w*inv - m.w*m.w + 1e-5f);
    }
    __syncthreads();
    float4 g4 = ((const float4*)g)[bcol];
    float4 b4 = ((const float4*)b)[bcol];
    float4 m4 = mean4, c4 = scl4;
    for (int r = t; r < nrows; r += 128) {
        float4 v = ((const float4*)X)[(size_t)r * 32 + bcol];
        float4 o;
        o.x = lrelu1((v.x - m4.x) * c4.x * g4.x + b4.x);
        o.y = lrelu1((v.y - m4.y) * c4.y * g4.y + b4.y);
        o.z = lrelu1((v.z - m4.z) * c4.z * g4.z + b4.z);
        o.w = lrelu1((v.w - m4.w) * c4.w * g4.w + b4.w);
        ((float4*)Y)[(size_t)r * 32 + bcol] = o;
    }
}

// ---------------- fused per-node attention (online softmax, warp per node) -----
// 4-edge unrolled for memory-level parallelism; fused column stats.
__global__ __launch_bounds__(256) void pf_attn(
    const unsigned short* __restrict__ qh, const unsigned short* __restrict__ vh,
    const int* __restrict__ offs, const int* __restrict__ csr,
    float* __restrict__ out, double* __restrict__ stats)
{
    __shared__ float sh[8][128];
    int w    = threadIdx.x >> 5;
    int n    = blockIdx.x * 8 + w;
    int lane = threadIdx.x & 31;
    int e0 = offs[n], e1 = offs[n + 1];
    uint2 qn2 = ((const uint2*)qh)[(size_t)n * 32 + lane];
    float2 qn0 = __bfloat1622float2(*(__nv_bfloat162*)&qn2.x);
    float2 qn1 = __bfloat1622float2(*(__nv_bfloat162*)&qn2.y);
    float m = __int_as_float(0xff800000);   // -inf
    float z = 0.f;
    float4 acc = make_float4(0.f, 0.f, 0.f, 0.f);

    int e = e0;
    for (; e + 4 <= e1; e += 4) {
        int d0 = csr[e], d1 = csr[e + 1], d2 = csr[e + 2], d3 = csr[e + 3];
        uint2 qa2 = ((const uint2*)qh)[(size_t)d0 * 32 + lane];
        uint2 qb2 = ((const uint2*)qh)[(size_t)d1 * 32 + lane];
        uint2 qc2 = ((const uint2*)qh)[(size_t)d2 * 32 + lane];
        uint2 qd2 = ((const uint2*)qh)[(size_t)d3 * 32 + lane];
        uint2 va2 = ((const uint2*)vh)[(size_t)d0 * 32 + lane];
        uint2 vb2 = ((const uint2*)vh)[(size_t)d1 * 32 + lane];
        uint2 vc2 = ((const uint2*)vh)[(size_t)d2 * 32 + lane];
        uint2 vd2 = ((const uint2*)vh)[(size_t)d3 * 32 + lane];
        float2 t0, t1;
        t0 = __bfloat1622float2(*(__nv_bfloat162*)&qa2.x);
        t1 = __bfloat1622float2(*(__nv_bfloat162*)&qa2.y);
        float p0 = qn0.x * t0.x + qn0.y * t0.y + qn1.x * t1.x + qn1.y * t1.y;
        t0 = __bfloat1622float2(*(__nv_bfloat162*)&qb2.x);
        t1 = __bfloat1622float2(*(__nv_bfloat162*)&qb2.y);
        float p1 = qn0.x * t0.x + qn0.y * t0.y + qn1.x * t1.x + qn1.y * t1.y;
        t0 = __bfloat1622float2(*(__nv_bfloat162*)&qc2.x);
        t1 = __bfloat1622float2(*(__nv_bfloat162*)&qc2.y);
        float p2 = qn0.x * t0.x + qn0.y * t0.y + qn1.x * t1.x + qn1.y * t1.y;
        t0 = __bfloat1622float2(*(__nv_bfloat162*)&qd2.x);
        t1 = __bfloat1622float2(*(__nv_bfloat162*)&qd2.y);
        float p3 = qn0.x * t0.x + qn0.y * t0.y + qn1.x * t1.x + qn1.y * t1.y;
#pragma unroll
        for (int mk = 1; mk <= 8; mk <<= 1) {
            p0 += __shfl_xor_sync(0xffffffffu, p0, mk);
            p1 += __shfl_xor_sync(0xffffffffu, p1, mk);
            p2 += __shfl_xor_sync(0xffffffffu, p2, mk);
            p3 += __shfl_xor_sync(0xffffffffu, p3, mk);
        }
        float s0 = p0 * (1.0f / 128.0f);
        float s1 = p1 * (1.0f / 128.0f);
        float s2 = p2 * (1.0f / 128.0f);
        float s3 = p3 * (1.0f / 128.0f);
        float mx = fmaxf(fmaxf(s0, s1), fmaxf(s2, s3));
        float mn = fmaxf(m, mx);
        float sc = __expf(m - mn);
        float ea = __expf(s0 - mn);
        float eb = __expf(s1 - mn);
        float ec = __expf(s2 - mn);
        float ed = __expf(s3 - mn);
        z = z * sc + (ea + eb) + (ec + ed);
        float2 va0 = __half22float2(*(__half2*)&va2.x);
        float2 va1 = __half22float2(*(__half2*)&va2.y);
        float2 vb0 = __half22float2(*(__half2*)&vb2.x);
        float2 vb1 = __half22float2(*(__half2*)&vb2.y);
        float2 vc0 = __half22float2(*(__half2*)&vc2.x);
        float2 vc1 = __half22float2(*(__half2*)&vc2.y);
        float2 vd0 = __half22float2(*(__half2*)&vd2.x);
        float2 vd1 = __half22float2(*(__half2*)&vd2.y);
        acc.x = acc.x * sc + (ea * va0.x + eb * vb0.x) + (ec * vc0.x + ed * vd0.x);
        acc.y = acc.y * sc + (ea * va0.y + eb * vb0.y) + (ec * vc0.y + ed * vd0.y);
        acc.z = acc.z * sc + (ea * va1.x + eb * vb1.x) + (ec * vc1.x + ed * vd1.x);
        acc.w = acc.w * sc + (ea * va1.y + eb * vb1.y) + (ec * vc1.y + ed * vd1.y);
        m = mn;
    }
    for (; e < e1; e++) {
        int d0 = csr[e];
        uint2 qa2 = ((const uint2*)qh)[(size_t)d0 * 32 + lane];
        uint2 va2 = ((const uint2*)vh)[(size_t)d0 * 32 + lane];
        float2 qa0 = __bfloat1622float2(*(__nv_bfloat162*)&qa2.x);
        float2 qa1 = __bfloat1622float2(*(__nv_bfloat162*)&qa2.y);
        float p0 = qn0.x * qa0.x + qn0.y * qa0.y + qn1.x * qa1.x + qn1.y * qa1.y;
#pragma unroll
        for (int mk = 1; mk <= 8; mk <<= 1)
            p0 += __shfl_xor_sync(0xffffffffu, p0, mk);
        float s0 = p0 * (1.0f / 128.0f);
        float2 va0 = __half22float2(*(__half2*)&va2.x);
        float2 va1 = __half22float2(*(__half2*)&va2.y);
        float mn = fmaxf(m, s0);
        float sc = __expf(m - mn);
        float ea = __expf(s0 - mn);
        z = z * sc + ea;
        acc.x = acc.x * sc + ea * va0.x;
        acc.y = acc.y * sc + ea * va0.y;
        acc.z = acc.z * sc + ea * va1.x;
        acc.w = acc.w * sc + ea * va1.y;
        m = mn;
    }
    float iz = (z > 0.f) ? __fdividef(1.f, z) : 0.f;
    float4 o = make_float4(acc.x * iz, acc.y * iz, acc.z * iz, acc.w * iz);
    ((float4*)out)[(size_t)n * 32 + lane] = o;

    // ---- fused column stats ----
    ((float4*)sh[w])[lane] = o;
    __syncthreads();
    if (threadIdx.x < 128) {
        float s = 0.f, q = 0.f;
#pragma unroll
        for (int r = 0; r < 8; r++) {
            float v = sh[r][threadIdx.x];
            s += v;
            q = fmaf(v, v, q);
        }
        int sl = (blockIdx.x & 31) * 256;
        atomicAdd(&stats[sl + threadIdx.x],       (double)s);
        atomicAdd(&stats[sl + 128 + threadIdx.x], (double)q);
    }
}

// ---------------- fused superpixel pooling (affine on x0 applied on load) -------
__global__ __launch_bounds__(256) void pool_f(
    const float* __restrict__ x0, const int* __restrict__ offs,
    const int* __restrict__ pix, const float* __restrict__ affA,
    const float* __restrict__ affB, float* __restrict__ hp)
{
    int s    = (blockIdx.x * 256 + threadIdx.x) >> 5;
    int lane = threadIdx.x & 31;
    int e0 = offs[s], e1 = offs[s + 1];
    float4 a4 = ((const float4*)affA)[lane];
    float4 b4 = ((const float4*)affB)[lane];
    float4 acc = make_float4(0.f, 0.f, 0.f, 0.f);
    for (int e = e0; e < e1; e++) {
        int p = pix[e];
        float4 xv = ((const float4*)x0)[(size_t)p * 32 + lane];
        acc.x += fmaf(xv.x, a4.x, b4.x);
        acc.y += fmaf(xv.y, a4.y, b4.y);
        acc.z += fmaf(xv.z, a4.z, b4.z);
        acc.w += fmaf(xv.w, a4.w, b4.w);
    }
    float ic = 1.f / fmaxf((float)(e1 - e0), 1.f);
    ((float4*)hp)[(size_t)s * 32 + lane] =
        make_float4(acc.x * ic, acc.y * ic, acc.z * ic, acc.w * ic);
}

// ---------------- merged first SF step: xs = A*hb; cur1 = (A*hp + xs)/2.9 -------
__global__ __launch_bounds__(256) void sf_prop2(
    const float* __restrict__ hb, const float* __restrict__ hp,
    const int* __restrict__ offs, const int* __restrict__ csrs,
    const float* __restrict__ csrw, float* __restrict__ xs,
    float* __restrict__ cur1)
{
    int n    = (blockIdx.x * 256 + threadIdx.x) >> 5;
    int lane = threadIdx.x & 31;
    int e0 = offs[n], e1 = offs[n + 1];
    float4 ab = make_float4(0.f, 0.f, 0.f, 0.f);
    float4 ap = make_float4(0.f, 0.f, 0.f, 0.f);
    for (int e = e0; e < e1; e++) {
        int s = csrs[e];
        float w = csrw[e];
        float4 hbv = ((const float4*)hb)[(size_t)s * 32 + lane];
        float4 hpv = ((const float4*)hp)[(size_t)s * 32 + lane];
        ab.x = fmaf(w, hbv.x, ab.x); ab.y = fmaf(w, hbv.y, ab.y);
        ab.z = fmaf(w, hbv.z, ab.z); ab.w = fmaf(w, hbv.w, ab.w);
        ap.x = fmaf(w, hpv.x, ap.x); ap.y = fmaf(w, hpv.y, ap.y);
        ap.z = fmaf(w, hpv.z, ap.z); ap.w = fmaf(w, hpv.w, ap.w);
    }
    ((float4*)xs)[(size_t)n * 32 + lane] = ab;
    const float inv = 1.0f / 2.9f;
    ((float4*)cur1)[(size_t)n * 32 + lane] =
        make_float4((ap.x + ab.x) * inv, (ap.y + ab.y) * inv,
                    (ap.z + ab.z) * inv, (ap.w + ab.w) * inv);
}

// ---------------- fused superpixel propagate (warp per dst node) ----------------
__global__ __launch_bounds__(256) void sf_prop_f(
    const float* __restrict__ h, const int* __restrict__ offs,
    const int* __restrict__ csrs, const float* __restrict__ csrw,
    const float* __restrict__ xs, float* __restrict__ out)
{
    int n    = (blockIdx.x * 256 + threadIdx.x) >> 5;
    int lane = threadIdx.x & 31;
    int e0 = offs[n], e1 = offs[n + 1];
    float4 acc = make_float4(0.f, 0.f, 0.f, 0.f);
    for (int e = e0; e < e1; e++) {
        int s = csrs[e];
        float w = csrw[e];
        float4 hv = ((const float4*)h)[(size_t)s * 32 + lane];
        acc.x = fmaf(w, hv.x, acc.x);
        acc.y = fmaf(w, hv.y, acc.y);
        acc.z = fmaf(w, hv.z, acc.z);
        acc.w = fmaf(w, hv.w, acc.w);
    }
    float4 x = ((const float4*)xs)[(size_t)n * 32 + lane];
    const float inv = 1.0f / 2.9f;
    ((float4*)out)[(size_t)n * 32 + lane] =
        make_float4((acc.x + x.x) * inv, (acc.y + x.y) * inv,
                    (acc.z + x.z) * inv, (acc.w + x.w) * inv);
}

// ---------------- final: H1 = BNaff(pfb) + hp[seg]; softmax(H1 @ W + b) ---------
__global__ __launch_bounds__(256) void final_out(
    const float* __restrict__ pf, const float* __restrict__ hp,
    const int* __restrict__ seg, const float* __restrict__ Wout,
    const float* __restrict__ bout, const float* __restrict__ affA,
    const float* __restrict__ affB, float* __restrict__ out, int nrows)
{
    __shared__ float sWt[16 * 128];
    __shared__ float sb[16];
    for (int i = threadIdx.x; i < 2048; i += 256) {
        int k = i >> 4, c = i & 15;
        sWt[c * 128 + k] = Wout[i];
    }
    if (threadIdx.x < 16) sb[threadIdx.x] = bout[threadIdx.x];
    __syncthreads();

    int warp = (blockIdx.x * 256 + threadIdx.x) >> 5;
    int lane = threadIdx.x & 31;
    if (warp >= nrows) return;
    int s = seg[warp];
    float4 aA = ((const float4*)affA)[lane];
    float4 aB = ((const float4*)affB)[lane];
    float4 a = ((const float4*)pf)[(size_t)warp * 32 + lane];
    float4 b = ((const float4*)hp)[(size_t)s * 32 + lane];
    float4 h;
    h.x = lrelu1(fmaf(a.x, aA.x, aB.x)) + b.x;
    h.y = lrelu1(fmaf(a.y, aA.y, aB.y)) + b.y;
    h.z = lrelu1(fmaf(a.z, aA.z, aB.z)) + b.z;
    h.w = lrelu1(fmaf(a.w, aA.w, aB.w)) + b.w;

    float lg[16];
#pragma unroll
    for (int c = 0; c < 16; c++) {
        float4 w = ((const float4*)sWt)[c * 32 + lane];
        lg[c] = h.x * w.x + h.y * w.y + h.z * w.z + h.w * w.w;
    }
#pragma unroll
    for (int off = 16; off >= 1; off >>= 1)
#pragma unroll
        for (int c = 0; c < 16; c++)
            lg[c] += __shfl_xor_sync(0xffffffffu, lg[c], off);

    if (lane < 16) {
        float mx = -1e30f;
#pragma unroll
        for (int c = 0; c < 16; c++) { lg[c] += sb[c]; mx = fmaxf(mx, lg[c]); }
        float sum = 0.f;
#pragma unroll
        for (int c = 0; c < 16; c++) { lg[c] = __expf(lg[c] - mx); sum += lg[c]; }
        float inv = __fdividef(1.0f, sum);
        float r = 0.f;
#pragma unroll
        for (int c = 0; c < 16; c++) if (lane == c) r = lg[c];
        out[(size_t)warp * 16 + lane] = r * inv;
    }
}

// ---------------- host ----------------
#define GSYM(p, sym) cudaGetSymbolAddress((void**)&p, sym)

extern "C" void kernel_launch(void* const* d_in, const int* in_sizes, int n_in,
                              void* d_out, int out_size)
{
    const float* x       = (const float*)d_in[0];
    const int*   seg     = (const int*)  d_in[1];
    const int*   a_src   = (const int*)  d_in[2];
    const int*   a_dst   = (const int*)  d_in[3];
    const float* a_w     = (const float*)d_in[4];
    const int*   m_src   = (const int*)  d_in[5];
    const int*   m_dst   = (const int*)  d_in[6];
    const float* pre_W   = (const float*)d_in[7];
    const float* pre_b   = (const float*)d_in[8];
    const float* bn0_g   = (const float*)d_in[9];
    const float* bn0_b   = (const float*)d_in[10];
    const float* sf_W    = (const float*)d_in[11];
    const float* sf_b    = (const float*)d_in[12];
    const float* sf_g    = (const float*)d_in[13];
    const float* sf_beta = (const float*)d_in[14];
    const float* pf_Wv   = (const float*)d_in[15];
    const float* pf_bv   = (const float*)d_in[16];
    const float* pf_Wq   = (const float*)d_in[17];
    const float* pf_bq   = (const float*)d_in[18];
    const float* pf_g    = (const float*)d_in[19];
    const float* pf_beta = (const float*)d_in[20];
    const float* out_W   = (const float*)d_in[21];
    const float* out_b   = (const float*)d_in[22];
    float* out = (float*)d_out;

    float *x0, *pfa, *pfb;
    unsigned short *qh, *vh;
    float *affA, *affB, *hp, *hb, *xs, *ba, *bb, *wv, *wq, *bv, *bq;
    double *stats;
    int *deg, *cursor, *offs, *btot, *csr;
    int *adeg, *acur, *aoffs, *acsrs;
    float *acsrw;
    int *sdeg, *scur, *soffs, *spix;
    GSYM(x0, d_x0);   GSYM(pfa, d_pfa); GSYM(pfb, d_pfb);
    GSYM(qh, d_qh);   GSYM(vh, d_vh);
    GSYM(stats, d_stats); GSYM(affA, d_affA); GSYM(affB, d_affB);
    GSYM(hp, d_hp); GSYM(hb, d_hb); GSYM(xs, d_xs);
    GSYM(ba, d_ba); GSYM(bb, d_bb);
    GSYM(wv, d_wv); GSYM(wq, d_wq); GSYM(bv, d_bv); GSYM(bq, d_bq);
    GSYM(deg, d_deg); GSYM(cursor, d_cursor); GSYM(offs, d_offs);
    GSYM(btot, d_btot); GSYM(csr, d_csr);
    GSYM(adeg, d_adeg); GSYM(acur, d_acur); GSYM(aoffs, d_aoffs);
    GSYM(acsrs, d_acsrs); GSYM(acsrw, d_acsrw);
    GSYM(sdeg, d_sdeg); GSYM(scur, d_scur); GSYM(soffs, d_soffs);
    GSYM(spix, d_spix);

    // ---- pixel-graph CSR first (kernels 0..4) so ncu -s 5 lands on the pre-GEMM ----
    cudaMemsetAsync(deg, 0, NPIX * sizeof(int));
    hist_kernel<<<EME / 256, 256>>>(m_src, deg, EME);
    scan_chunk<<<256, 256>>>(deg, offs, btot);
    scan_btot<<<1, 256>>>(btot);
    scan_add<<<NPIX / 256, 256>>>(offs, btot, cursor, NPIX, EME);
    scatter_px<<<EME / 256, 256>>>(m_src, m_dst, cursor, csr, EME);

    // ---- pre: x0raw = x @ pre_W + pre_b; stats fused in epilogue (slot 0) ----
    cudaMemsetAsync(stats, 0, 32 * 256 * sizeof(double));
    gemm_tc<<<NPIX / 128, 256>>>(x, pre_W, pre_b, x0, NPIX, CIN, stats);
    finalize_aff<<<1, 128>>>(stats, bn0_g, bn0_b, affA, affB, 1.0 / (double)NPIX);

    // ---- remaining CSRs + weight packing ----
    pack_weights<<<(2 * HD * HD + 255) / 256, 256>>>(pf_Wv, pf_bv, pf_Wq, pf_bq,
                                                     wv, bv, wq, bq);
    cudaMemsetAsync(adeg, 0, SP * sizeof(int));
    hist_kernel<<<EAE / 256, 256>>>(a_dst, adeg, EAE);
    scan4k<<<1, 1024>>>(adeg, aoffs, acur, EAE);
    scatter_a<<<EAE / 256, 256>>>(a_src, a_dst, a_w, acur, acsrs, acsrw, EAE);

    cudaMemsetAsync(sdeg, 0, SP * sizeof(int));
    hist_kernel<<<NPIX / 256, 256>>>(seg, sdeg, NPIX);
    scan4k<<<1, 1024>>>(sdeg, soffs, scur, NPIX);
    scatter_seg<<<NPIX / 256, 256>>>(seg, scur, spix, NPIX);

    // ---- PF branch: 2 attention layers on the pixel graph ----
    const float* pin = x0;
    for (int l = 0; l < 2; l++) {
        float* pout = (l == 0) ? pfa : pfb;
        const float* aA = affA + l * HD;
        const float* aB = affB + l * HD;
        int lr = (l > 0);
        cudaMemsetAsync(stats, 0, 32 * 256 * sizeof(double));
        gemm_qv<<<NPIX / 128 * 2, 256>>>(pin, wv + l * HD * HD, wq + l * HD * HD,
                                         bv + l * HD, bq + l * HD, vh, qh, aA, aB, lr);
        pf_attn<<<NPIX / 8, 256>>>(qh, vh, offs, csr, pout, stats);
        finalize_aff<<<1, 128>>>(stats, pf_g + l * HD, pf_beta + l * HD,
                                 affA + (l + 1) * HD, affB + (l + 1) * HD,
                                 1.0 / (double)NPIX);
        pin = pout;
    }

    // ---- SF branch: pool (bn0 affine fused) -> 5 SFNet layers ----
    pool_f<<<SP / 8, 256>>>(x0, soffs, spix, affA, affB, hp);

    for (int l = 0; l < 5; l++) {
        gemm_tc<<<SP / 128, 256>>>(hp, sf_W + l * HD * HD, sf_b + l * HD, hb,
                                   SP, HD, (double*)0);
        // iteration 1 merged with x_start computation
        sf_prop2<<<SP / 8, 256>>>(hb, hp, aoffs, acsrs, acsrw, xs, ba);
        const float* cur = ba;
        for (int it = 1; it < 5; it++) {
            float* nxt = (it & 1) ? bb : ba;
            sf_prop_f<<<SP / 8, 256>>>(cur, aoffs, acsrs, acsrw, xs, nxt);
            cur = nxt;
        }
        bn_small<<<32, 128>>>(cur, hp, sf_g + l * HD, sf_beta + l * HD, SP);
    }

    // ---- final: softmax((BNaff(pfb) + hp[seg]) @ out_W + out_b) ----
    final_out<<<NPIX / 8, 256>>>(pfb, hp, seg, out_W, out_b,
                                 affA + 2 * HD, affB + 2 * HD, out, NPIX);
}